// round 2
// baseline (speedup 1.0000x reference)
#include <cuda_runtime.h>
#include <cuda_bf16.h>
#include <stdint.h>

// ---------------------------------------------------------------------------
// SEALNetwork: 3-layer GNN (N=32768, H=128, E=524288) + dense pooling head.
// CSR build (deterministic via per-node sort) -> per layer:
//   fused SGEMM (x_in/x_out/x_root share h tile, static 43KB smem) ->
//   warp-per-node gather/mean/LN/ReLU -> per-graph pooling + LN + linear.
// Input dtypes for edge_index / mask_breaks are runtime-detected on device.
// ---------------------------------------------------------------------------

#define N_NODES 32768
#define N_EDGES 524288
#define NG      256
#define NPG     128
#define HD      128
#define NL      3
#define NC      16
#define BK      16

// scratch (static device globals: allocation-free per harness rules)
__device__ float        g_h[2][N_NODES * HD];
__device__ float        g_xin [N_NODES * HD];
__device__ float        g_xout[N_NODES * HD];
__device__ float        g_xroot[N_NODES * HD];
__device__ int          g_cnt[N_NODES];
__device__ int          g_start[N_NODES];
__device__ int          g_wcur[N_NODES];
__device__ float        g_invc[N_NODES];
__device__ unsigned int g_csr[N_EDGES];
__device__ float        g_l1[NG];
__device__ int          g_ei64;     // 1 if edge_index is int64, 0 if int32
__device__ int          g_mk_kind;  // 0 = uint8/bool, 1 = int32, 2 = float32

// ---------------------------------------------------------------------------
// dtype detection (1 thread, deterministic, reads only in-bounds prefixes)
// ---------------------------------------------------------------------------
__global__ void detect_kernel(const unsigned int* __restrict__ ei_w,
                              const unsigned int* __restrict__ mk_w) {
    // edge_index: if int64 (values < 2^31), every odd 32-bit word is 0.
    int odd_nonzero = 0;
    for (int i = 0; i < 64; i++)
        if (ei_w[2 * i + 1] != 0u) odd_nonzero++;
    g_ei64 = (odd_nonzero == 0) ? 1 : 0;

    // mask_breaks: f32 -> words in {0, 0x3F800000}; u8 -> multi-byte patterns;
    // i32 -> words in {0, 1}.
    int has_f1 = 0, multi = 0;
    for (int i = 0; i < 256; i++) {
        unsigned int w = mk_w[i];
        if (w == 0x3F800000u) { has_f1 = 1; continue; }
        if ((w >> 8) != 0u) multi = 1;  // any byte above byte0 set (not f32 1.0)
    }
    g_mk_kind = has_f1 ? 2 : (multi ? 0 : 1);
}

// ---------------------------------------------------------------------------
// CSR construction
// ---------------------------------------------------------------------------
__device__ __forceinline__ int load_idx(const void* ei, int pos) {
    if (g_ei64) return (int)((const long long*)ei)[pos];
    return ((const int*)ei)[pos];
}

__device__ __forceinline__ bool load_mask(const void* mk, int e) {
    int kind = g_mk_kind;
    if (kind == 0) return ((const unsigned char*)mk)[e] != 0;
    if (kind == 1) return ((const int*)mk)[e] != 0;
    return ((const float*)mk)[e] != 0.0f;
}

__global__ void zero_cnt_kernel() {
    int i = blockIdx.x * blockDim.x + threadIdx.x;
    if (i < N_NODES) g_cnt[i] = 0;
}

__global__ void hist_kernel(const void* __restrict__ ei) {
    int e = blockIdx.x * blockDim.x + threadIdx.x;
    if (e >= N_EDGES) return;
    int t = load_idx(ei, N_EDGES + e);
    if ((unsigned)t < (unsigned)N_NODES) atomicAdd(&g_cnt[t], 1);
}

// one block, 1024 threads, each handles 32 nodes. exclusive scan of g_cnt.
__global__ void scan_kernel() {
    __shared__ int part[1024];
    int tid = threadIdx.x;
    int base = tid * 32;
    int s = 0;
    #pragma unroll 4
    for (int j = 0; j < 32; j++) s += g_cnt[base + j];
    part[tid] = s;
    __syncthreads();
    for (int off = 1; off < 1024; off <<= 1) {
        int v = (tid >= off) ? part[tid - off] : 0;
        __syncthreads();
        part[tid] += v;
        __syncthreads();
    }
    int run = part[tid] - s;   // exclusive prefix for this thread's chunk
    for (int j = 0; j < 32; j++) {
        int idx = base + j;
        int c = g_cnt[idx];
        g_start[idx] = run;
        g_wcur[idx]  = run;
        g_invc[idx]  = 1.0f / fmaxf((float)c, 1.0f);
        run += c;
    }
}

__global__ void scatter_kernel(const void* __restrict__ ei,
                               const void* __restrict__ mk) {
    int e = blockIdx.x * blockDim.x + threadIdx.x;
    if (e >= N_EDGES) return;
    int t    = load_idx(ei, N_EDGES + e);
    int srcv = load_idx(ei, e);
    if ((unsigned)t >= (unsigned)N_NODES) return;
    if ((unsigned)srcv >= (unsigned)N_NODES) return;
    unsigned int p = (unsigned int)srcv | (load_mask(mk, e) ? 0x80000000u : 0u);
    int pos = atomicAdd(&g_wcur[t], 1);
    if (pos < N_EDGES) g_csr[pos] = p;
}

// deterministic ordering: insertion sort each node's edge list (avg deg 16)
__global__ void sort_kernel() {
    int t = blockIdx.x * blockDim.x + threadIdx.x;
    if (t >= N_NODES) return;
    int s0 = g_start[t], d = g_cnt[t];
    for (int i = 1; i < d; i++) {
        unsigned int key = g_csr[s0 + i];
        int j = i - 1;
        while (j >= 0 && g_csr[s0 + j] > key) {
            g_csr[s0 + j + 1] = g_csr[s0 + j];
            j--;
        }
        g_csr[s0 + j + 1] = key;
    }
}

// ---------------------------------------------------------------------------
// Fused GEMM: 64-row h tile -> h@Wn^T+bn, h@Wo^T+bo, h@Wr^T.
// Static smem: hs[64][132] (33792B) + bs[128][18] (9216B) = 43008B < 48KB.
// 256 threads (tx=tid&15, ty=tid>>4); micro-tile 4 rows x 8 cols.
// W streamed in k-slices of 16 (8 slices). All inner-loop LDS conflict-free:
//   a-reads broadcast; b-reads stride 18 (gcd(18,32)=2, period 16 -> distinct).
// ---------------------------------------------------------------------------
__global__ void __launch_bounds__(256)
gemm3_kernel(const float* __restrict__ x,
             const float* __restrict__ Wn, const float* __restrict__ bn,
             const float* __restrict__ Wo, const float* __restrict__ bo,
             const float* __restrict__ Wr, int layer) {
    __shared__ float hs[64 * 132];
    __shared__ float bs[128 * 18];

    const float* hin = (layer == 0) ? x : g_h[(layer - 1) & 1];
    int tid = threadIdx.x;
    int tx = tid & 15, ty = tid >> 4;
    int row0 = blockIdx.x * 64;

    // load h tile (64 x 128), float4, conflict-free
    #pragma unroll
    for (int i = 0; i < 8; i++) {
        int idx = tid + i * 256;          // 0..2047
        int r = idx >> 5, kq = idx & 31;
        float4 v = *(const float4*)(hin + (size_t)(row0 + r) * HD + kq * 4);
        *(float4*)(hs + r * 132 + kq * 4) = v;
    }

    const float* Wp[3] = {Wn, Wo, Wr};
    const float* Bp[3] = {bn, bo, (const float*)0};
    float*       Op[3] = {g_xin, g_xout, g_xroot};

    for (int m = 0; m < 3; m++) {
        const float* Wm = Wp[m];
        float acc[4][8];
        #pragma unroll
        for (int i = 0; i < 4; i++)
            #pragma unroll
            for (int j = 0; j < 8; j++) acc[i][j] = 0.0f;

        for (int sl = 0; sl < HD / BK; sl++) {
            __syncthreads();   // previous slice's reads done (also covers hs on first pass)
            // load W[:, sl*16 .. +15] into bs[o*18 + kk]
            #pragma unroll
            for (int i = 0; i < 2; i++) {
                int fidx = tid + i * 256;      // 0..511 float4 chunks
                int o = fidx >> 2, kc = fidx & 3;
                float4 v = *(const float4*)(Wm + (size_t)o * HD + sl * BK + kc * 4);
                float2* dst = (float2*)(bs + o * 18 + kc * 4);
                dst[0] = make_float2(v.x, v.y);
                dst[1] = make_float2(v.z, v.w);
            }
            __syncthreads();

            const float* hrow0 = hs + (ty * 4 + 0) * 132 + sl * BK;
            const float* hrow1 = hs + (ty * 4 + 1) * 132 + sl * BK;
            const float* hrow2 = hs + (ty * 4 + 2) * 132 + sl * BK;
            const float* hrow3 = hs + (ty * 4 + 3) * 132 + sl * BK;

            #pragma unroll
            for (int kk = 0; kk < BK; kk++) {
                float a0 = hrow0[kk], a1 = hrow1[kk];
                float a2 = hrow2[kk], a3 = hrow3[kk];
                float b[8];
                #pragma unroll
                for (int j = 0; j < 8; j++) b[j] = bs[(tx + 16 * j) * 18 + kk];
                #pragma unroll
                for (int j = 0; j < 8; j++) {
                    acc[0][j] = fmaf(a0, b[j], acc[0][j]);
                    acc[1][j] = fmaf(a1, b[j], acc[1][j]);
                    acc[2][j] = fmaf(a2, b[j], acc[2][j]);
                    acc[3][j] = fmaf(a3, b[j], acc[3][j]);
                }
            }
        }

        const float* bb = Bp[m];
        float* O = Op[m];
        #pragma unroll
        for (int i = 0; i < 4; i++) {
            size_t r = (size_t)(row0 + ty * 4 + i);
            #pragma unroll
            for (int j = 0; j < 8; j++) {
                int c = tx + 16 * j;
                float v = acc[i][j];
                if (bb) v += bb[c];
                O[r * HD + c] = v;
            }
        }
    }
}

// ---------------------------------------------------------------------------
// Aggregation + mean + residual(x_root) + LayerNorm + ReLU. One warp / node.
// ---------------------------------------------------------------------------
__global__ void agg_kernel(const float* __restrict__ lng,
                           const float* __restrict__ lnb, int layer) {
    int gw = (blockIdx.x * blockDim.x + threadIdx.x) >> 5;
    int lane = threadIdx.x & 31;
    if (gw >= N_NODES) return;

    int s0 = g_start[gw], d = g_cnt[gw];
    float ax = 0.f, ay = 0.f, az = 0.f, aw = 0.f;

    for (int c0 = 0; c0 < d; c0 += 32) {
        int m = min(32, d - c0);
        unsigned int pl = (lane < m) ? g_csr[s0 + c0 + lane] : 0u;
        for (int e = 0; e < m; e++) {
            unsigned int p = __shfl_sync(0xffffffffu, pl, e);
            const float* base = (p & 0x80000000u) ? g_xin : g_xout;
            int src = (int)(p & 0x7fffffffu);
            float4 v = *(const float4*)(base + (size_t)src * HD + lane * 4);
            ax += v.x; ay += v.y; az += v.z; aw += v.w;
        }
    }

    float inv = g_invc[gw];
    float4 r4 = *(const float4*)(g_xroot + (size_t)gw * HD + lane * 4);
    float v0 = fmaf(ax, inv, r4.x);
    float v1 = fmaf(ay, inv, r4.y);
    float v2 = fmaf(az, inv, r4.z);
    float v3 = fmaf(aw, inv, r4.w);

    float sum = v0 + v1 + v2 + v3;
    float sq  = v0 * v0 + v1 * v1 + v2 * v2 + v3 * v3;
    #pragma unroll
    for (int o = 16; o; o >>= 1) {
        sum += __shfl_xor_sync(0xffffffffu, sum, o);
        sq  += __shfl_xor_sync(0xffffffffu, sq,  o);
    }
    float mu   = sum * (1.0f / 128.0f);
    float var  = sq * (1.0f / 128.0f) - mu * mu;
    float rstd = rsqrtf(var + 1e-5f);

    int f = lane * 4;
    float o0 = fmaxf((v0 - mu) * rstd * lng[f + 0] + lnb[f + 0], 0.f);
    float o1 = fmaxf((v1 - mu) * rstd * lng[f + 1] + lnb[f + 1], 0.f);
    float o2 = fmaxf((v2 - mu) * rstd * lng[f + 2] + lnb[f + 2], 0.f);
    float o3 = fmaxf((v3 - mu) * rstd * lng[f + 3] + lnb[f + 3], 0.f);

    float* hout = g_h[layer & 1];
    *(float4*)(hout + (size_t)gw * HD + f) = make_float4(o0, o1, o2, o3);
}

// ---------------------------------------------------------------------------
// Per-graph pooling: pooled[c,h] = sum_n s[n,c]*x[n,h]; LN over h; dot lin_w;
// mask by column sums; writes out[g], xc[g,:] and per-graph l1 term.
// ---------------------------------------------------------------------------
__global__ void pool_kernel(const float* __restrict__ s,
                            const float* __restrict__ flng,
                            const float* __restrict__ flnb,
                            const float* __restrict__ linw,
                            const float* __restrict__ bias,
                            float* __restrict__ dout) {
    __shared__ float sd[NPG * NC];     // 8KB
    __shared__ float pl[NC * HD];      // 8KB
    __shared__ float colsum[NC];
    __shared__ float xcs[NC];

    int g = blockIdx.x;
    int tid = threadIdx.x;
    const float* hf = g_h[(NL - 1) & 1];
    const float* xg = hf + (size_t)g * NPG * HD;

    for (int i = tid; i < NPG * NC / 4; i += 256)
        *(float4*)(sd + i * 4) = *(const float4*)(s + (size_t)g * NPG * NC + i * 4);
    __syncthreads();

    if (tid < NC) {
        float cs = 0.f;
        for (int n = 0; n < NPG; n++) cs += sd[n * NC + tid];
        colsum[tid] = cs;
    }

    int hcol = tid & 127;
    int cg = tid >> 7;    // 0..1 (8 channels each)
    float acc[8] = {0, 0, 0, 0, 0, 0, 0, 0};
    #pragma unroll 4
    for (int n = 0; n < NPG; n++) {
        float xv = xg[(size_t)n * HD + hcol];
        #pragma unroll
        for (int c = 0; c < 8; c++)
            acc[c] = fmaf(sd[n * NC + cg * 8 + c], xv, acc[c]);
    }
    #pragma unroll
    for (int c = 0; c < 8; c++) pl[(cg * 8 + c) * HD + hcol] = acc[c];
    __syncthreads();

    int wid = tid >> 5, lane = tid & 31;
    for (int rr = wid * 2; rr < wid * 2 + 2; rr++) {
        float4 v = *(float4*)(pl + rr * HD + lane * 4);
        float sum = v.x + v.y + v.z + v.w;
        float sq  = v.x * v.x + v.y * v.y + v.z * v.z + v.w * v.w;
        #pragma unroll
        for (int o = 16; o; o >>= 1) {
            sum += __shfl_xor_sync(0xffffffffu, sum, o);
            sq  += __shfl_xor_sync(0xffffffffu, sq,  o);
        }
        float mu   = sum * (1.0f / 128.0f);
        float var  = sq * (1.0f / 128.0f) - mu * mu;
        float rstd = rsqrtf(var + 1e-5f);
        int f = lane * 4;
        float dot = ((v.x - mu) * rstd * flng[f + 0] + flnb[f + 0]) * linw[f + 0]
                  + ((v.y - mu) * rstd * flng[f + 1] + flnb[f + 1]) * linw[f + 1]
                  + ((v.z - mu) * rstd * flng[f + 2] + flnb[f + 2]) * linw[f + 2]
                  + ((v.w - mu) * rstd * flng[f + 3] + flnb[f + 3]) * linw[f + 3];
        #pragma unroll
        for (int o = 16; o; o >>= 1) dot += __shfl_xor_sync(0xffffffffu, dot, o);
        if (lane == 0) xcs[rr] = dot;
    }
    __syncthreads();

    if (tid == 0) {
        float ov = 0.f, l1 = 0.f, dn = 0.f;
        #pragma unroll
        for (int c = 0; c < NC; c++) {
            float mflag = (colsum[c] > 0.f) ? 1.f : 0.f;
            float v = xcs[c] * mflag;
            dout[257 + g * NC + c] = v;          // xc
            ov += v;
            l1 += fabsf(v);
            dn += mflag;
        }
        dout[g] = ov + bias[0];                  // out
        g_l1[g] = l1 / (dn + 1e-7f);
    }
}

// losses = 0.01*(sum|Wo|+sum|bo|) + 0.01*mean_g(l1[g])
__global__ void loss_kernel(const float* __restrict__ Wo,
                            const float* __restrict__ bo,
                            float* __restrict__ dout) {
    __shared__ float red[256];
    __shared__ float sreg;
    int tid = threadIdx.x;
    float rs = 0.f;
    for (int i = tid; i < NL * HD * HD; i += 256) rs += fabsf(Wo[i]);
    for (int i = tid; i < NL * HD; i += 256)      rs += fabsf(bo[i]);
    red[tid] = rs;
    __syncthreads();
    for (int o = 128; o; o >>= 1) {
        if (tid < o) red[tid] += red[tid + o];
        __syncthreads();
    }
    if (tid == 0) sreg = red[0];
    __syncthreads();
    float ls = (tid < NG) ? g_l1[tid] : 0.f;
    red[tid] = ls;
    __syncthreads();
    for (int o = 128; o; o >>= 1) {
        if (tid < o) red[tid] += red[tid + o];
        __syncthreads();
    }
    if (tid == 0)
        dout[256] = 0.01f * sreg + 0.01f * (red[0] / (float)NG);
}

// ---------------------------------------------------------------------------
extern "C" void kernel_launch(void* const* d_in, const int* in_sizes, int n_in,
                              void* d_out, int out_size) {
    const float* x    = (const float*)d_in[0];
    const void*  ei   = d_in[1];
    const void*  mk   = d_in[2];
    const float* s    = (const float*)d_in[3];
    // d_in[4] = batch (unused: graphs are equal-size, sorted)
    const float* Wn   = (const float*)d_in[5];
    const float* bn   = (const float*)d_in[6];
    const float* Wo   = (const float*)d_in[7];
    const float* bo   = (const float*)d_in[8];
    const float* Wr   = (const float*)d_in[9];
    const float* lng  = (const float*)d_in[10];
    const float* lnb  = (const float*)d_in[11];
    const float* flng = (const float*)d_in[12];
    const float* flnb = (const float*)d_in[13];
    const float* linw = (const float*)d_in[14];
    const float* bias = (const float*)d_in[15];
    float* out = (float*)d_out;

    detect_kernel<<<1, 1>>>((const unsigned int*)ei, (const unsigned int*)mk);

    // CSR build (deterministic: post-scatter per-node sort)
    zero_cnt_kernel<<<N_NODES / 256, 256>>>();
    hist_kernel<<<N_EDGES / 256, 256>>>(ei);
    scan_kernel<<<1, 1024>>>();
    scatter_kernel<<<N_EDGES / 256, 256>>>(ei, mk);
    sort_kernel<<<N_NODES / 256, 256>>>();

    for (int l = 0; l < NL; l++) {
        gemm3_kernel<<<N_NODES / 64, 256>>>(
            x, Wn + l * HD * HD, bn + l * HD,
            Wo + l * HD * HD, bo + l * HD, Wr + l * HD * HD, l);
        agg_kernel<<<(N_NODES * 32) / 256, 256>>>(lng + l * HD, lnb + l * HD, l);
    }

    pool_kernel<<<NG, 256>>>(s, flng, flnb, linw, bias, out);
    loss_kernel<<<1, 256>>>(Wo, bo, out);
}

// round 3
// speedup vs baseline: 1.0030x; 1.0030x over previous
#include <cuda_runtime.h>
#include <cuda_bf16.h>
#include <stdint.h>

// ---------------------------------------------------------------------------
// SEALNetwork: 3-layer GNN (N=32768, H=128, E=524288) + dense pooling head.
// CSR build (deterministic via per-node sort) -> per layer:
//   fused SGEMM (x_in/x_out/x_root share h tile, static 43KB smem) ->
//   warp-per-node gather/mean/LN/ReLU -> per-graph pooling + LN + linear.
// Input dtypes for edge_index / mask_breaks are runtime-detected on device.
// ---------------------------------------------------------------------------

#define N_NODES 32768
#define N_EDGES 524288
#define NG      256
#define NPG     128
#define HD      128
#define NL      3
#define NC      16
#define BK      16

// scratch (static device globals: allocation-free per harness rules)
__device__ float        g_h[2][N_NODES * HD];
__device__ float        g_xin [N_NODES * HD];
__device__ float        g_xout[N_NODES * HD];
__device__ float        g_xroot[N_NODES * HD];
__device__ int          g_cnt[N_NODES];
__device__ int          g_start[N_NODES];
__device__ int          g_wcur[N_NODES];
__device__ float        g_invc[N_NODES];
__device__ unsigned int g_csr[N_EDGES];
__device__ float        g_l1[NG];
__device__ int          g_ei64;     // 1 if edge_index is int64, 0 if int32
__device__ int          g_mk_kind;  // 0 = uint8/bool, 1 = int32, 2 = float32

// ---------------------------------------------------------------------------
// dtype detection (1 thread, deterministic, reads only in-bounds prefixes)
// ---------------------------------------------------------------------------
__global__ void detect_kernel(const unsigned int* __restrict__ ei_w,
                              const unsigned int* __restrict__ mk_w) {
    // edge_index: if int64 (values < 2^31), every odd 32-bit word is 0.
    int odd_nonzero = 0;
    for (int i = 0; i < 64; i++)
        if (ei_w[2 * i + 1] != 0u) odd_nonzero++;
    g_ei64 = (odd_nonzero == 0) ? 1 : 0;

    // mask_breaks: f32 -> words in {0, 0x3F800000}; u8 -> multi-byte patterns;
    // i32 -> words in {0, 1}.
    int has_f1 = 0, multi = 0;
    for (int i = 0; i < 256; i++) {
        unsigned int w = mk_w[i];
        if (w == 0x3F800000u) { has_f1 = 1; continue; }
        if ((w >> 8) != 0u) multi = 1;  // any byte above byte0 set (not f32 1.0)
    }
    g_mk_kind = has_f1 ? 2 : (multi ? 0 : 1);
}

// ---------------------------------------------------------------------------
// CSR construction
// ---------------------------------------------------------------------------
__device__ __forceinline__ int load_idx(const void* ei, int pos) {
    if (g_ei64) return (int)((const long long*)ei)[pos];
    return ((const int*)ei)[pos];
}

__device__ __forceinline__ bool load_mask(const void* mk, int e) {
    int kind = g_mk_kind;
    if (kind == 0) return ((const unsigned char*)mk)[e] != 0;
    if (kind == 1) return ((const int*)mk)[e] != 0;
    return ((const float*)mk)[e] != 0.0f;
}

__global__ void zero_cnt_kernel() {
    int i = blockIdx.x * blockDim.x + threadIdx.x;
    if (i < N_NODES) g_cnt[i] = 0;
}

__global__ void hist_kernel(const void* __restrict__ ei) {
    int e = blockIdx.x * blockDim.x + threadIdx.x;
    if (e >= N_EDGES) return;
    int t = load_idx(ei, N_EDGES + e);
    if ((unsigned)t < (unsigned)N_NODES) atomicAdd(&g_cnt[t], 1);
}

// one block, 1024 threads, each handles 32 nodes. exclusive scan of g_cnt.
__global__ void scan_kernel() {
    __shared__ int part[1024];
    int tid = threadIdx.x;
    int base = tid * 32;
    int s = 0;
    #pragma unroll 4
    for (int j = 0; j < 32; j++) s += g_cnt[base + j];
    part[tid] = s;
    __syncthreads();
    for (int off = 1; off < 1024; off <<= 1) {
        int v = (tid >= off) ? part[tid - off] : 0;
        __syncthreads();
        part[tid] += v;
        __syncthreads();
    }
    int run = part[tid] - s;   // exclusive prefix for this thread's chunk
    for (int j = 0; j < 32; j++) {
        int idx = base + j;
        int c = g_cnt[idx];
        g_start[idx] = run;
        g_wcur[idx]  = run;
        g_invc[idx]  = 1.0f / fmaxf((float)c, 1.0f);
        run += c;
    }
}

__global__ void scatter_kernel(const void* __restrict__ ei,
                               const void* __restrict__ mk) {
    int e = blockIdx.x * blockDim.x + threadIdx.x;
    if (e >= N_EDGES) return;
    int t    = load_idx(ei, N_EDGES + e);
    int srcv = load_idx(ei, e);
    if ((unsigned)t >= (unsigned)N_NODES) return;
    if ((unsigned)srcv >= (unsigned)N_NODES) return;
    unsigned int p = (unsigned int)srcv | (load_mask(mk, e) ? 0x80000000u : 0u);
    int pos = atomicAdd(&g_wcur[t], 1);
    if (pos < N_EDGES) g_csr[pos] = p;
}

// deterministic ordering: insertion sort each node's edge list (avg deg 16)
__global__ void sort_kernel() {
    int t = blockIdx.x * blockDim.x + threadIdx.x;
    if (t >= N_NODES) return;
    int s0 = g_start[t], d = g_cnt[t];
    for (int i = 1; i < d; i++) {
        unsigned int key = g_csr[s0 + i];
        int j = i - 1;
        while (j >= 0 && g_csr[s0 + j] > key) {
            g_csr[s0 + j + 1] = g_csr[s0 + j];
            j--;
        }
        g_csr[s0 + j + 1] = key;
    }
}

// ---------------------------------------------------------------------------
// Fused GEMM: 64-row h tile -> h@Wn^T+bn, h@Wo^T+bo, h@Wr^T.
// Static smem: hs[64][132] (33792B) + bs[128][18] (9216B) = 43008B < 48KB.
// 256 threads (tx=tid&15, ty=tid>>4); micro-tile 4 rows x 8 cols.
// W streamed in k-slices of 16 (8 slices). All inner-loop LDS conflict-free:
//   a-reads broadcast; b-reads stride 18 (gcd(18,32)=2, period 16 -> distinct).
// ---------------------------------------------------------------------------
__global__ void __launch_bounds__(256)
gemm3_kernel(const float* __restrict__ x,
             const float* __restrict__ Wn, const float* __restrict__ bn,
             const float* __restrict__ Wo, const float* __restrict__ bo,
             const float* __restrict__ Wr, int layer) {
    __shared__ float hs[64 * 132];
    __shared__ float bs[128 * 18];

    const float* hin = (layer == 0) ? x : g_h[(layer - 1) & 1];
    int tid = threadIdx.x;
    int tx = tid & 15, ty = tid >> 4;
    int row0 = blockIdx.x * 64;

    // load h tile (64 x 128), float4, conflict-free
    #pragma unroll
    for (int i = 0; i < 8; i++) {
        int idx = tid + i * 256;          // 0..2047
        int r = idx >> 5, kq = idx & 31;
        float4 v = *(const float4*)(hin + (size_t)(row0 + r) * HD + kq * 4);
        *(float4*)(hs + r * 132 + kq * 4) = v;
    }

    const float* Wp[3] = {Wn, Wo, Wr};
    const float* Bp[3] = {bn, bo, (const float*)0};
    float*       Op[3] = {g_xin, g_xout, g_xroot};

    for (int m = 0; m < 3; m++) {
        const float* Wm = Wp[m];
        float acc[4][8];
        #pragma unroll
        for (int i = 0; i < 4; i++)
            #pragma unroll
            for (int j = 0; j < 8; j++) acc[i][j] = 0.0f;

        for (int sl = 0; sl < HD / BK; sl++) {
            __syncthreads();   // previous slice's reads done (also covers hs on first pass)
            // load W[:, sl*16 .. +15] into bs[o*18 + kk]
            #pragma unroll
            for (int i = 0; i < 2; i++) {
                int fidx = tid + i * 256;      // 0..511 float4 chunks
                int o = fidx >> 2, kc = fidx & 3;
                float4 v = *(const float4*)(Wm + (size_t)o * HD + sl * BK + kc * 4);
                float2* dst = (float2*)(bs + o * 18 + kc * 4);
                dst[0] = make_float2(v.x, v.y);
                dst[1] = make_float2(v.z, v.w);
            }
            __syncthreads();

            const float* hrow0 = hs + (ty * 4 + 0) * 132 + sl * BK;
            const float* hrow1 = hs + (ty * 4 + 1) * 132 + sl * BK;
            const float* hrow2 = hs + (ty * 4 + 2) * 132 + sl * BK;
            const float* hrow3 = hs + (ty * 4 + 3) * 132 + sl * BK;

            #pragma unroll
            for (int kk = 0; kk < BK; kk++) {
                float a0 = hrow0[kk], a1 = hrow1[kk];
                float a2 = hrow2[kk], a3 = hrow3[kk];
                float b[8];
                #pragma unroll
                for (int j = 0; j < 8; j++) b[j] = bs[(tx + 16 * j) * 18 + kk];
                #pragma unroll
                for (int j = 0; j < 8; j++) {
                    acc[0][j] = fmaf(a0, b[j], acc[0][j]);
                    acc[1][j] = fmaf(a1, b[j], acc[1][j]);
                    acc[2][j] = fmaf(a2, b[j], acc[2][j]);
                    acc[3][j] = fmaf(a3, b[j], acc[3][j]);
                }
            }
        }

        const float* bb = Bp[m];
        float* O = Op[m];
        #pragma unroll
        for (int i = 0; i < 4; i++) {
            size_t r = (size_t)(row0 + ty * 4 + i);
            #pragma unroll
            for (int j = 0; j < 8; j++) {
                int c = tx + 16 * j;
                float v = acc[i][j];
                if (bb) v += bb[c];
                O[r * HD + c] = v;
            }
        }
    }
}

// ---------------------------------------------------------------------------
// Aggregation + mean + residual(x_root) + LayerNorm + ReLU. One warp / node.
// ---------------------------------------------------------------------------
__global__ void agg_kernel(const float* __restrict__ lng,
                           const float* __restrict__ lnb, int layer) {
    int gw = (blockIdx.x * blockDim.x + threadIdx.x) >> 5;
    int lane = threadIdx.x & 31;
    if (gw >= N_NODES) return;

    int s0 = g_start[gw], d = g_cnt[gw];
    float ax = 0.f, ay = 0.f, az = 0.f, aw = 0.f;

    for (int c0 = 0; c0 < d; c0 += 32) {
        int m = min(32, d - c0);
        unsigned int pl = (lane < m) ? g_csr[s0 + c0 + lane] : 0u;
        for (int e = 0; e < m; e++) {
            unsigned int p = __shfl_sync(0xffffffffu, pl, e);
            const float* base = (p & 0x80000000u) ? g_xin : g_xout;
            int src = (int)(p & 0x7fffffffu);
            float4 v = *(const float4*)(base + (size_t)src * HD + lane * 4);
            ax += v.x; ay += v.y; az += v.z; aw += v.w;
        }
    }

    float inv = g_invc[gw];
    float4 r4 = *(const float4*)(g_xroot + (size_t)gw * HD + lane * 4);
    float v0 = fmaf(ax, inv, r4.x);
    float v1 = fmaf(ay, inv, r4.y);
    float v2 = fmaf(az, inv, r4.z);
    float v3 = fmaf(aw, inv, r4.w);

    float sum = v0 + v1 + v2 + v3;
    float sq  = v0 * v0 + v1 * v1 + v2 * v2 + v3 * v3;
    #pragma unroll
    for (int o = 16; o; o >>= 1) {
        sum += __shfl_xor_sync(0xffffffffu, sum, o);
        sq  += __shfl_xor_sync(0xffffffffu, sq,  o);
    }
    float mu   = sum * (1.0f / 128.0f);
    float var  = sq * (1.0f / 128.0f) - mu * mu;
    float rstd = rsqrtf(var + 1e-5f);

    int f = lane * 4;
    float o0 = fmaxf((v0 - mu) * rstd * lng[f + 0] + lnb[f + 0], 0.f);
    float o1 = fmaxf((v1 - mu) * rstd * lng[f + 1] + lnb[f + 1], 0.f);
    float o2 = fmaxf((v2 - mu) * rstd * lng[f + 2] + lnb[f + 2], 0.f);
    float o3 = fmaxf((v3 - mu) * rstd * lng[f + 3] + lnb[f + 3], 0.f);

    float* hout = g_h[layer & 1];
    *(float4*)(hout + (size_t)gw * HD + f) = make_float4(o0, o1, o2, o3);
}

// ---------------------------------------------------------------------------
// Per-graph pooling: pooled[c,h] = sum_n s[n,c]*x[n,h]; LN over h; dot lin_w;
// mask by column sums; writes out[g], xc[g,:] and per-graph l1 term.
// ---------------------------------------------------------------------------
__global__ void pool_kernel(const float* __restrict__ s,
                            const float* __restrict__ flng,
                            const float* __restrict__ flnb,
                            const float* __restrict__ linw,
                            const float* __restrict__ bias,
                            float* __restrict__ dout) {
    __shared__ float sd[NPG * NC];     // 8KB
    __shared__ float pl[NC * HD];      // 8KB
    __shared__ float colsum[NC];
    __shared__ float xcs[NC];

    int g = blockIdx.x;
    int tid = threadIdx.x;
    const float* hf = g_h[(NL - 1) & 1];
    const float* xg = hf + (size_t)g * NPG * HD;

    for (int i = tid; i < NPG * NC / 4; i += 256)
        *(float4*)(sd + i * 4) = *(const float4*)(s + (size_t)g * NPG * NC + i * 4);
    __syncthreads();

    if (tid < NC) {
        float cs = 0.f;
        for (int n = 0; n < NPG; n++) cs += sd[n * NC + tid];
        colsum[tid] = cs;
    }

    int hcol = tid & 127;
    int cg = tid >> 7;    // 0..1 (8 channels each)
    float acc[8] = {0, 0, 0, 0, 0, 0, 0, 0};
    #pragma unroll 4
    for (int n = 0; n < NPG; n++) {
        float xv = xg[(size_t)n * HD + hcol];
        #pragma unroll
        for (int c = 0; c < 8; c++)
            acc[c] = fmaf(sd[n * NC + cg * 8 + c], xv, acc[c]);
    }
    #pragma unroll
    for (int c = 0; c < 8; c++) pl[(cg * 8 + c) * HD + hcol] = acc[c];
    __syncthreads();

    int wid = tid >> 5, lane = tid & 31;
    for (int rr = wid * 2; rr < wid * 2 + 2; rr++) {
        float4 v = *(float4*)(pl + rr * HD + lane * 4);
        float sum = v.x + v.y + v.z + v.w;
        float sq  = v.x * v.x + v.y * v.y + v.z * v.z + v.w * v.w;
        #pragma unroll
        for (int o = 16; o; o >>= 1) {
            sum += __shfl_xor_sync(0xffffffffu, sum, o);
            sq  += __shfl_xor_sync(0xffffffffu, sq,  o);
        }
        float mu   = sum * (1.0f / 128.0f);
        float var  = sq * (1.0f / 128.0f) - mu * mu;
        float rstd = rsqrtf(var + 1e-5f);
        int f = lane * 4;
        float dot = ((v.x - mu) * rstd * flng[f + 0] + flnb[f + 0]) * linw[f + 0]
                  + ((v.y - mu) * rstd * flng[f + 1] + flnb[f + 1]) * linw[f + 1]
                  + ((v.z - mu) * rstd * flng[f + 2] + flnb[f + 2]) * linw[f + 2]
                  + ((v.w - mu) * rstd * flng[f + 3] + flnb[f + 3]) * linw[f + 3];
        #pragma unroll
        for (int o = 16; o; o >>= 1) dot += __shfl_xor_sync(0xffffffffu, dot, o);
        if (lane == 0) xcs[rr] = dot;
    }
    __syncthreads();

    if (tid == 0) {
        float ov = 0.f, l1 = 0.f, dn = 0.f;
        #pragma unroll
        for (int c = 0; c < NC; c++) {
            float mflag = (colsum[c] > 0.f) ? 1.f : 0.f;
            float v = xcs[c] * mflag;
            dout[257 + g * NC + c] = v;          // xc
            ov += v;
            l1 += fabsf(v);
            dn += mflag;
        }
        dout[g] = ov + bias[0];                  // out
        g_l1[g] = l1 / (dn + 1e-7f);
    }
}

// losses = 0.01*(sum|Wo|+sum|bo|) + 0.01*mean_g(l1[g])
__global__ void loss_kernel(const float* __restrict__ Wo,
                            const float* __restrict__ bo,
                            float* __restrict__ dout) {
    __shared__ float red[256];
    __shared__ float sreg;
    int tid = threadIdx.x;
    float rs = 0.f;
    for (int i = tid; i < NL * HD * HD; i += 256) rs += fabsf(Wo[i]);
    for (int i = tid; i < NL * HD; i += 256)      rs += fabsf(bo[i]);
    red[tid] = rs;
    __syncthreads();
    for (int o = 128; o; o >>= 1) {
        if (tid < o) red[tid] += red[tid + o];
        __syncthreads();
    }
    if (tid == 0) sreg = red[0];
    __syncthreads();
    float ls = (tid < NG) ? g_l1[tid] : 0.f;
    red[tid] = ls;
    __syncthreads();
    for (int o = 128; o; o >>= 1) {
        if (tid < o) red[tid] += red[tid + o];
        __syncthreads();
    }
    if (tid == 0)
        dout[256] = 0.01f * sreg + 0.01f * (red[0] / (float)NG);
}

// ---------------------------------------------------------------------------
extern "C" void kernel_launch(void* const* d_in, const int* in_sizes, int n_in,
                              void* d_out, int out_size) {
    const float* x    = (const float*)d_in[0];
    const void*  ei   = d_in[1];
    const void*  mk   = d_in[2];
    const float* s    = (const float*)d_in[3];
    // d_in[4] = batch (unused: graphs are equal-size, sorted)
    const float* Wn   = (const float*)d_in[5];
    const float* bn   = (const float*)d_in[6];
    const float* Wo   = (const float*)d_in[7];
    const float* bo   = (const float*)d_in[8];
    const float* Wr   = (const float*)d_in[9];
    const float* lng  = (const float*)d_in[10];
    const float* lnb  = (const float*)d_in[11];
    const float* flng = (const float*)d_in[12];
    const float* flnb = (const float*)d_in[13];
    const float* linw = (const float*)d_in[14];
    const float* bias = (const float*)d_in[15];
    float* out = (float*)d_out;

    detect_kernel<<<1, 1>>>((const unsigned int*)ei, (const unsigned int*)mk);

    // CSR build (deterministic: post-scatter per-node sort)
    zero_cnt_kernel<<<N_NODES / 256, 256>>>();
    hist_kernel<<<N_EDGES / 256, 256>>>(ei);
    scan_kernel<<<1, 1024>>>();
    scatter_kernel<<<N_EDGES / 256, 256>>>(ei, mk);
    sort_kernel<<<N_NODES / 256, 256>>>();

    for (int l = 0; l < NL; l++) {
        gemm3_kernel<<<N_NODES / 64, 256>>>(
            x, Wn + l * HD * HD, bn + l * HD,
            Wo + l * HD * HD, bo + l * HD, Wr + l * HD * HD, l);
        agg_kernel<<<(N_NODES * 32) / 256, 256>>>(lng + l * HD, lnb + l * HD, l);
    }

    pool_kernel<<<NG, 256>>>(s, flng, flnb, linw, bias, out);
    loss_kernel<<<1, 256>>>(Wo, bo, out);
}

// round 4
// speedup vs baseline: 1.4034x; 1.3991x over previous
#include <cuda_runtime.h>
#include <cuda_bf16.h>
#include <stdint.h>

// ---------------------------------------------------------------------------
// SEALNetwork: 3-layer GNN (N=32768, H=128, E=524288) + dense pooling head.
// CSR build (parallel scan, deterministic per-node sort) -> per layer:
//   fused SGEMM with packed fma.rn.f32x2 (x_in/x_out/x_root share h tile) ->
//   warp-per-node gather/mean/LN/ReLU -> per-graph pooling + LN + linear.
// ---------------------------------------------------------------------------

#define N_NODES 32768
#define N_EDGES 524288
#define NG      256
#define NPG     128
#define HD      128
#define NL      3
#define NC      16
#define BK      16
#define BSTR    130   // transposed-W smem stride (floats)

// scratch (static device globals: allocation-free per harness rules)
__device__ float        g_h[2][N_NODES * HD];
__device__ float        g_xin [N_NODES * HD];
__device__ float        g_xout[N_NODES * HD];
__device__ float        g_xroot[N_NODES * HD];
__device__ int          g_cnt[N_NODES];
__device__ int          g_start[N_NODES];
__device__ int          g_wcur[N_NODES];
__device__ float        g_invc[N_NODES];
__device__ unsigned int g_csr[N_EDGES];
__device__ float        g_l1[NG];
__device__ int          g_part[256];
__device__ int          g_poff[256];
__device__ int          g_ei64;     // 1 if edge_index is int64, 0 if int32
__device__ int          g_mk_kind;  // 0 = uint8/bool, 1 = int32, 2 = float32

// ---------------------------------------------------------------------------
// f32x2 packed helpers
// ---------------------------------------------------------------------------
__device__ __forceinline__ unsigned long long splat2(float a) {
    unsigned long long r;
    unsigned int ai = __float_as_uint(a);
    asm("mov.b64 %0, {%1, %1};" : "=l"(r) : "r"(ai));
    return r;
}
__device__ __forceinline__ void fma2(unsigned long long& acc,
                                     unsigned long long a,
                                     unsigned long long b) {
    asm("fma.rn.f32x2 %0, %1, %2, %0;" : "+l"(acc) : "l"(a), "l"(b));
}

// ---------------------------------------------------------------------------
// dtype detection (1 thread, deterministic, reads only in-bounds prefixes)
// ---------------------------------------------------------------------------
__global__ void detect_kernel(const unsigned int* __restrict__ ei_w,
                              const unsigned int* __restrict__ mk_w) {
    int odd_nonzero = 0;
    for (int i = 0; i < 64; i++)
        if (ei_w[2 * i + 1] != 0u) odd_nonzero++;
    g_ei64 = (odd_nonzero == 0) ? 1 : 0;

    int has_f1 = 0, multi = 0;
    for (int i = 0; i < 256; i++) {
        unsigned int w = mk_w[i];
        if (w == 0x3F800000u) { has_f1 = 1; continue; }
        if ((w >> 8) != 0u) multi = 1;
    }
    g_mk_kind = has_f1 ? 2 : (multi ? 0 : 1);
}

// ---------------------------------------------------------------------------
// CSR construction
// ---------------------------------------------------------------------------
__device__ __forceinline__ int load_idx(const void* ei, int pos) {
    if (g_ei64) return (int)((const long long*)ei)[pos];
    return ((const int*)ei)[pos];
}
__device__ __forceinline__ bool load_mask(const void* mk, int e) {
    int kind = g_mk_kind;
    if (kind == 0) return ((const unsigned char*)mk)[e] != 0;
    if (kind == 1) return ((const int*)mk)[e] != 0;
    return ((const float*)mk)[e] != 0.0f;
}

__global__ void zero_cnt_kernel() {
    int i = blockIdx.x * blockDim.x + threadIdx.x;
    if (i < N_NODES) g_cnt[i] = 0;
}

__global__ void hist_kernel(const void* __restrict__ ei) {
    int e = blockIdx.x * blockDim.x + threadIdx.x;
    if (e >= N_EDGES) return;
    int t = load_idx(ei, N_EDGES + e);
    if ((unsigned)t < (unsigned)N_NODES) atomicAdd(&g_cnt[t], 1);
}

// phase 1: per-block (128 nodes) exclusive scan; block total -> g_part
__global__ void scan1_kernel() {
    __shared__ int sm[128];
    int b = blockIdx.x, tid = threadIdx.x;
    int i = b * 128 + tid;
    int v = g_cnt[i];
    sm[tid] = v;
    __syncthreads();
    #pragma unroll
    for (int off = 1; off < 128; off <<= 1) {
        int t = (tid >= off) ? sm[tid - off] : 0;
        __syncthreads();
        sm[tid] += t;
        __syncthreads();
    }
    g_start[i] = sm[tid] - v;            // block-local exclusive prefix
    if (tid == 127) g_part[b] = sm[127];
}

// phase 2: 1 block, exclusive scan of 256 block totals
__global__ void scan2_kernel() {
    __shared__ int sm[256];
    int tid = threadIdx.x;
    int v = g_part[tid];
    sm[tid] = v;
    __syncthreads();
    #pragma unroll
    for (int off = 1; off < 256; off <<= 1) {
        int t = (tid >= off) ? sm[tid - off] : 0;
        __syncthreads();
        sm[tid] += t;
        __syncthreads();
    }
    g_poff[tid] = sm[tid] - v;
}

// phase 3: add block offsets, init wcur/invc
__global__ void scan3_kernel() {
    int b = blockIdx.x, tid = threadIdx.x;
    int i = b * 128 + tid;
    int s = g_start[i] + g_poff[b];
    g_start[i] = s;
    g_wcur[i]  = s;
    g_invc[i]  = 1.0f / fmaxf((float)g_cnt[i], 1.0f);
}

__global__ void scatter_kernel(const void* __restrict__ ei,
                               const void* __restrict__ mk) {
    int e = blockIdx.x * blockDim.x + threadIdx.x;
    if (e >= N_EDGES) return;
    int t    = load_idx(ei, N_EDGES + e);
    int srcv = load_idx(ei, e);
    if ((unsigned)t >= (unsigned)N_NODES) return;
    if ((unsigned)srcv >= (unsigned)N_NODES) return;
    unsigned int p = (unsigned int)srcv | (load_mask(mk, e) ? 0x80000000u : 0u);
    int pos = atomicAdd(&g_wcur[t], 1);
    if (pos < N_EDGES) g_csr[pos] = p;
}

// deterministic ordering: sort each node's edge list (local buffer fast path)
__global__ void sort_kernel() {
    int t = blockIdx.x * blockDim.x + threadIdx.x;
    if (t >= N_NODES) return;
    int s0 = g_start[t], d = g_cnt[t];
    if (d <= 1) return;
    if (d <= 64) {
        unsigned int buf[64];
        for (int i = 0; i < d; i++) buf[i] = g_csr[s0 + i];
        for (int i = 1; i < d; i++) {
            unsigned int key = buf[i];
            int j = i - 1;
            while (j >= 0 && buf[j] > key) { buf[j + 1] = buf[j]; j--; }
            buf[j + 1] = key;
        }
        for (int i = 0; i < d; i++) g_csr[s0 + i] = buf[i];
    } else {
        for (int i = 1; i < d; i++) {
            unsigned int key = g_csr[s0 + i];
            int j = i - 1;
            while (j >= 0 && g_csr[s0 + j] > key) {
                g_csr[s0 + j + 1] = g_csr[s0 + j];
                j--;
            }
            g_csr[s0 + j + 1] = key;
        }
    }
}

// ---------------------------------------------------------------------------
// Fused GEMM (packed f32x2): 64-row h tile -> h@Wn^T+bn, h@Wo^T+bo, h@Wr^T.
// smem: hs[64][132] (33792B) + transposed W slice bs[16][130] (8320B) = 42KB.
// 256 threads: tx=tid&15, ty=tid>>4. Thread tile: 4 rows x 4 column-PAIRS
// (cols tx*2+32*j+{0,1}), accumulators in packed f32x2; b-operand is a
// natural LDS.64 from the transposed slice; a-operand splatted via mov.b64.
// ---------------------------------------------------------------------------
__global__ void __launch_bounds__(256)
gemm3_kernel(const float* __restrict__ x,
             const float* __restrict__ Wn, const float* __restrict__ bn,
             const float* __restrict__ Wo, const float* __restrict__ bo,
             const float* __restrict__ Wr, int layer) {
    __shared__ float hs[64 * 132];
    __shared__ float bs[BK * BSTR];

    const float* hin = (layer == 0) ? x : g_h[(layer - 1) & 1];
    int tid = threadIdx.x;
    int tx = tid & 15, ty = tid >> 4;
    int row0 = blockIdx.x * 64;

    // load h tile (64 x 128), float4, conflict-free
    #pragma unroll
    for (int i = 0; i < 8; i++) {
        int idx = tid + i * 256;
        int r = idx >> 5, kq = idx & 31;
        float4 v = *(const float4*)(hin + (size_t)(row0 + r) * HD + kq * 4);
        *(float4*)(hs + r * 132 + kq * 4) = v;
    }

    const float* Wp[3] = {Wn, Wo, Wr};
    const float* Bp[3] = {bn, bo, (const float*)0};
    float*       Op[3] = {g_xin, g_xout, g_xroot};

    for (int m = 0; m < 3; m++) {
        const float* Wm = Wp[m];
        unsigned long long acc2[4][4];
        #pragma unroll
        for (int i = 0; i < 4; i++)
            #pragma unroll
            for (int j = 0; j < 4; j++) acc2[i][j] = 0ull;

        for (int sl = 0; sl < HD / BK; sl++) {
            __syncthreads();   // previous slice's reads done (covers hs first pass)
            // load W[:, sl*16..+15] TRANSPOSED into bs[kk][o]
            #pragma unroll
            for (int i = 0; i < 2; i++) {
                int fidx = tid + i * 256;          // 0..511
                int o = fidx >> 2, kc = fidx & 3;  // o: out col, kc: k-chunk
                float4 v = *(const float4*)(Wm + (size_t)o * HD + sl * BK + kc * 4);
                bs[(kc * 4 + 0) * BSTR + o] = v.x;
                bs[(kc * 4 + 1) * BSTR + o] = v.y;
                bs[(kc * 4 + 2) * BSTR + o] = v.z;
                bs[(kc * 4 + 3) * BSTR + o] = v.w;
            }
            __syncthreads();

            const float* hrow0 = hs + (ty * 4 + 0) * 132 + sl * BK;
            const float* hrow1 = hs + (ty * 4 + 1) * 132 + sl * BK;
            const float* hrow2 = hs + (ty * 4 + 2) * 132 + sl * BK;
            const float* hrow3 = hs + (ty * 4 + 3) * 132 + sl * BK;

            #pragma unroll 4
            for (int kk = 0; kk < BK; kk++) {
                unsigned long long a0 = splat2(hrow0[kk]);
                unsigned long long a1 = splat2(hrow1[kk]);
                unsigned long long a2 = splat2(hrow2[kk]);
                unsigned long long a3 = splat2(hrow3[kk]);
                const unsigned long long* bp =
                    (const unsigned long long*)(bs + kk * BSTR + tx * 2);
                #pragma unroll
                for (int j = 0; j < 4; j++) {
                    unsigned long long b2 = bp[16 * j];   // cols tx*2+32j, +1
                    fma2(acc2[0][j], a0, b2);
                    fma2(acc2[1][j], a1, b2);
                    fma2(acc2[2][j], a2, b2);
                    fma2(acc2[3][j], a3, b2);
                }
            }
        }

        const float* bb = Bp[m];
        float* O = Op[m];
        #pragma unroll
        for (int i = 0; i < 4; i++) {
            size_t r = (size_t)(row0 + ty * 4 + i);
            #pragma unroll
            for (int j = 0; j < 4; j++) {
                int c0 = tx * 2 + 32 * j;
                float lo = __uint_as_float((unsigned int)(acc2[i][j]));
                float hi = __uint_as_float((unsigned int)(acc2[i][j] >> 32));
                if (bb) { lo += bb[c0]; hi += bb[c0 + 1]; }
                *(float2*)(O + r * HD + c0) = make_float2(lo, hi);
            }
        }
    }
}

// ---------------------------------------------------------------------------
// Aggregation + mean + residual(x_root) + LayerNorm + ReLU. One warp / node.
// ---------------------------------------------------------------------------
__global__ void agg_kernel(const float* __restrict__ lng,
                           const float* __restrict__ lnb, int layer) {
    int gw = (blockIdx.x * blockDim.x + threadIdx.x) >> 5;
    int lane = threadIdx.x & 31;
    if (gw >= N_NODES) return;

    int s0 = g_start[gw], d = g_cnt[gw];
    float ax = 0.f, ay = 0.f, az = 0.f, aw = 0.f;

    for (int c0 = 0; c0 < d; c0 += 32) {
        int m = min(32, d - c0);
        unsigned int pl = (lane < m) ? g_csr[s0 + c0 + lane] : 0u;
        for (int e = 0; e < m; e++) {
            unsigned int p = __shfl_sync(0xffffffffu, pl, e);
            const float* base = (p & 0x80000000u) ? g_xin : g_xout;
            int src = (int)(p & 0x7fffffffu);
            float4 v = *(const float4*)(base + (size_t)src * HD + lane * 4);
            ax += v.x; ay += v.y; az += v.z; aw += v.w;
        }
    }

    float inv = g_invc[gw];
    float4 r4 = *(const float4*)(g_xroot + (size_t)gw * HD + lane * 4);
    float v0 = fmaf(ax, inv, r4.x);
    float v1 = fmaf(ay, inv, r4.y);
    float v2 = fmaf(az, inv, r4.z);
    float v3 = fmaf(aw, inv, r4.w);

    float sum = v0 + v1 + v2 + v3;
    float sq  = v0 * v0 + v1 * v1 + v2 * v2 + v3 * v3;
    #pragma unroll
    for (int o = 16; o; o >>= 1) {
        sum += __shfl_xor_sync(0xffffffffu, sum, o);
        sq  += __shfl_xor_sync(0xffffffffu, sq,  o);
    }
    float mu   = sum * (1.0f / 128.0f);
    float var  = sq * (1.0f / 128.0f) - mu * mu;
    float rstd = rsqrtf(var + 1e-5f);

    int f = lane * 4;
    float o0 = fmaxf((v0 - mu) * rstd * lng[f + 0] + lnb[f + 0], 0.f);
    float o1 = fmaxf((v1 - mu) * rstd * lng[f + 1] + lnb[f + 1], 0.f);
    float o2 = fmaxf((v2 - mu) * rstd * lng[f + 2] + lnb[f + 2], 0.f);
    float o3 = fmaxf((v3 - mu) * rstd * lng[f + 3] + lnb[f + 3], 0.f);

    float* hout = g_h[layer & 1];
    *(float4*)(hout + (size_t)gw * HD + f) = make_float4(o0, o1, o2, o3);
}

// ---------------------------------------------------------------------------
// Per-graph pooling head
// ---------------------------------------------------------------------------
__global__ void pool_kernel(const float* __restrict__ s,
                            const float* __restrict__ flng,
                            const float* __restrict__ flnb,
                            const float* __restrict__ linw,
                            const float* __restrict__ bias,
                            float* __restrict__ dout) {
    __shared__ float sd[NPG * NC];
    __shared__ float pl[NC * HD];
    __shared__ float colsum[NC];
    __shared__ float xcs[NC];

    int g = blockIdx.x;
    int tid = threadIdx.x;
    const float* hf = g_h[(NL - 1) & 1];
    const float* xg = hf + (size_t)g * NPG * HD;

    for (int i = tid; i < NPG * NC / 4; i += 256)
        *(float4*)(sd + i * 4) = *(const float4*)(s + (size_t)g * NPG * NC + i * 4);
    __syncthreads();

    if (tid < NC) {
        float cs = 0.f;
        for (int n = 0; n < NPG; n++) cs += sd[n * NC + tid];
        colsum[tid] = cs;
    }

    int hcol = tid & 127;
    int cg = tid >> 7;
    float acc[8] = {0, 0, 0, 0, 0, 0, 0, 0};
    #pragma unroll 4
    for (int n = 0; n < NPG; n++) {
        float xv = xg[(size_t)n * HD + hcol];
        #pragma unroll
        for (int c = 0; c < 8; c++)
            acc[c] = fmaf(sd[n * NC + cg * 8 + c], xv, acc[c]);
    }
    #pragma unroll
    for (int c = 0; c < 8; c++) pl[(cg * 8 + c) * HD + hcol] = acc[c];
    __syncthreads();

    int wid = tid >> 5, lane = tid & 31;
    for (int rr = wid * 2; rr < wid * 2 + 2; rr++) {
        float4 v = *(float4*)(pl + rr * HD + lane * 4);
        float sum = v.x + v.y + v.z + v.w;
        float sq  = v.x * v.x + v.y * v.y + v.z * v.z + v.w * v.w;
        #pragma unroll
        for (int o = 16; o; o >>= 1) {
            sum += __shfl_xor_sync(0xffffffffu, sum, o);
            sq  += __shfl_xor_sync(0xffffffffu, sq,  o);
        }
        float mu   = sum * (1.0f / 128.0f);
        float var  = sq * (1.0f / 128.0f) - mu * mu;
        float rstd = rsqrtf(var + 1e-5f);
        int f = lane * 4;
        float dot = ((v.x - mu) * rstd * flng[f + 0] + flnb[f + 0]) * linw[f + 0]
                  + ((v.y - mu) * rstd * flng[f + 1] + flnb[f + 1]) * linw[f + 1]
                  + ((v.z - mu) * rstd * flng[f + 2] + flnb[f + 2]) * linw[f + 2]
                  + ((v.w - mu) * rstd * flng[f + 3] + flnb[f + 3]) * linw[f + 3];
        #pragma unroll
        for (int o = 16; o; o >>= 1) dot += __shfl_xor_sync(0xffffffffu, dot, o);
        if (lane == 0) xcs[rr] = dot;
    }
    __syncthreads();

    if (tid == 0) {
        float ov = 0.f, l1 = 0.f, dn = 0.f;
        #pragma unroll
        for (int c = 0; c < NC; c++) {
            float mflag = (colsum[c] > 0.f) ? 1.f : 0.f;
            float v = xcs[c] * mflag;
            dout[257 + g * NC + c] = v;          // xc
            ov += v;
            l1 += fabsf(v);
            dn += mflag;
        }
        dout[g] = ov + bias[0];                  // out
        g_l1[g] = l1 / (dn + 1e-7f);
    }
}

// losses = 0.01*(sum|Wo|+sum|bo|) + 0.01*mean_g(l1[g])
__global__ void loss_kernel(const float* __restrict__ Wo,
                            const float* __restrict__ bo,
                            float* __restrict__ dout) {
    __shared__ float red[256];
    __shared__ float sreg;
    int tid = threadIdx.x;
    float rs = 0.f;
    for (int i = tid; i < NL * HD * HD; i += 256) rs += fabsf(Wo[i]);
    for (int i = tid; i < NL * HD; i += 256)      rs += fabsf(bo[i]);
    red[tid] = rs;
    __syncthreads();
    for (int o = 128; o; o >>= 1) {
        if (tid < o) red[tid] += red[tid + o];
        __syncthreads();
    }
    if (tid == 0) sreg = red[0];
    __syncthreads();
    float ls = (tid < NG) ? g_l1[tid] : 0.f;
    red[tid] = ls;
    __syncthreads();
    for (int o = 128; o; o >>= 1) {
        if (tid < o) red[tid] += red[tid + o];
        __syncthreads();
    }
    if (tid == 0)
        dout[256] = 0.01f * sreg + 0.01f * (red[0] / (float)NG);
}

// ---------------------------------------------------------------------------
extern "C" void kernel_launch(void* const* d_in, const int* in_sizes, int n_in,
                              void* d_out, int out_size) {
    const float* x    = (const float*)d_in[0];
    const void*  ei   = d_in[1];
    const void*  mk   = d_in[2];
    const float* s    = (const float*)d_in[3];
    // d_in[4] = batch (unused: graphs are equal-size, sorted)
    const float* Wn   = (const float*)d_in[5];
    const float* bn   = (const float*)d_in[6];
    const float* Wo   = (const float*)d_in[7];
    const float* bo   = (const float*)d_in[8];
    const float* Wr   = (const float*)d_in[9];
    const float* lng  = (const float*)d_in[10];
    const float* lnb  = (const float*)d_in[11];
    const float* flng = (const float*)d_in[12];
    const float* flnb = (const float*)d_in[13];
    const float* linw = (const float*)d_in[14];
    const float* bias = (const float*)d_in[15];
    float* out = (float*)d_out;

    detect_kernel<<<1, 1>>>((const unsigned int*)ei, (const unsigned int*)mk);

    // CSR build (parallel scan, deterministic post-scatter per-node sort)
    zero_cnt_kernel<<<N_NODES / 256, 256>>>();
    hist_kernel<<<N_EDGES / 256, 256>>>(ei);
    scan1_kernel<<<256, 128>>>();
    scan2_kernel<<<1, 256>>>();
    scan3_kernel<<<256, 128>>>();
    scatter_kernel<<<N_EDGES / 256, 256>>>(ei, mk);
    sort_kernel<<<N_NODES / 256, 256>>>();

    for (int l = 0; l < NL; l++) {
        gemm3_kernel<<<N_NODES / 64, 256>>>(
            x, Wn + l * HD * HD, bn + l * HD,
            Wo + l * HD * HD, bo + l * HD, Wr + l * HD * HD, l);
        agg_kernel<<<(N_NODES * 32) / 256, 256>>>(lng + l * HD, lnb + l * HD, l);
    }

    pool_kernel<<<NG, 256>>>(s, flng, flnb, linw, bias, out);
    loss_kernel<<<1, 256>>>(Wo, bo, out);
}

// round 6
// speedup vs baseline: 1.4723x; 1.0491x over previous
#include <cuda_runtime.h>
#include <cuda_bf16.h>
#include <stdint.h>

// ---------------------------------------------------------------------------
// SEALNetwork: 3-layer GNN (N=32768, H=128, E=524288) + dense pooling head.
// CSR build (parallel scan, deterministic per-node sort) -> per layer:
//   mma.sync bf16-split GEMM (x_in/x_out/x_root share converted h tile) ->
//   warp-per-node gather/mean/LN/ReLU -> per-graph pooling + LN + linear.
// (tcgen05 is rejected by the harness toolchain: PTX target is sm_103 non-a,
//  so tensor work goes through standard HMMA mma.sync instead.)
// ---------------------------------------------------------------------------

#define N_NODES 32768
#define N_EDGES 524288
#define NG      256
#define NPG     128
#define HD      128
#define NL      3
#define NC      16
#define ASTR    136   // bf16 smem row stride (272B): ldmatrix conflict-free

// scratch (static device globals: allocation-free per harness rules)
__device__ float        g_h[2][N_NODES * HD];
__device__ float        g_xin [N_NODES * HD];
__device__ float        g_xout[N_NODES * HD];
__device__ float        g_xroot[N_NODES * HD];
__device__ int          g_cnt[N_NODES];
__device__ int          g_start[N_NODES];
__device__ int          g_wcur[N_NODES];
__device__ float        g_invc[N_NODES];
__device__ unsigned int g_csr[N_EDGES];
__device__ float        g_l1[NG];
__device__ int          g_part[256];
__device__ int          g_poff[256];
__device__ int          g_ei64;     // 1 if edge_index is int64, 0 if int32
__device__ int          g_mk_kind;  // 0 = uint8/bool, 1 = int32, 2 = float32

// ---------------------------------------------------------------------------
// helpers
// ---------------------------------------------------------------------------
__device__ __forceinline__ uint32_t smem_u32(const void* p) {
    uint32_t a;
    asm("{ .reg .u64 t; cvta.to.shared.u64 t, %1; cvt.u32.u64 %0, t; }"
        : "=r"(a) : "l"(p));
    return a;
}

__device__ __forceinline__ void ldm_x4(uint32_t& r0, uint32_t& r1,
                                       uint32_t& r2, uint32_t& r3,
                                       uint32_t addr) {
    asm volatile("ldmatrix.sync.aligned.m8n8.x4.shared.b16 {%0,%1,%2,%3}, [%4];"
                 : "=r"(r0), "=r"(r1), "=r"(r2), "=r"(r3) : "r"(addr));
}

__device__ __forceinline__ void mma_bf16(float* c, const uint32_t* a,
                                         uint32_t b0, uint32_t b1) {
    asm volatile(
        "mma.sync.aligned.m16n8k16.row.col.f32.bf16.bf16.f32 "
        "{%0,%1,%2,%3}, {%4,%5,%6,%7}, {%8,%9}, {%0,%1,%2,%3};"
        : "+f"(c[0]), "+f"(c[1]), "+f"(c[2]), "+f"(c[3])
        : "r"(a[0]), "r"(a[1]), "r"(a[2]), "r"(a[3]), "r"(b0), "r"(b1));
}

// ---------------------------------------------------------------------------
// dtype detection (1 thread, deterministic, reads only in-bounds prefixes)
// ---------------------------------------------------------------------------
__global__ void detect_kernel(const unsigned int* __restrict__ ei_w,
                              const unsigned int* __restrict__ mk_w) {
    int odd_nonzero = 0;
    for (int i = 0; i < 64; i++)
        if (ei_w[2 * i + 1] != 0u) odd_nonzero++;
    g_ei64 = (odd_nonzero == 0) ? 1 : 0;

    int has_f1 = 0, multi = 0;
    for (int i = 0; i < 256; i++) {
        unsigned int w = mk_w[i];
        if (w == 0x3F800000u) { has_f1 = 1; continue; }
        if ((w >> 8) != 0u) multi = 1;
    }
    g_mk_kind = has_f1 ? 2 : (multi ? 0 : 1);
}

// ---------------------------------------------------------------------------
// CSR construction
// ---------------------------------------------------------------------------
__device__ __forceinline__ int load_idx(const void* ei, int pos) {
    if (g_ei64) return (int)((const long long*)ei)[pos];
    return ((const int*)ei)[pos];
}
__device__ __forceinline__ bool load_mask(const void* mk, int e) {
    int kind = g_mk_kind;
    if (kind == 0) return ((const unsigned char*)mk)[e] != 0;
    if (kind == 1) return ((const int*)mk)[e] != 0;
    return ((const float*)mk)[e] != 0.0f;
}

__global__ void zero_cnt_kernel() {
    int i = blockIdx.x * blockDim.x + threadIdx.x;
    if (i < N_NODES) g_cnt[i] = 0;
}

__global__ void hist_kernel(const void* __restrict__ ei) {
    int e = blockIdx.x * blockDim.x + threadIdx.x;
    if (e >= N_EDGES) return;
    int t = load_idx(ei, N_EDGES + e);
    if ((unsigned)t < (unsigned)N_NODES) atomicAdd(&g_cnt[t], 1);
}

__global__ void scan1_kernel() {
    __shared__ int sm[128];
    int b = blockIdx.x, tid = threadIdx.x;
    int i = b * 128 + tid;
    int v = g_cnt[i];
    sm[tid] = v;
    __syncthreads();
    #pragma unroll
    for (int off = 1; off < 128; off <<= 1) {
        int t = (tid >= off) ? sm[tid - off] : 0;
        __syncthreads();
        sm[tid] += t;
        __syncthreads();
    }
    g_start[i] = sm[tid] - v;
    if (tid == 127) g_part[b] = sm[127];
}

__global__ void scan2_kernel() {
    __shared__ int sm[256];
    int tid = threadIdx.x;
    int v = g_part[tid];
    sm[tid] = v;
    __syncthreads();
    #pragma unroll
    for (int off = 1; off < 256; off <<= 1) {
        int t = (tid >= off) ? sm[tid - off] : 0;
        __syncthreads();
        sm[tid] += t;
        __syncthreads();
    }
    g_poff[tid] = sm[tid] - v;
}

__global__ void scan3_kernel() {
    int b = blockIdx.x, tid = threadIdx.x;
    int i = b * 128 + tid;
    int s = g_start[i] + g_poff[b];
    g_start[i] = s;
    g_wcur[i]  = s;
    g_invc[i]  = 1.0f / fmaxf((float)g_cnt[i], 1.0f);
}

__global__ void scatter_kernel(const void* __restrict__ ei,
                               const void* __restrict__ mk) {
    int e = blockIdx.x * blockDim.x + threadIdx.x;
    if (e >= N_EDGES) return;
    int t    = load_idx(ei, N_EDGES + e);
    int srcv = load_idx(ei, e);
    if ((unsigned)t >= (unsigned)N_NODES) return;
    if ((unsigned)srcv >= (unsigned)N_NODES) return;
    unsigned int p = (unsigned int)srcv | (load_mask(mk, e) ? 0x80000000u : 0u);
    int pos = atomicAdd(&g_wcur[t], 1);
    if (pos < N_EDGES) g_csr[pos] = p;
}

__global__ void sort_kernel() {
    int t = blockIdx.x * blockDim.x + threadIdx.x;
    if (t >= N_NODES) return;
    int s0 = g_start[t], d = g_cnt[t];
    if (d <= 1) return;
    if (d <= 64) {
        unsigned int buf[64];
        for (int i = 0; i < d; i++) buf[i] = g_csr[s0 + i];
        for (int i = 1; i < d; i++) {
            unsigned int key = buf[i];
            int j = i - 1;
            while (j >= 0 && buf[j] > key) { buf[j + 1] = buf[j]; j--; }
            buf[j + 1] = key;
        }
        for (int i = 0; i < d; i++) g_csr[s0 + i] = buf[i];
    } else {
        for (int i = 1; i < d; i++) {
            unsigned int key = g_csr[s0 + i];
            int j = i - 1;
            while (j >= 0 && g_csr[s0 + j] > key) {
                g_csr[s0 + j + 1] = g_csr[s0 + j];
                j--;
            }
            g_csr[s0 + j + 1] = key;
        }
    }
}

// ---------------------------------------------------------------------------
// HMMA fused GEMM: per CTA one 128-row h tile, K=128, N=128.
// bf16 split (hi/lo): D = Ah*Bh + Ah*Bl + Al*Bh  (~fp32 accuracy).
// 512 threads = 16 warps; warp tile 32x32 (2 m-tiles x 4 n-tiles m16n8k16).
// smem: Ah|Al|Bh|Bl, each [128][ASTR] bf16. B buffers reused per matrix.
// ---------------------------------------------------------------------------
#define GEMM_DSMEM (4 * 128 * ASTR * 2)

__global__ void __launch_bounds__(512)
gemm3_mma_kernel(const float* __restrict__ x,
                 const float* __restrict__ Wn, const float* __restrict__ bn,
                 const float* __restrict__ Wo, const float* __restrict__ bo,
                 const float* __restrict__ Wr, int layer) {
    extern __shared__ __align__(16) char dyn[];
    __nv_bfloat16* Ah = (__nv_bfloat16*)dyn;
    __nv_bfloat16* Al = Ah + 128 * ASTR;
    __nv_bfloat16* Bh = Al + 128 * ASTR;
    __nv_bfloat16* Bl = Bh + 128 * ASTR;

    int tid  = threadIdx.x;
    int w    = tid >> 5, lane = tid & 31;
    int m_blk = (w >> 2) * 32, n_blk = (w & 3) * 32;
    int grp  = lane >> 2, tig = lane & 3;
    int row0 = blockIdx.x * 128;

    uint32_t AhA = smem_u32(Ah), AlA = smem_u32(Al);
    uint32_t BhA = smem_u32(Bh), BlA = smem_u32(Bl);

    const float* hin = (layer == 0) ? x : g_h[(layer - 1) & 1];

    // --- convert A (h tile) -> Ah/Al, packed bf16x2 stores ---
    #pragma unroll
    for (int i = 0; i < 8; i++) {
        int f4 = tid + i * 512;               // 0..4095 float4 chunks
        int r = f4 >> 5, c4 = (f4 & 31) * 4;
        float4 v = *(const float4*)(hin + (size_t)(row0 + r) * HD + c4);
        __nv_bfloat16 h0 = __float2bfloat16(v.x), h1 = __float2bfloat16(v.y);
        __nv_bfloat16 h2 = __float2bfloat16(v.z), h3 = __float2bfloat16(v.w);
        __nv_bfloat16 l0 = __float2bfloat16(v.x - __bfloat162float(h0));
        __nv_bfloat16 l1 = __float2bfloat16(v.y - __bfloat162float(h1));
        __nv_bfloat16 l2 = __float2bfloat16(v.z - __bfloat162float(h2));
        __nv_bfloat16 l3 = __float2bfloat16(v.w - __bfloat162float(h3));
        int base = r * ASTR + c4;
        *(__nv_bfloat162*)(Ah + base)     = __nv_bfloat162(h0, h1);
        *(__nv_bfloat162*)(Ah + base + 2) = __nv_bfloat162(h2, h3);
        *(__nv_bfloat162*)(Al + base)     = __nv_bfloat162(l0, l1);
        *(__nv_bfloat162*)(Al + base + 2) = __nv_bfloat162(l2, l3);
    }

    const float* Wp[3] = {Wn, Wo, Wr};
    const float* BiP[3] = {bn, bo, (const float*)0};
    float*       Op[3] = {g_xin, g_xout, g_xroot};

    // ldmatrix source addresses (element offsets *2 for bytes)
    // A tiles: lanes 0-7 rows+0 k0 | 8-15 rows+8 k0 | 16-23 rows+0 k8 | 24-31 rows+8 k8
    int a_row = (lane & 15);
    int a_kof = (lane >> 4) << 3;
    // B tiles: lanes 0-7 n+0 k0 | 8-15 n+0 k8 | 16-23 n+8 k0 | 24-31 n+8 k8
    int b_row = ((lane & 16) >> 1) + (lane & 7);
    int b_kof = (lane & 8);

    for (int m = 0; m < 3; m++) {
        // --- convert B (weight m) -> Bh/Bl ---
        const float* Wm = Wp[m];
        #pragma unroll
        for (int i = 0; i < 8; i++) {
            int f4 = tid + i * 512;
            int r = f4 >> 5, c4 = (f4 & 31) * 4;
            float4 v = *(const float4*)(Wm + (size_t)r * HD + c4);
            __nv_bfloat16 h0 = __float2bfloat16(v.x), h1 = __float2bfloat16(v.y);
            __nv_bfloat16 h2 = __float2bfloat16(v.z), h3 = __float2bfloat16(v.w);
            __nv_bfloat16 l0 = __float2bfloat16(v.x - __bfloat162float(h0));
            __nv_bfloat16 l1 = __float2bfloat16(v.y - __bfloat162float(h1));
            __nv_bfloat16 l2 = __float2bfloat16(v.z - __bfloat162float(h2));
            __nv_bfloat16 l3 = __float2bfloat16(v.w - __bfloat162float(h3));
            int base = r * ASTR + c4;
            *(__nv_bfloat162*)(Bh + base)     = __nv_bfloat162(h0, h1);
            *(__nv_bfloat162*)(Bh + base + 2) = __nv_bfloat162(h2, h3);
            *(__nv_bfloat162*)(Bl + base)     = __nv_bfloat162(l0, l1);
            *(__nv_bfloat162*)(Bl + base + 2) = __nv_bfloat162(l2, l3);
        }
        __syncthreads();

        float acc[2][4][4];
        #pragma unroll
        for (int mt = 0; mt < 2; mt++)
            #pragma unroll
            for (int nt = 0; nt < 4; nt++)
                #pragma unroll
                for (int q = 0; q < 4; q++) acc[mt][nt][q] = 0.0f;

        #pragma unroll
        for (int p = 0; p < 3; p++) {
            uint32_t Ab = (p == 2) ? AlA : AhA;
            uint32_t Bb = (p == 1) ? BlA : BhA;
            #pragma unroll
            for (int ks = 0; ks < 8; ks++) {
                int k0 = ks * 16;
                uint32_t a[2][4];
                #pragma unroll
                for (int mt = 0; mt < 2; mt++) {
                    uint32_t addr = Ab + (uint32_t)(
                        (m_blk + mt * 16 + a_row) * ASTR + k0 + a_kof) * 2;
                    ldm_x4(a[mt][0], a[mt][1], a[mt][2], a[mt][3], addr);
                }
                uint32_t bfr[4][2];
                #pragma unroll
                for (int np = 0; np < 2; np++) {
                    uint32_t addr = Bb + (uint32_t)(
                        (n_blk + np * 16 + b_row) * ASTR + k0 + b_kof) * 2;
                    uint32_t r0, r1, r2, r3;
                    ldm_x4(r0, r1, r2, r3, addr);
                    bfr[np * 2 + 0][0] = r0; bfr[np * 2 + 0][1] = r1;
                    bfr[np * 2 + 1][0] = r2; bfr[np * 2 + 1][1] = r3;
                }
                #pragma unroll
                for (int mt = 0; mt < 2; mt++)
                    #pragma unroll
                    for (int nt = 0; nt < 4; nt++)
                        mma_bf16(acc[mt][nt], a[mt], bfr[nt][0], bfr[nt][1]);
            }
        }

        // --- epilogue: write acc (+bias) to output matrix m ---
        const float* bb = BiP[m];
        float* O = Op[m];
        #pragma unroll
        for (int mt = 0; mt < 2; mt++) {
            #pragma unroll
            for (int nt = 0; nt < 4; nt++) {
                int rg = row0 + m_blk + mt * 16 + grp;
                int cg = n_blk + nt * 8 + tig * 2;
                float b0 = bb ? bb[cg] : 0.f, b1 = bb ? bb[cg + 1] : 0.f;
                *(float2*)(O + (size_t)rg * HD + cg) =
                    make_float2(acc[mt][nt][0] + b0, acc[mt][nt][1] + b1);
                *(float2*)(O + (size_t)(rg + 8) * HD + cg) =
                    make_float2(acc[mt][nt][2] + b0, acc[mt][nt][3] + b1);
            }
        }
        __syncthreads();   // before overwriting Bh/Bl for next matrix
    }
}

// ---------------------------------------------------------------------------
// Aggregation + mean + residual(x_root) + LayerNorm + ReLU. One warp / node.
// ---------------------------------------------------------------------------
__global__ void agg_kernel(const float* __restrict__ lng,
                           const float* __restrict__ lnb, int layer) {
    int gw = (blockIdx.x * blockDim.x + threadIdx.x) >> 5;
    int lane = threadIdx.x & 31;
    if (gw >= N_NODES) return;

    int s0 = g_start[gw], d = g_cnt[gw];
    float ax = 0.f, ay = 0.f, az = 0.f, aw = 0.f;

    for (int c0 = 0; c0 < d; c0 += 32) {
        int m = min(32, d - c0);
        unsigned int pl = (lane < m) ? g_csr[s0 + c0 + lane] : 0u;
        for (int e = 0; e < m; e++) {
            unsigned int p = __shfl_sync(0xffffffffu, pl, e);
            const float* base = (p & 0x80000000u) ? g_xin : g_xout;
            int src = (int)(p & 0x7fffffffu);
            float4 v = *(const float4*)(base + (size_t)src * HD + lane * 4);
            ax += v.x; ay += v.y; az += v.z; aw += v.w;
        }
    }

    float inv = g_invc[gw];
    float4 r4 = *(const float4*)(g_xroot + (size_t)gw * HD + lane * 4);
    float v0 = fmaf(ax, inv, r4.x);
    float v1 = fmaf(ay, inv, r4.y);
    float v2 = fmaf(az, inv, r4.z);
    float v3 = fmaf(aw, inv, r4.w);

    float sum = v0 + v1 + v2 + v3;
    float sq  = v0 * v0 + v1 * v1 + v2 * v2 + v3 * v3;
    #pragma unroll
    for (int o = 16; o; o >>= 1) {
        sum += __shfl_xor_sync(0xffffffffu, sum, o);
        sq  += __shfl_xor_sync(0xffffffffu, sq,  o);
    }
    float mu   = sum * (1.0f / 128.0f);
    float var  = sq * (1.0f / 128.0f) - mu * mu;
    float rstd = rsqrtf(var + 1e-5f);

    int f = lane * 4;
    float o0 = fmaxf((v0 - mu) * rstd * lng[f + 0] + lnb[f + 0], 0.f);
    float o1 = fmaxf((v1 - mu) * rstd * lng[f + 1] + lnb[f + 1], 0.f);
    float o2 = fmaxf((v2 - mu) * rstd * lng[f + 2] + lnb[f + 2], 0.f);
    float o3 = fmaxf((v3 - mu) * rstd * lng[f + 3] + lnb[f + 3], 0.f);

    float* hout = g_h[layer & 1];
    *(float4*)(hout + (size_t)gw * HD + f) = make_float4(o0, o1, o2, o3);
}

// ---------------------------------------------------------------------------
// Per-graph pooling head
// ---------------------------------------------------------------------------
__global__ void pool_kernel(const float* __restrict__ s,
                            const float* __restrict__ flng,
                            const float* __restrict__ flnb,
                            const float* __restrict__ linw,
                            const float* __restrict__ bias,
                            float* __restrict__ dout) {
    __shared__ float sd[NPG * NC];
    __shared__ float pl[NC * HD];
    __shared__ float colsum[NC];
    __shared__ float xcs[NC];

    int g = blockIdx.x;
    int tid = threadIdx.x;
    const float* hf = g_h[(NL - 1) & 1];
    const float* xg = hf + (size_t)g * NPG * HD;

    for (int i = tid; i < NPG * NC / 4; i += 256)
        *(float4*)(sd + i * 4) = *(const float4*)(s + (size_t)g * NPG * NC + i * 4);
    __syncthreads();

    if (tid < NC) {
        float cs = 0.f;
        for (int n = 0; n < NPG; n++) cs += sd[n * NC + tid];
        colsum[tid] = cs;
    }

    int hcol = tid & 127;
    int cg = tid >> 7;
    float acc[8] = {0, 0, 0, 0, 0, 0, 0, 0};
    #pragma unroll 4
    for (int n = 0; n < NPG; n++) {
        float xv = xg[(size_t)n * HD + hcol];
        #pragma unroll
        for (int c = 0; c < 8; c++)
            acc[c] = fmaf(sd[n * NC + cg * 8 + c], xv, acc[c]);
    }
    #pragma unroll
    for (int c = 0; c < 8; c++) pl[(cg * 8 + c) * HD + hcol] = acc[c];
    __syncthreads();

    int wid = tid >> 5, lane = tid & 31;
    for (int rr = wid * 2; rr < wid * 2 + 2; rr++) {
        float4 v = *(float4*)(pl + rr * HD + lane * 4);
        float sum = v.x + v.y + v.z + v.w;
        float sq  = v.x * v.x + v.y * v.y + v.z * v.z + v.w * v.w;
        #pragma unroll
        for (int o = 16; o; o >>= 1) {
            sum += __shfl_xor_sync(0xffffffffu, sum, o);
            sq  += __shfl_xor_sync(0xffffffffu, sq,  o);
        }
        float mu   = sum * (1.0f / 128.0f);
        float var  = sq * (1.0f / 128.0f) - mu * mu;
        float rstd = rsqrtf(var + 1e-5f);
        int f = lane * 4;
        float dot = ((v.x - mu) * rstd * flng[f + 0] + flnb[f + 0]) * linw[f + 0]
                  + ((v.y - mu) * rstd * flng[f + 1] + flnb[f + 1]) * linw[f + 1]
                  + ((v.z - mu) * rstd * flng[f + 2] + flnb[f + 2]) * linw[f + 2]
                  + ((v.w - mu) * rstd * flng[f + 3] + flnb[f + 3]) * linw[f + 3];
        #pragma unroll
        for (int o = 16; o; o >>= 1) dot += __shfl_xor_sync(0xffffffffu, dot, o);
        if (lane == 0) xcs[rr] = dot;
    }
    __syncthreads();

    if (tid == 0) {
        float ov = 0.f, l1 = 0.f, dn = 0.f;
        #pragma unroll
        for (int c = 0; c < NC; c++) {
            float mflag = (colsum[c] > 0.f) ? 1.f : 0.f;
            float v = xcs[c] * mflag;
            dout[257 + g * NC + c] = v;          // xc
            ov += v;
            l1 += fabsf(v);
            dn += mflag;
        }
        dout[g] = ov + bias[0];                  // out
        g_l1[g] = l1 / (dn + 1e-7f);
    }
}

// losses = 0.01*(sum|Wo|+sum|bo|) + 0.01*mean_g(l1[g])
__global__ void loss_kernel(const float* __restrict__ Wo,
                            const float* __restrict__ bo,
                            float* __restrict__ dout) {
    __shared__ float red[256];
    __shared__ float sreg;
    int tid = threadIdx.x;
    float rs = 0.f;
    for (int i = tid; i < NL * HD * HD; i += 256) rs += fabsf(Wo[i]);
    for (int i = tid; i < NL * HD; i += 256)      rs += fabsf(bo[i]);
    red[tid] = rs;
    __syncthreads();
    for (int o = 128; o; o >>= 1) {
        if (tid < o) red[tid] += red[tid + o];
        __syncthreads();
    }
    if (tid == 0) sreg = red[0];
    __syncthreads();
    float ls = (tid < NG) ? g_l1[tid] : 0.f;
    red[tid] = ls;
    __syncthreads();
    for (int o = 128; o; o >>= 1) {
        if (tid < o) red[tid] += red[tid + o];
        __syncthreads();
    }
    if (tid == 0)
        dout[256] = 0.01f * sreg + 0.01f * (red[0] / (float)NG);
}

// ---------------------------------------------------------------------------
extern "C" void kernel_launch(void* const* d_in, const int* in_sizes, int n_in,
                              void* d_out, int out_size) {
    const float* x    = (const float*)d_in[0];
    const void*  ei   = d_in[1];
    const void*  mk   = d_in[2];
    const float* s    = (const float*)d_in[3];
    // d_in[4] = batch (unused: graphs are equal-size, sorted)
    const float* Wn   = (const float*)d_in[5];
    const float* bn   = (const float*)d_in[6];
    const float* Wo   = (const float*)d_in[7];
    const float* bo   = (const float*)d_in[8];
    const float* Wr   = (const float*)d_in[9];
    const float* lng  = (const float*)d_in[10];
    const float* lnb  = (const float*)d_in[11];
    const float* flng = (const float*)d_in[12];
    const float* flnb = (const float*)d_in[13];
    const float* linw = (const float*)d_in[14];
    const float* bias = (const float*)d_in[15];
    float* out = (float*)d_out;

    cudaFuncSetAttribute(gemm3_mma_kernel,
                         cudaFuncAttributeMaxDynamicSharedMemorySize, GEMM_DSMEM);

    detect_kernel<<<1, 1>>>((const unsigned int*)ei, (const unsigned int*)mk);

    // CSR build (parallel scan, deterministic post-scatter per-node sort)
    zero_cnt_kernel<<<N_NODES / 256, 256>>>();
    hist_kernel<<<N_EDGES / 256, 256>>>(ei);
    scan1_kernel<<<256, 128>>>();
    scan2_kernel<<<1, 256>>>();
    scan3_kernel<<<256, 128>>>();
    scatter_kernel<<<N_EDGES / 256, 256>>>(ei, mk);
    sort_kernel<<<N_NODES / 256, 256>>>();

    for (int l = 0; l < NL; l++) {
        gemm3_mma_kernel<<<N_NODES / 128, 512, GEMM_DSMEM>>>(
            x, Wn + l * HD * HD, bn + l * HD,
            Wo + l * HD * HD, bo + l * HD, Wr + l * HD * HD, l);
        agg_kernel<<<(N_NODES * 32) / 256, 256>>>(lng + l * HD, lnb + l * HD, l);
    }

    pool_kernel<<<NG, 256>>>(s, flng, flnb, linw, bias, out);
    loss_kernel<<<1, 256>>>(Wo, bo, out);
}

// round 8
// speedup vs baseline: 1.7440x; 1.1846x over previous
#include <cuda_runtime.h>
#include <cuda_bf16.h>
#include <stdint.h>

// ---------------------------------------------------------------------------
// SEALNetwork: 3-layer GNN (N=32768, H=128, E=524288) + dense pooling head.
// KEY STRUCTURE: edges are within-graph and each graph = 128 nodes = 1 CTA,
// so mean-aggregation is a dense per-graph GEMM with integer-count adjacency
// matrices (exact in bf16). Whole layer fused into ONE kernel:
//   h -> (split bf16) -> 3 weight HMMA GEMMs -> x_in/x_out transposed-split
//   in smem -> adjacency HMMA GEMMs -> mean + x_root + LN + ReLU -> h.
// No CSR, no sort, no intermediate global traffic.
// ---------------------------------------------------------------------------

#define N_NODES 32768
#define N_EDGES 524288
#define NG      256
#define NPG     128
#define HD      128
#define NL      3
#define NC      16
#define ASTR    136              // bf16 smem row stride (272B)
#define TSZ     17408            // 128*ASTR elements per smem buffer
#define ADJ_EL  (NG * NPG * NPG) // 4194304 per adjacency matrix

// scratch (static device globals: allocation-free per harness rules)
__device__ float         g_h[2][N_NODES * HD];
__device__ int           g_cnt[N_NODES];
__device__ float         g_invc[N_NODES];
__device__ float         g_l1[NG];
__device__ float         g_adj_f[2][ADJ_EL];       // [0]=masked(in), [1]=out
__device__ __nv_bfloat16 g_adj_b[2][ADJ_EL];
__device__ int           g_ei64;     // 1 if edge_index is int64, 0 if int32
__device__ int           g_mk_kind;  // 0 = uint8/bool, 1 = int32, 2 = float32

// ---------------------------------------------------------------------------
// helpers
// ---------------------------------------------------------------------------
__device__ __forceinline__ uint32_t smem_u32(const void* p) {
    uint32_t a;
    asm("{ .reg .u64 t; cvta.to.shared.u64 t, %1; cvt.u32.u64 %0, t; }"
        : "=r"(a) : "l"(p));
    return a;
}

__device__ __forceinline__ void ldm_x4(uint32_t& r0, uint32_t& r1,
                                       uint32_t& r2, uint32_t& r3,
                                       uint32_t addr) {
    asm volatile("ldmatrix.sync.aligned.m8n8.x4.shared.b16 {%0,%1,%2,%3}, [%4];"
                 : "=r"(r0), "=r"(r1), "=r"(r2), "=r"(r3) : "r"(addr));
}

__device__ __forceinline__ void mma_bf16(float* c, const uint32_t* a,
                                         uint32_t b0, uint32_t b1) {
    asm volatile(
        "mma.sync.aligned.m16n8k16.row.col.f32.bf16.bf16.f32 "
        "{%0,%1,%2,%3}, {%4,%5,%6,%7}, {%8,%9}, {%0,%1,%2,%3};"
        : "+f"(c[0]), "+f"(c[1]), "+f"(c[2]), "+f"(c[3])
        : "r"(a[0]), "r"(a[1]), "r"(a[2]), "r"(a[3]), "r"(b0), "r"(b1));
}

// one full K=128 pass: acc += A(128x128 from Abase) * B^T(128x128 from Bbase)
__device__ __forceinline__ void gemm_pass(float acc[2][4][4],
                                          uint32_t Abase, uint32_t Bbase,
                                          int m_blk, int n_blk,
                                          int a_row, int a_kof,
                                          int b_row, int b_kof) {
    #pragma unroll
    for (int ks = 0; ks < 8; ks++) {
        int k0 = ks * 16;
        uint32_t a[2][4];
        #pragma unroll
        for (int mt = 0; mt < 2; mt++) {
            uint32_t addr = Abase + (uint32_t)(
                (m_blk + mt * 16 + a_row) * ASTR + k0 + a_kof) * 2;
            ldm_x4(a[mt][0], a[mt][1], a[mt][2], a[mt][3], addr);
        }
        uint32_t bfr[4][2];
        #pragma unroll
        for (int np = 0; np < 2; np++) {
            uint32_t addr = Bbase + (uint32_t)(
                (n_blk + np * 16 + b_row) * ASTR + k0 + b_kof) * 2;
            uint32_t r0, r1, r2, r3;
            ldm_x4(r0, r1, r2, r3, addr);
            bfr[np * 2 + 0][0] = r0; bfr[np * 2 + 0][1] = r1;
            bfr[np * 2 + 1][0] = r2; bfr[np * 2 + 1][1] = r3;
        }
        #pragma unroll
        for (int mt = 0; mt < 2; mt++)
            #pragma unroll
            for (int nt = 0; nt < 4; nt++)
                mma_bf16(acc[mt][nt], a[mt], bfr[nt][0], bfr[nt][1]);
    }
}

// ---------------------------------------------------------------------------
// dtype detection (1 thread, deterministic, reads only in-bounds prefixes)
// ---------------------------------------------------------------------------
__global__ void detect_kernel(const unsigned int* __restrict__ ei_w,
                              const unsigned int* __restrict__ mk_w) {
    int odd_nonzero = 0;
    for (int i = 0; i < 64; i++)
        if (ei_w[2 * i + 1] != 0u) odd_nonzero++;
    g_ei64 = (odd_nonzero == 0) ? 1 : 0;

    int has_f1 = 0, multi = 0;
    for (int i = 0; i < 256; i++) {
        unsigned int w = mk_w[i];
        if (w == 0x3F800000u) { has_f1 = 1; continue; }
        if ((w >> 8) != 0u) multi = 1;
    }
    g_mk_kind = has_f1 ? 2 : (multi ? 0 : 1);
}

__device__ __forceinline__ int load_idx(const void* ei, int pos) {
    if (g_ei64) return (int)((const long long*)ei)[pos];
    return ((const int*)ei)[pos];
}
__device__ __forceinline__ bool load_mask(const void* mk, int e) {
    int kind = g_mk_kind;
    if (kind == 0) return ((const unsigned char*)mk)[e] != 0;
    if (kind == 1) return ((const int*)mk)[e] != 0;
    return ((const float*)mk)[e] != 0.0f;
}

// ---------------------------------------------------------------------------
// adjacency pipeline
// ---------------------------------------------------------------------------
__global__ void zero_all_kernel() {
    int stride = gridDim.x * blockDim.x;
    int i0 = blockIdx.x * blockDim.x + threadIdx.x;
    float4 z = make_float4(0.f, 0.f, 0.f, 0.f);
    for (int i = i0; i < ADJ_EL / 4; i += stride) {
        *(float4*)(&g_adj_f[0][i * 4]) = z;
        *(float4*)(&g_adj_f[1][i * 4]) = z;
    }
    for (int i = i0; i < N_NODES; i += stride) g_cnt[i] = 0;
}

// fused in-degree histogram + dense adjacency build (float counts: exact,
// commutative -> deterministic)
__global__ void adj_build_kernel(const void* __restrict__ ei,
                                 const void* __restrict__ mk) {
    int e = blockIdx.x * blockDim.x + threadIdx.x;
    if (e >= N_EDGES) return;
    int t = load_idx(ei, N_EDGES + e);
    int s = load_idx(ei, e);
    if ((unsigned)t >= (unsigned)N_NODES) return;
    if ((unsigned)s >= (unsigned)N_NODES) return;
    if ((t >> 7) != (s >> 7)) return;           // edges are within-graph
    atomicAdd(&g_cnt[t], 1);
    int sel = load_mask(mk, e) ? 0 : 1;
    size_t idx = ((size_t)(t >> 7) * NPG + (t & 127)) * NPG + (s & 127);
    atomicAdd(&g_adj_f[sel][idx], 1.0f);
}

__global__ void adj_finish_kernel() {
    int stride = gridDim.x * blockDim.x;
    int i0 = blockIdx.x * blockDim.x + threadIdx.x;
    for (int i = i0; i < ADJ_EL / 2; i += stride) {
        float2 a = *(const float2*)(&g_adj_f[0][i * 2]);
        float2 b = *(const float2*)(&g_adj_f[1][i * 2]);
        *(__nv_bfloat162*)(&g_adj_b[0][i * 2]) =
            __nv_bfloat162(__float2bfloat16(a.x), __float2bfloat16(a.y));
        *(__nv_bfloat162*)(&g_adj_b[1][i * 2]) =
            __nv_bfloat162(__float2bfloat16(b.x), __float2bfloat16(b.y));
    }
    for (int i = i0; i < N_NODES; i += stride)
        g_invc[i] = 1.0f / fmaxf((float)g_cnt[i], 1.0f);
}

// ---------------------------------------------------------------------------
// Fully fused layer kernel. 256 CTAs (one per graph), 512 threads (16 warps,
// warp tile 32x32). smem buffers (bf16, stride ASTR):
//   A0/A1: h tile hi/lo     B0/B1: W hi/lo, then x^T hi/lo   C0/C1: Adj in/out
// After GEMMs, A region is reused as fp32 LN scratch [128][132].
// ---------------------------------------------------------------------------
#define LAYER_SMEM (6 * TSZ * 2)

__global__ void __launch_bounds__(512)
layer_kernel(const float* __restrict__ x,
             const float* __restrict__ Wn, const float* __restrict__ bn,
             const float* __restrict__ Wo, const float* __restrict__ bo,
             const float* __restrict__ Wr,
             const float* __restrict__ lng, const float* __restrict__ lnb,
             int layer) {
    extern __shared__ __align__(16) char dyn[];
    __nv_bfloat16* A0 = (__nv_bfloat16*)dyn;
    __nv_bfloat16* A1 = A0 + TSZ;
    __nv_bfloat16* B0 = A1 + TSZ;
    __nv_bfloat16* B1 = B0 + TSZ;
    __nv_bfloat16* C0 = B1 + TSZ;
    __nv_bfloat16* C1 = C0 + TSZ;
    float* S = (float*)dyn;              // reuse A region: 128*132*4 <= 2*TSZ*2

    int tid = threadIdx.x;
    int w = tid >> 5, lane = tid & 31;
    int m_blk = (w >> 2) * 32, n_blk = (w & 3) * 32;
    int grp = lane >> 2, tig = lane & 3;
    int g = blockIdx.x, row0 = g * 128;

    uint32_t A0a = smem_u32(A0), A1a = smem_u32(A1);
    uint32_t B0a = smem_u32(B0), B1a = smem_u32(B1);
    uint32_t C0a = smem_u32(C0), C1a = smem_u32(C1);

    int a_row = (lane & 15);
    int a_kof = (lane >> 4) << 3;
    int b_row = ((lane & 16) >> 1) + (lane & 7);
    int b_kof = (lane & 8);

    const float* hin = (layer == 0) ? x : g_h[(layer - 1) & 1];

    // --- load h tile -> A0/A1 (bf16 split) ---
    #pragma unroll
    for (int i = 0; i < 8; i++) {
        int f4 = tid + i * 512;               // 0..4095
        int r = f4 >> 5, c4 = (f4 & 31) * 4;
        float4 v = *(const float4*)(hin + (size_t)(row0 + r) * HD + c4);
        __nv_bfloat16 h0 = __float2bfloat16(v.x), h1 = __float2bfloat16(v.y);
        __nv_bfloat16 h2 = __float2bfloat16(v.z), h3 = __float2bfloat16(v.w);
        __nv_bfloat16 l0 = __float2bfloat16(v.x - __bfloat162float(h0));
        __nv_bfloat16 l1 = __float2bfloat16(v.y - __bfloat162float(h1));
        __nv_bfloat16 l2 = __float2bfloat16(v.z - __bfloat162float(h2));
        __nv_bfloat16 l3 = __float2bfloat16(v.w - __bfloat162float(h3));
        int base = r * ASTR + c4;
        *(__nv_bfloat162*)(A0 + base)     = __nv_bfloat162(h0, h1);
        *(__nv_bfloat162*)(A0 + base + 2) = __nv_bfloat162(h2, h3);
        *(__nv_bfloat162*)(A1 + base)     = __nv_bfloat162(l0, l1);
        *(__nv_bfloat162*)(A1 + base + 2) = __nv_bfloat162(l2, l3);
    }

    // --- load adjacency (already exact bf16) -> C0/C1 ---
    {
        const uint4* src0 = (const uint4*)(g_adj_b[0] + (size_t)g * NPG * NPG);
        const uint4* src1 = (const uint4*)(g_adj_b[1] + (size_t)g * NPG * NPG);
        #pragma unroll
        for (int i = 0; i < 4; i++) {
            int f = tid + i * 512;            // 0..2047 uint4 per matrix
            int r = f >> 4, c = f & 15;       // 16 uint4 per 128-elem row
            *(uint4*)(C0 + r * ASTR + c * 8) = src0[f];
            *(uint4*)(C1 + r * ASTR + c * 8) = src1[f];
        }
    }

    float agg[2][4][4];
    #pragma unroll
    for (int mt = 0; mt < 2; mt++)
        #pragma unroll
        for (int nt = 0; nt < 4; nt++)
            #pragma unroll
            for (int q = 0; q < 4; q++) agg[mt][nt][q] = 0.0f;

    float acc[2][4][4];

    const float* Wp[3]  = {Wn, Wo, Wr};
    const float* BiP[3] = {bn, bo, (const float*)0};

    #pragma unroll 1
    for (int m = 0; m < 3; m++) {
        // load weight m -> B0/B1 (split). (First iter: also fences A/C loads.)
        __syncthreads();
        const float* Wm = Wp[m];
        #pragma unroll
        for (int i = 0; i < 8; i++) {
            int f4 = tid + i * 512;
            int r = f4 >> 5, c4 = (f4 & 31) * 4;
            float4 v = *(const float4*)(Wm + (size_t)r * HD + c4);
            __nv_bfloat16 h0 = __float2bfloat16(v.x), h1 = __float2bfloat16(v.y);
            __nv_bfloat16 h2 = __float2bfloat16(v.z), h3 = __float2bfloat16(v.w);
            __nv_bfloat16 l0 = __float2bfloat16(v.x - __bfloat162float(h0));
            __nv_bfloat16 l1 = __float2bfloat16(v.y - __bfloat162float(h1));
            __nv_bfloat16 l2 = __float2bfloat16(v.z - __bfloat162float(h2));
            __nv_bfloat16 l3 = __float2bfloat16(v.w - __bfloat162float(h3));
            int base = r * ASTR + c4;
            *(__nv_bfloat162*)(B0 + base)     = __nv_bfloat162(h0, h1);
            *(__nv_bfloat162*)(B0 + base + 2) = __nv_bfloat162(h2, h3);
            *(__nv_bfloat162*)(B1 + base)     = __nv_bfloat162(l0, l1);
            *(__nv_bfloat162*)(B1 + base + 2) = __nv_bfloat162(l2, l3);
        }
        __syncthreads();

        // x_m = h @ Wm^T : Ah*Bh + Ah*Bl + Al*Bh
        #pragma unroll
        for (int mt = 0; mt < 2; mt++)
            #pragma unroll
            for (int nt = 0; nt < 4; nt++)
                #pragma unroll
                for (int q = 0; q < 4; q++) acc[mt][nt][q] = 0.0f;
        gemm_pass(acc, A0a, B0a, m_blk, n_blk, a_row, a_kof, b_row, b_kof);
        gemm_pass(acc, A0a, B1a, m_blk, n_blk, a_row, a_kof, b_row, b_kof);
        gemm_pass(acc, A1a, B0a, m_blk, n_blk, a_row, a_kof, b_row, b_kof);

        if (m < 2) {
            // add bias, split, store TRANSPOSED (x^T[h][s]) into B0/B1
            const float* bb = BiP[m];
            __syncthreads();   // all warps done reading W from B
            #pragma unroll
            for (int mt = 0; mt < 2; mt++) {
                int sI = m_blk + mt * 16 + grp;
                #pragma unroll
                for (int nt = 0; nt < 4; nt++) {
                    int hI = n_blk + nt * 8 + tig * 2;
                    float b0 = bb[hI], b1 = bb[hI + 1];
                    float v0 = acc[mt][nt][0] + b0, v1 = acc[mt][nt][1] + b1;
                    float v2 = acc[mt][nt][2] + b0, v3 = acc[mt][nt][3] + b1;
                    __nv_bfloat16 h0 = __float2bfloat16(v0);
                    __nv_bfloat16 h1 = __float2bfloat16(v1);
                    __nv_bfloat16 h2 = __float2bfloat16(v2);
                    __nv_bfloat16 h3 = __float2bfloat16(v3);
                    B0[hI * ASTR + sI]           = h0;
                    B0[(hI + 1) * ASTR + sI]     = h1;
                    B0[hI * ASTR + sI + 8]       = h2;
                    B0[(hI + 1) * ASTR + sI + 8] = h3;
                    B1[hI * ASTR + sI]           = __float2bfloat16(v0 - __bfloat162float(h0));
                    B1[(hI + 1) * ASTR + sI]     = __float2bfloat16(v1 - __bfloat162float(h1));
                    B1[hI * ASTR + sI + 8]       = __float2bfloat16(v2 - __bfloat162float(h2));
                    B1[(hI + 1) * ASTR + sI + 8] = __float2bfloat16(v3 - __bfloat162float(h3));
                }
            }
            __syncthreads();
            // agg += Adj_m * x_m   (adjacency exact; x split hi+lo)
            uint32_t Ca = (m == 0) ? C0a : C1a;
            gemm_pass(agg, Ca, B0a, m_blk, n_blk, a_row, a_kof, b_row, b_kof);
            gemm_pass(agg, Ca, B1a, m_blk, n_blk, a_row, a_kof, b_row, b_kof);
        }
    }

    // --- combine: val = agg * invc[row] + x_root; write to fp32 scratch ---
    __syncthreads();   // all warps done reading A (h) and B/C
    #pragma unroll
    for (int mt = 0; mt < 2; mt++) {
        int rg = m_blk + mt * 16 + grp;
        float ic0 = g_invc[row0 + rg];
        float ic1 = g_invc[row0 + rg + 8];
        #pragma unroll
        for (int nt = 0; nt < 4; nt++) {
            int cg = n_blk + nt * 8 + tig * 2;
            S[rg * 132 + cg]           = fmaf(agg[mt][nt][0], ic0, acc[mt][nt][0]);
            S[rg * 132 + cg + 1]       = fmaf(agg[mt][nt][1], ic0, acc[mt][nt][1]);
            S[(rg + 8) * 132 + cg]     = fmaf(agg[mt][nt][2], ic1, acc[mt][nt][2]);
            S[(rg + 8) * 132 + cg + 1] = fmaf(agg[mt][nt][3], ic1, acc[mt][nt][3]);
        }
    }
    __syncthreads();

    // --- LayerNorm + ReLU: 4 threads per row ---
    {
        int row = tid >> 2, q = tid & 3;
        const float* Sr = S + row * 132 + q * 32;
        float v[32];
        float sum = 0.f, sq = 0.f;
        #pragma unroll
        for (int j = 0; j < 32; j++) {
            v[j] = Sr[j];
            sum += v[j];
            sq  += v[j] * v[j];
        }
        sum += __shfl_xor_sync(0xffffffffu, sum, 1);
        sum += __shfl_xor_sync(0xffffffffu, sum, 2);
        sq  += __shfl_xor_sync(0xffffffffu, sq, 1);
        sq  += __shfl_xor_sync(0xffffffffu, sq, 2);
        float mu   = sum * (1.0f / 128.0f);
        float var  = sq * (1.0f / 128.0f) - mu * mu;
        float rstd = rsqrtf(var + 1e-5f);

        float* hout = g_h[layer & 1] + (size_t)(row0 + row) * HD + q * 32;
        const float* gma = lng + q * 32;
        const float* bta = lnb + q * 32;
        #pragma unroll
        for (int j = 0; j < 32; j += 4) {
            float o0 = fmaxf((v[j]     - mu) * rstd * gma[j]     + bta[j],     0.f);
            float o1 = fmaxf((v[j + 1] - mu) * rstd * gma[j + 1] + bta[j + 1], 0.f);
            float o2 = fmaxf((v[j + 2] - mu) * rstd * gma[j + 2] + bta[j + 2], 0.f);
            float o3 = fmaxf((v[j + 3] - mu) * rstd * gma[j + 3] + bta[j + 3], 0.f);
            *(float4*)(hout + j) = make_float4(o0, o1, o2, o3);
        }
    }
}

// ---------------------------------------------------------------------------
// Per-graph pooling head
// ---------------------------------------------------------------------------
__global__ void pool_kernel(const float* __restrict__ s,
                            const float* __restrict__ flng,
                            const float* __restrict__ flnb,
                            const float* __restrict__ linw,
                            const float* __restrict__ bias,
                            float* __restrict__ dout) {
    __shared__ float sd[NPG * NC];
    __shared__ float pl[NC * HD];
    __shared__ float colsum[NC];
    __shared__ float xcs[NC];

    int g = blockIdx.x;
    int tid = threadIdx.x;
    const float* hf = g_h[(NL - 1) & 1];
    const float* xg = hf + (size_t)g * NPG * HD;

    for (int i = tid; i < NPG * NC / 4; i += 256)
        *(float4*)(sd + i * 4) = *(const float4*)(s + (size_t)g * NPG * NC + i * 4);
    __syncthreads();

    if (tid < NC) {
        float cs = 0.f;
        for (int n = 0; n < NPG; n++) cs += sd[n * NC + tid];
        colsum[tid] = cs;
    }

    int hcol = tid & 127;
    int cg = tid >> 7;
    float acc[8] = {0, 0, 0, 0, 0, 0, 0, 0};
    #pragma unroll 4
    for (int n = 0; n < NPG; n++) {
        float xv = xg[(size_t)n * HD + hcol];
        #pragma unroll
        for (int c = 0; c < 8; c++)
            acc[c] = fmaf(sd[n * NC + cg * 8 + c], xv, acc[c]);
    }
    #pragma unroll
    for (int c = 0; c < 8; c++) pl[(cg * 8 + c) * HD + hcol] = acc[c];
    __syncthreads();

    int wid = tid >> 5, lane = tid & 31;
    for (int rr = wid * 2; rr < wid * 2 + 2; rr++) {
        float4 v = *(float4*)(pl + rr * HD + lane * 4);
        float sum = v.x + v.y + v.z + v.w;
        float sq  = v.x * v.x + v.y * v.y + v.z * v.z + v.w * v.w;
        #pragma unroll
        for (int o = 16; o; o >>= 1) {
            sum += __shfl_xor_sync(0xffffffffu, sum, o);
            sq  += __shfl_xor_sync(0xffffffffu, sq,  o);
        }
        float mu   = sum * (1.0f / 128.0f);
        float var  = sq * (1.0f / 128.0f) - mu * mu;
        float rstd = rsqrtf(var + 1e-5f);
        int f = lane * 4;
        float dot = ((v.x - mu) * rstd * flng[f + 0] + flnb[f + 0]) * linw[f + 0]
                  + ((v.y - mu) * rstd * flng[f + 1] + flnb[f + 1]) * linw[f + 1]
                  + ((v.z - mu) * rstd * flng[f + 2] + flnb[f + 2]) * linw[f + 2]
                  + ((v.w - mu) * rstd * flng[f + 3] + flnb[f + 3]) * linw[f + 3];
        #pragma unroll
        for (int o = 16; o; o >>= 1) dot += __shfl_xor_sync(0xffffffffu, dot, o);
        if (lane == 0) xcs[rr] = dot;
    }
    __syncthreads();

    if (tid == 0) {
        float ov = 0.f, l1 = 0.f, dn = 0.f;
        #pragma unroll
        for (int c = 0; c < NC; c++) {
            float mflag = (colsum[c] > 0.f) ? 1.f : 0.f;
            float v = xcs[c] * mflag;
            dout[257 + g * NC + c] = v;          // xc
            ov += v;
            l1 += fabsf(v);
            dn += mflag;
        }
        dout[g] = ov + bias[0];                  // out
        g_l1[g] = l1 / (dn + 1e-7f);
    }
}

// losses = 0.01*(sum|Wo|+sum|bo|) + 0.01*mean_g(l1[g])
__global__ void loss_kernel(const float* __restrict__ Wo,
                            const float* __restrict__ bo,
                            float* __restrict__ dout) {
    __shared__ float red[256];
    __shared__ float sreg;
    int tid = threadIdx.x;
    float rs = 0.f;
    for (int i = tid; i < NL * HD * HD; i += 256) rs += fabsf(Wo[i]);
    for (int i = tid; i < NL * HD; i += 256)      rs += fabsf(bo[i]);
    red[tid] = rs;
    __syncthreads();
    for (int o = 128; o; o >>= 1) {
        if (tid < o) red[tid] += red[tid + o];
        __syncthreads();
    }
    if (tid == 0) sreg = red[0];
    __syncthreads();
    float ls = (tid < NG) ? g_l1[tid] : 0.f;
    red[tid] = ls;
    __syncthreads();
    for (int o = 128; o; o >>= 1) {
        if (tid < o) red[tid] += red[tid + o];
        __syncthreads();
    }
    if (tid == 0)
        dout[256] = 0.01f * sreg + 0.01f * (red[0] / (float)NG);
}

// ---------------------------------------------------------------------------
extern "C" void kernel_launch(void* const* d_in, const int* in_sizes, int n_in,
                              void* d_out, int out_size) {
    const float* x    = (const float*)d_in[0];
    const void*  ei   = d_in[1];
    const void*  mk   = d_in[2];
    const float* s    = (const float*)d_in[3];
    // d_in[4] = batch (unused: graphs are equal-size, sorted)
    const float* Wn   = (const float*)d_in[5];
    const float* bn   = (const float*)d_in[6];
    const float* Wo   = (const float*)d_in[7];
    const float* bo   = (const float*)d_in[8];
    const float* Wr   = (const float*)d_in[9];
    const float* lng  = (const float*)d_in[10];
    const float* lnb  = (const float*)d_in[11];
    const float* flng = (const float*)d_in[12];
    const float* flnb = (const float*)d_in[13];
    const float* linw = (const float*)d_in[14];
    const float* bias = (const float*)d_in[15];
    float* out = (float*)d_out;

    cudaFuncSetAttribute(layer_kernel,
                         cudaFuncAttributeMaxDynamicSharedMemorySize, LAYER_SMEM);

    detect_kernel<<<1, 1>>>((const unsigned int*)ei, (const unsigned int*)mk);

    zero_all_kernel<<<2048, 256>>>();
    adj_build_kernel<<<N_EDGES / 256, 256>>>(ei, mk);
    adj_finish_kernel<<<2048, 256>>>();

    for (int l = 0; l < NL; l++) {
        layer_kernel<<<NG, 512, LAYER_SMEM>>>(
            x, Wn + l * HD * HD, bn + l * HD,
            Wo + l * HD * HD, bo + l * HD, Wr + l * HD * HD,
            lng + l * HD, lnb + l * HD, l);
    }

    pool_kernel<<<NG, 256>>>(s, flng, flnb, linw, bias, out);
    loss_kernel<<<1, 256>>>(Wo, bo, out);
}

// round 9
// speedup vs baseline: 1.8863x; 1.0816x over previous
#include <cuda_runtime.h>
#include <cuda_bf16.h>
#include <stdint.h>

// ---------------------------------------------------------------------------
// SEALNetwork: 3-layer GNN (N=32768, H=128, E=524288) + dense pooling head.
// Aggregate-first formulation:
//   agg = (Ain.h).Wn^T + (Aout.h).Wo^T + cnt_in (x) bn + cnt_out (x) bo
// Per CTA (one graph, 128 nodes): h split bf16 -> root GEMM -> adjacency
// GEMMs (h as row-major B via ldmatrix.trans; exact integer adjacency) ->
// Hin/Hout split row-major in smem -> weight GEMMs -> epilogue LN+ReLU.
// Adjacency stored as packed u8; all smem XOR-swizzled stride-128.
// ---------------------------------------------------------------------------

#define N_NODES 32768
#define N_EDGES 524288
#define NG      256
#define NPG     128
#define HD      128
#define NL      3
#define NC      16
#define BUFB    32768            // bytes per swizzled bf16 buffer (128x128)
#define ADJ_EL  (NG * NPG * NPG) // 4194304 per adjacency matrix

// scratch (static device globals: allocation-free per harness rules)
__device__ float         g_h[2][N_NODES * HD];
__device__ int           g_cin[N_NODES];
__device__ int           g_cout[N_NODES];
__device__ float         g_l1[NG];
__device__ unsigned char g_adj[2][ADJ_EL];   // [0]=masked(in), [1]=out
__device__ int           g_ei64;     // 1 if edge_index is int64
__device__ int           g_mk_kind;  // 0 = uint8/bool, 1 = int32, 2 = float32

// ---------------------------------------------------------------------------
// helpers
// ---------------------------------------------------------------------------
__device__ __forceinline__ uint32_t smem_u32(const void* p) {
    uint32_t a;
    asm("{ .reg .u64 t; cvta.to.shared.u64 t, %1; cvt.u32.u64 %0, t; }"
        : "=r"(a) : "l"(p));
    return a;
}

__device__ __forceinline__ void ldm_x4(uint32_t& r0, uint32_t& r1,
                                       uint32_t& r2, uint32_t& r3,
                                       uint32_t addr) {
    asm volatile("ldmatrix.sync.aligned.m8n8.x4.shared.b16 {%0,%1,%2,%3}, [%4];"
                 : "=r"(r0), "=r"(r1), "=r"(r2), "=r"(r3) : "r"(addr));
}

__device__ __forceinline__ void ldm_x4t(uint32_t& r0, uint32_t& r1,
                                        uint32_t& r2, uint32_t& r3,
                                        uint32_t addr) {
    asm volatile(
        "ldmatrix.sync.aligned.m8n8.x4.trans.shared.b16 {%0,%1,%2,%3}, [%4];"
        : "=r"(r0), "=r"(r1), "=r"(r2), "=r"(r3) : "r"(addr));
}

__device__ __forceinline__ void mma_bf16(float* c, const uint32_t* a,
                                         uint32_t b0, uint32_t b1) {
    asm volatile(
        "mma.sync.aligned.m16n8k16.row.col.f32.bf16.bf16.f32 "
        "{%0,%1,%2,%3}, {%4,%5,%6,%7}, {%8,%9}, {%0,%1,%2,%3};"
        : "+f"(c[0]), "+f"(c[1]), "+f"(c[2]), "+f"(c[3])
        : "r"(a[0]), "r"(a[1]), "r"(a[2]), "r"(a[3]), "r"(b0), "r"(b1));
}

__device__ __forceinline__ uint32_t bf2pack(float a, float b) {
    unsigned short lo = __bfloat16_as_ushort(__float2bfloat16(a));
    unsigned short hi = __bfloat16_as_ushort(__float2bfloat16(b));
    return (uint32_t)lo | ((uint32_t)hi << 16);
}

// swizzled byte offset for bf16 element (r, c) in a 128x128 buffer
__device__ __forceinline__ uint32_t swz(int r, int c) {
    return (uint32_t)(r * 256 + ((((c >> 3) ^ (r & 7)) << 4) | ((c & 7) * 2)));
}

// acc += A(Abase, rows m_blk..+31) * B^T(Bbase rows = n dim, k-contig)
__device__ __forceinline__ void pass_nn(float acc[2][4][4], uint32_t Abase,
                                        uint32_t Bbase, int m_blk, int n_blk,
                                        int lane) {
    int ar = lane & 15, ak = lane >> 4;
    int br = (lane & 7) + ((lane & 16) >> 1), bk = (lane & 8) >> 3;
    #pragma unroll
    for (int ks = 0; ks < 8; ks++) {
        uint32_t a[2][4];
        #pragma unroll
        for (int mt = 0; mt < 2; mt++) {
            int row = m_blk + mt * 16 + ar;
            int kg = ks * 2 + ak;
            ldm_x4(a[mt][0], a[mt][1], a[mt][2], a[mt][3],
                   Abase + (uint32_t)(row * 256 + ((kg ^ (row & 7)) << 4)));
        }
        uint32_t b[4][2];
        #pragma unroll
        for (int np = 0; np < 2; np++) {
            int row = n_blk + np * 16 + br;
            int kg = ks * 2 + bk;
            uint32_t r0, r1, r2, r3;
            ldm_x4(r0, r1, r2, r3,
                   Bbase + (uint32_t)(row * 256 + ((kg ^ (row & 7)) << 4)));
            b[np * 2][0] = r0;     b[np * 2][1] = r1;
            b[np * 2 + 1][0] = r2; b[np * 2 + 1][1] = r3;
        }
        #pragma unroll
        for (int mt = 0; mt < 2; mt++)
            #pragma unroll
            for (int nt = 0; nt < 4; nt++)
                mma_bf16(acc[mt][nt], a[mt], b[nt][0], b[nt][1]);
    }
}

// acc += A(Abase) * B(Bbase) where B is ROW-MAJOR [k][n] (ldmatrix.trans)
__device__ __forceinline__ void pass_nt(float acc[2][4][4], uint32_t Abase,
                                        uint32_t Bbase, int m_blk, int n_blk,
                                        int lane) {
    int ar = lane & 15, ak = lane >> 4;
    int tr = lane & 15, tn = lane >> 4;
    #pragma unroll
    for (int ks = 0; ks < 8; ks++) {
        uint32_t a[2][4];
        #pragma unroll
        for (int mt = 0; mt < 2; mt++) {
            int row = m_blk + mt * 16 + ar;
            int kg = ks * 2 + ak;
            ldm_x4(a[mt][0], a[mt][1], a[mt][2], a[mt][3],
                   Abase + (uint32_t)(row * 256 + ((kg ^ (row & 7)) << 4)));
        }
        uint32_t b[4][2];
        #pragma unroll
        for (int np = 0; np < 2; np++) {
            int row = ks * 16 + tr;
            int ng = ((n_blk + np * 16) >> 3) + tn;
            uint32_t r0, r1, r2, r3;
            ldm_x4t(r0, r1, r2, r3,
                    Bbase + (uint32_t)(row * 256 + ((ng ^ (row & 7)) << 4)));
            b[np * 2][0] = r0;     b[np * 2][1] = r1;
            b[np * 2 + 1][0] = r2; b[np * 2 + 1][1] = r3;
        }
        #pragma unroll
        for (int mt = 0; mt < 2; mt++)
            #pragma unroll
            for (int nt = 0; nt < 4; nt++)
                mma_bf16(acc[mt][nt], a[mt], b[nt][0], b[nt][1]);
    }
}

// ---------------------------------------------------------------------------
// dtype detection (one warp)
// ---------------------------------------------------------------------------
__global__ void detect_kernel(const unsigned int* __restrict__ ei_w,
                              const unsigned int* __restrict__ mk_w) {
    int lane = threadIdx.x;
    int odd = 0;
    for (int i = lane; i < 64; i += 32)
        if (ei_w[2 * i + 1] != 0u) odd = 1;
    unsigned m1 = __ballot_sync(0xffffffffu, odd);
    int f1 = 0, mb = 0;
    for (int i = lane; i < 256; i += 32) {
        unsigned w = mk_w[i];
        if (w == 0x3F800000u) f1 = 1;
        else if ((w >> 8) != 0u) mb = 1;
    }
    unsigned mf = __ballot_sync(0xffffffffu, f1);
    unsigned mm = __ballot_sync(0xffffffffu, mb);
    if (lane == 0) {
        g_ei64 = (m1 == 0u) ? 1 : 0;
        g_mk_kind = mf ? 2 : (mm ? 0 : 1);
    }
}

__device__ __forceinline__ int load_idx(const void* ei, int pos) {
    if (g_ei64) return (int)((const long long*)ei)[pos];
    return ((const int*)ei)[pos];
}
__device__ __forceinline__ bool load_mask(const void* mk, int e) {
    int kind = g_mk_kind;
    if (kind == 0) return ((const unsigned char*)mk)[e] != 0;
    if (kind == 1) return ((const int*)mk)[e] != 0;
    return ((const float*)mk)[e] != 0.0f;
}

// ---------------------------------------------------------------------------
// adjacency pipeline (u8 packed)
// ---------------------------------------------------------------------------
__global__ void zero_all_kernel() {
    int stride = gridDim.x * blockDim.x;
    int i0 = blockIdx.x * blockDim.x + threadIdx.x;
    uint4 z = make_uint4(0, 0, 0, 0);
    for (int i = i0; i < ADJ_EL / 16; i += stride) {
        ((uint4*)g_adj[0])[i] = z;
        ((uint4*)g_adj[1])[i] = z;
    }
    for (int i = i0; i < N_NODES; i += stride) {
        g_cin[i] = 0;
        g_cout[i] = 0;
    }
}

__global__ void adj_build_kernel(const void* __restrict__ ei,
                                 const void* __restrict__ mk) {
    int e = blockIdx.x * blockDim.x + threadIdx.x;
    if (e >= N_EDGES) return;
    int t = load_idx(ei, N_EDGES + e);
    int s = load_idx(ei, e);
    if ((unsigned)t >= (unsigned)N_NODES) return;
    if ((unsigned)s >= (unsigned)N_NODES) return;
    if ((t >> 7) != (s >> 7)) return;
    int sel = load_mask(mk, e) ? 0 : 1;
    int idx = ((t >> 7) * NPG + (t & 127)) * NPG + (s & 127);
    atomicAdd(&((unsigned int*)g_adj[sel])[idx >> 2],
              1u << ((idx & 3) * 8));
    atomicAdd(sel ? &g_cout[t] : &g_cin[t], 1);
}

// ---------------------------------------------------------------------------
// Fused layer kernel. One CTA per graph, 512 threads (16 warps, 32x32 tiles).
// dyn smem buffers (swizzled 128x128 bf16, 32KB each):
//  [0]=C0 adjIn->HinHi [1]=C1 adjOut->HoutHi [2]=D HinLo
//  [3]=A0 hHi [4]=A1 hLo->HoutLo [5]=W0 Whi [6]=W1 Wlo
// fp32 LN scratch S[128][132] overlays dyn start after GEMMs.
// ---------------------------------------------------------------------------
#define LAYER_SMEM (7 * BUFB)

__global__ void __launch_bounds__(512)
layer_kernel(const float* __restrict__ x,
             const float* __restrict__ Wn, const float* __restrict__ bn,
             const float* __restrict__ Wo, const float* __restrict__ bo,
             const float* __restrict__ Wr,
             const float* __restrict__ lng, const float* __restrict__ lnb,
             int layer) {
    extern __shared__ __align__(16) char dyn[];
    __shared__ float sbn[HD], sbo[HD];

    int tid = threadIdx.x;
    int w = tid >> 5, lane = tid & 31;
    int m_blk = (w >> 2) * 32, n_blk = (w & 3) * 32;
    int grp = lane >> 2, tig = lane & 3;
    int g = blockIdx.x, row0 = g * 128;

    uint32_t base = smem_u32(dyn);
    uint32_t C0 = base, C1 = base + BUFB, Dd = base + 2 * BUFB;
    uint32_t A0 = base + 3 * BUFB, A1 = base + 4 * BUFB;
    uint32_t W0 = base + 5 * BUFB, W1 = base + 6 * BUFB;
    float* S = (float*)dyn;

    const float* hin_g = (layer == 0) ? x : g_h[(layer - 1) & 1];

    if (tid < HD) { sbn[tid] = bn[tid]; sbo[tid] = bo[tid]; }
    else if (tid < 2 * HD) { }

    // --- load h (split) ---
    #pragma unroll
    for (int i = 0; i < 4; i++) {
        int gid = tid + i * 512;             // 0..2047 granules
        int r = gid >> 4, gq = gid & 15;
        const float* src = hin_g + (size_t)(row0 + r) * HD + gq * 8;
        float v[8];
        *(float4*)(v)     = *(const float4*)(src);
        *(float4*)(v + 4) = *(const float4*)(src + 4);
        uint32_t hi[4], lo[4];
        #pragma unroll
        for (int j = 0; j < 4; j++) {
            float a = v[2 * j], b = v[2 * j + 1];
            __nv_bfloat16 ha = __float2bfloat16(a), hb = __float2bfloat16(b);
            hi[j] = (uint32_t)__bfloat16_as_ushort(ha)
                  | ((uint32_t)__bfloat16_as_ushort(hb) << 16);
            lo[j] = bf2pack(a - __bfloat162float(ha), b - __bfloat162float(hb));
        }
        uint32_t off = (uint32_t)(r * 256 + ((gq ^ (r & 7)) << 4));
        *(uint4*)((char*)dyn + (A0 - base) + off) = make_uint4(hi[0], hi[1], hi[2], hi[3]);
        *(uint4*)((char*)dyn + (A1 - base) + off) = make_uint4(lo[0], lo[1], lo[2], lo[3]);
    }

    // --- load adjacency u8 -> bf16 (exact) into C0/C1 ---
    #pragma unroll
    for (int sel = 0; sel < 2; sel++) {
        const unsigned char* src = g_adj[sel] + (size_t)g * NPG * NPG;
        uint32_t dst = (sel == 0) ? C0 : C1;
        #pragma unroll
        for (int i = 0; i < 4; i++) {
            int gid = tid + i * 512;
            int r = gid >> 4, gq = gid & 15;
            uint2 raw = *(const uint2*)(src + r * NPG + gq * 8);
            uint32_t p[4];
            p[0] = bf2pack((float)(raw.x & 255), (float)((raw.x >> 8) & 255));
            p[1] = bf2pack((float)((raw.x >> 16) & 255), (float)(raw.x >> 24));
            p[2] = bf2pack((float)(raw.y & 255), (float)((raw.y >> 8) & 255));
            p[3] = bf2pack((float)((raw.y >> 16) & 255), (float)(raw.y >> 24));
            uint32_t off = (uint32_t)(r * 256 + ((gq ^ (r & 7)) << 4));
            *(uint4*)((char*)dyn + (dst - base) + off) = make_uint4(p[0], p[1], p[2], p[3]);
        }
    }

    // --- load Wr (split) into W0/W1 ---
    #pragma unroll
    for (int i = 0; i < 4; i++) {
        int gid = tid + i * 512;
        int r = gid >> 4, gq = gid & 15;
        const float* src = Wr + (size_t)r * HD + gq * 8;
        float v[8];
        *(float4*)(v)     = *(const float4*)(src);
        *(float4*)(v + 4) = *(const float4*)(src + 4);
        uint32_t hi[4], lo[4];
        #pragma unroll
        for (int j = 0; j < 4; j++) {
            float a = v[2 * j], b = v[2 * j + 1];
            __nv_bfloat16 ha = __float2bfloat16(a), hb = __float2bfloat16(b);
            hi[j] = (uint32_t)__bfloat16_as_ushort(ha)
                  | ((uint32_t)__bfloat16_as_ushort(hb) << 16);
            lo[j] = bf2pack(a - __bfloat162float(ha), b - __bfloat162float(hb));
        }
        uint32_t off = (uint32_t)(r * 256 + ((gq ^ (r & 7)) << 4));
        *(uint4*)((char*)dyn + (W0 - base) + off) = make_uint4(hi[0], hi[1], hi[2], hi[3]);
        *(uint4*)((char*)dyn + (W1 - base) + off) = make_uint4(lo[0], lo[1], lo[2], lo[3]);
    }
    __syncthreads();

    // --- root = h @ Wr^T (3-pass split) ---
    float root[2][4][4];
    #pragma unroll
    for (int mt = 0; mt < 2; mt++)
        #pragma unroll
        for (int nt = 0; nt < 4; nt++)
            #pragma unroll
            for (int q = 0; q < 4; q++) root[mt][nt][q] = 0.f;
    pass_nn(root, A0, W0, m_blk, n_blk, lane);
    pass_nn(root, A0, W1, m_blk, n_blk, lane);
    pass_nn(root, A1, W0, m_blk, n_blk, lane);

    // --- Hin = Ain @ h (2 passes, h as row-major B via trans; exact) ---
    float hacc[2][4][4];
    #pragma unroll
    for (int mt = 0; mt < 2; mt++)
        #pragma unroll
        for (int nt = 0; nt < 4; nt++)
            #pragma unroll
            for (int q = 0; q < 4; q++) hacc[mt][nt][q] = 0.f;
    pass_nt(hacc, C0, A0, m_blk, n_blk, lane);
    pass_nt(hacc, C0, A1, m_blk, n_blk, lane);
    __syncthreads();                       // before overwriting C0
    // store Hin split: hi -> C0, lo -> D
    #pragma unroll
    for (int mt = 0; mt < 2; mt++) {
        #pragma unroll
        for (int nt = 0; nt < 4; nt++) {
            int rg = m_blk + mt * 16 + grp;
            int cg = n_blk + nt * 8 + tig * 2;
            #pragma unroll
            for (int half = 0; half < 2; half++) {
                int row = rg + half * 8;
                float a = hacc[mt][nt][half * 2], b = hacc[mt][nt][half * 2 + 1];
                __nv_bfloat16 ha = __float2bfloat16(a), hb = __float2bfloat16(b);
                uint32_t off = swz(row, cg);
                *(uint32_t*)((char*)dyn + (C0 - base) + off) =
                    (uint32_t)__bfloat16_as_ushort(ha)
                    | ((uint32_t)__bfloat16_as_ushort(hb) << 16);
                *(uint32_t*)((char*)dyn + (Dd - base) + off) =
                    bf2pack(a - __bfloat162float(ha), b - __bfloat162float(hb));
            }
        }
    }

    // --- Hout = Aout @ h (2 passes) ---
    #pragma unroll
    for (int mt = 0; mt < 2; mt++)
        #pragma unroll
        for (int nt = 0; nt < 4; nt++)
            #pragma unroll
            for (int q = 0; q < 4; q++) hacc[mt][nt][q] = 0.f;
    pass_nt(hacc, C1, A0, m_blk, n_blk, lane);
    pass_nt(hacc, C1, A1, m_blk, n_blk, lane);
    __syncthreads();                       // before overwriting C1/A1
    // store Hout split: hi -> C1, lo -> A1 (h no longer needed)
    #pragma unroll
    for (int mt = 0; mt < 2; mt++) {
        #pragma unroll
        for (int nt = 0; nt < 4; nt++) {
            int rg = m_blk + mt * 16 + grp;
            int cg = n_blk + nt * 8 + tig * 2;
            #pragma unroll
            for (int half = 0; half < 2; half++) {
                int row = rg + half * 8;
                float a = hacc[mt][nt][half * 2], b = hacc[mt][nt][half * 2 + 1];
                __nv_bfloat16 ha = __float2bfloat16(a), hb = __float2bfloat16(b);
                uint32_t off = swz(row, cg);
                *(uint32_t*)((char*)dyn + (C1 - base) + off) =
                    (uint32_t)__bfloat16_as_ushort(ha)
                    | ((uint32_t)__bfloat16_as_ushort(hb) << 16);
                *(uint32_t*)((char*)dyn + (A1 - base) + off) =
                    bf2pack(a - __bfloat162float(ha), b - __bfloat162float(hb));
            }
        }
    }
    __syncthreads();

    // --- agg = Hin @ Wn^T + Hout @ Wo^T (3+3 passes into one acc) ---
    float agg[2][4][4];
    #pragma unroll
    for (int mt = 0; mt < 2; mt++)
        #pragma unroll
        for (int nt = 0; nt < 4; nt++)
            #pragma unroll
            for (int q = 0; q < 4; q++) agg[mt][nt][q] = 0.f;

    const float* Wptr[2] = {Wn, Wo};
    #pragma unroll 1
    for (int m = 0; m < 2; m++) {
        // load weight m (split) into W0/W1
        const float* Wm = Wptr[m];
        #pragma unroll
        for (int i = 0; i < 4; i++) {
            int gid = tid + i * 512;
            int r = gid >> 4, gq = gid & 15;
            const float* src = Wm + (size_t)r * HD + gq * 8;
            float v[8];
            *(float4*)(v)     = *(const float4*)(src);
            *(float4*)(v + 4) = *(const float4*)(src + 4);
            uint32_t hi[4], lo[4];
            #pragma unroll
            for (int j = 0; j < 4; j++) {
                float a = v[2 * j], b = v[2 * j + 1];
                __nv_bfloat16 ha = __float2bfloat16(a), hb = __float2bfloat16(b);
                hi[j] = (uint32_t)__bfloat16_as_ushort(ha)
                      | ((uint32_t)__bfloat16_as_ushort(hb) << 16);
                lo[j] = bf2pack(a - __bfloat162float(ha),
                                b - __bfloat162float(hb));
            }
            uint32_t off = (uint32_t)(r * 256 + ((gq ^ (r & 7)) << 4));
            *(uint4*)((char*)dyn + (W0 - base) + off) = make_uint4(hi[0], hi[1], hi[2], hi[3]);
            *(uint4*)((char*)dyn + (W1 - base) + off) = make_uint4(lo[0], lo[1], lo[2], lo[3]);
        }
        __syncthreads();

        uint32_t Hhi = (m == 0) ? C0 : C1;
        uint32_t Hlo = (m == 0) ? Dd : A1;
        pass_nn(agg, Hhi, W0, m_blk, n_blk, lane);
        pass_nn(agg, Hhi, W1, m_blk, n_blk, lane);
        pass_nn(agg, Hlo, W0, m_blk, n_blk, lane);
        __syncthreads();                   // before reloading W (or S overlay)
    }

    // --- epilogue: val = (agg + cin*bn + cout*bo)*invc + root -> S ---
    #pragma unroll
    for (int mt = 0; mt < 2; mt++) {
        int rg = m_blk + mt * 16 + grp;
        #pragma unroll
        for (int half = 0; half < 2; half++) {
            int row = rg + half * 8;
            float ci = (float)g_cin[row0 + row];
            float co = (float)g_cout[row0 + row];
            float inv = 1.0f / fmaxf(ci + co, 1.0f);
            #pragma unroll
            for (int nt = 0; nt < 4; nt++) {
                int cg = n_blk + nt * 8 + tig * 2;
                float v0 = (agg[mt][nt][half * 2]     + ci * sbn[cg]
                            + co * sbo[cg]) * inv + root[mt][nt][half * 2];
                float v1 = (agg[mt][nt][half * 2 + 1] + ci * sbn[cg + 1]
                            + co * sbo[cg + 1]) * inv + root[mt][nt][half * 2 + 1];
                S[row * 132 + cg]     = v0;
                S[row * 132 + cg + 1] = v1;
            }
        }
    }
    __syncthreads();

    // --- LayerNorm + ReLU: 4 threads per row ---
    {
        int row = tid >> 2, q = tid & 3;
        const float* Sr = S + row * 132 + q * 32;
        float v[32];
        float sum = 0.f, sq = 0.f;
        #pragma unroll
        for (int j = 0; j < 32; j++) {
            v[j] = Sr[j];
            sum += v[j];
            sq  += v[j] * v[j];
        }
        sum += __shfl_xor_sync(0xffffffffu, sum, 1);
        sum += __shfl_xor_sync(0xffffffffu, sum, 2);
        sq  += __shfl_xor_sync(0xffffffffu, sq, 1);
        sq  += __shfl_xor_sync(0xffffffffu, sq, 2);
        float mu   = sum * (1.0f / 128.0f);
        float var  = sq * (1.0f / 128.0f) - mu * mu;
        float rstd = rsqrtf(var + 1e-5f);

        float* hout = g_h[layer & 1] + (size_t)(row0 + row) * HD + q * 32;
        const float* gma = lng + q * 32;
        const float* bta = lnb + q * 32;
        #pragma unroll
        for (int j = 0; j < 32; j += 4) {
            float o0 = fmaxf((v[j]     - mu) * rstd * gma[j]     + bta[j],     0.f);
            float o1 = fmaxf((v[j + 1] - mu) * rstd * gma[j + 1] + bta[j + 1], 0.f);
            float o2 = fmaxf((v[j + 2] - mu) * rstd * gma[j + 2] + bta[j + 2], 0.f);
            float o3 = fmaxf((v[j + 3] - mu) * rstd * gma[j + 3] + bta[j + 3], 0.f);
            *(float4*)(hout + j) = make_float4(o0, o1, o2, o3);
        }
    }
}

// ---------------------------------------------------------------------------
// Per-graph pooling head
// ---------------------------------------------------------------------------
__global__ void pool_kernel(const float* __restrict__ s,
                            const float* __restrict__ flng,
                            const float* __restrict__ flnb,
                            const float* __restrict__ linw,
                            const float* __restrict__ bias,
                            float* __restrict__ dout) {
    __shared__ float sd[NPG * NC];
    __shared__ float pl[NC * HD];
    __shared__ float colsum[NC];
    __shared__ float xcs[NC];

    int g = blockIdx.x;
    int tid = threadIdx.x;
    const float* hf = g_h[(NL - 1) & 1];
    const float* xg = hf + (size_t)g * NPG * HD;

    for (int i = tid; i < NPG * NC / 4; i += 256)
        *(float4*)(sd + i * 4) = *(const float4*)(s + (size_t)g * NPG * NC + i * 4);
    __syncthreads();

    if (tid < NC) {
        float cs = 0.f;
        for (int n = 0; n < NPG; n++) cs += sd[n * NC + tid];
        colsum[tid] = cs;
    }

    int hcol = tid & 127;
    int cg = tid >> 7;
    float acc[8] = {0, 0, 0, 0, 0, 0, 0, 0};
    #pragma unroll 4
    for (int n = 0; n < NPG; n++) {
        float xv = xg[(size_t)n * HD + hcol];
        #pragma unroll
        for (int c = 0; c < 8; c++)
            acc[c] = fmaf(sd[n * NC + cg * 8 + c], xv, acc[c]);
    }
    #pragma unroll
    for (int c = 0; c < 8; c++) pl[(cg * 8 + c) * HD + hcol] = acc[c];
    __syncthreads();

    int wid = tid >> 5, lane = tid & 31;
    for (int rr = wid * 2; rr < wid * 2 + 2; rr++) {
        float4 v = *(float4*)(pl + rr * HD + lane * 4);
        float sum = v.x + v.y + v.z + v.w;
        float sq  = v.x * v.x + v.y * v.y + v.z * v.z + v.w * v.w;
        #pragma unroll
        for (int o = 16; o; o >>= 1) {
            sum += __shfl_xor_sync(0xffffffffu, sum, o);
            sq  += __shfl_xor_sync(0xffffffffu, sq,  o);
        }
        float mu   = sum * (1.0f / 128.0f);
        float var  = sq * (1.0f / 128.0f) - mu * mu;
        float rstd = rsqrtf(var + 1e-5f);
        int f = lane * 4;
        float dot = ((v.x - mu) * rstd * flng[f + 0] + flnb[f + 0]) * linw[f + 0]
                  + ((v.y - mu) * rstd * flng[f + 1] + flnb[f + 1]) * linw[f + 1]
                  + ((v.z - mu) * rstd * flng[f + 2] + flnb[f + 2]) * linw[f + 2]
                  + ((v.w - mu) * rstd * flng[f + 3] + flnb[f + 3]) * linw[f + 3];
        #pragma unroll
        for (int o = 16; o; o >>= 1) dot += __shfl_xor_sync(0xffffffffu, dot, o);
        if (lane == 0) xcs[rr] = dot;
    }
    __syncthreads();

    if (tid == 0) {
        float ov = 0.f, l1 = 0.f, dn = 0.f;
        #pragma unroll
        for (int c = 0; c < NC; c++) {
            float mflag = (colsum[c] > 0.f) ? 1.f : 0.f;
            float v = xcs[c] * mflag;
            dout[257 + g * NC + c] = v;          // xc
            ov += v;
            l1 += fabsf(v);
            dn += mflag;
        }
        dout[g] = ov + bias[0];                  // out
        g_l1[g] = l1 / (dn + 1e-7f);
    }
}

// losses = 0.01*(sum|Wo|+sum|bo|) + 0.01*mean_g(l1[g])
__global__ void loss_kernel(const float* __restrict__ Wo,
                            const float* __restrict__ bo,
                            float* __restrict__ dout) {
    __shared__ float red[256];
    __shared__ float sreg;
    int tid = threadIdx.x;
    float rs = 0.f;
    for (int i = tid; i < NL * HD * HD; i += 256) rs += fabsf(Wo[i]);
    for (int i = tid; i < NL * HD; i += 256)      rs += fabsf(bo[i]);
    red[tid] = rs;
    __syncthreads();
    for (int o = 128; o; o >>= 1) {
        if (tid < o) red[tid] += red[tid + o];
        __syncthreads();
    }
    if (tid == 0) sreg = red[0];
    __syncthreads();
    float ls = (tid < NG) ? g_l1[tid] : 0.f;
    red[tid] = ls;
    __syncthreads();
    for (int o = 128; o; o >>= 1) {
        if (tid < o) red[tid] += red[tid + o];
        __syncthreads();
    }
    if (tid == 0)
        dout[256] = 0.01f * sreg + 0.01f * (red[0] / (float)NG);
}

// ---------------------------------------------------------------------------
extern "C" void kernel_launch(void* const* d_in, const int* in_sizes, int n_in,
                              void* d_out, int out_size) {
    const float* x    = (const float*)d_in[0];
    const void*  ei   = d_in[1];
    const void*  mk   = d_in[2];
    const float* s    = (const float*)d_in[3];
    // d_in[4] = batch (unused: graphs are equal-size, sorted)
    const float* Wn   = (const float*)d_in[5];
    const float* bn   = (const float*)d_in[6];
    const float* Wo   = (const float*)d_in[7];
    const float* bo   = (const float*)d_in[8];
    const float* Wr   = (const float*)d_in[9];
    const float* lng  = (const float*)d_in[10];
    const float* lnb  = (const float*)d_in[11];
    const float* flng = (const float*)d_in[12];
    const float* flnb = (const float*)d_in[13];
    const float* linw = (const float*)d_in[14];
    const float* bias = (const float*)d_in[15];
    float* out = (float*)d_out;

    cudaFuncSetAttribute(layer_kernel,
                         cudaFuncAttributeMaxDynamicSharedMemorySize, LAYER_SMEM);

    detect_kernel<<<1, 32>>>((const unsigned int*)ei, (const unsigned int*)mk);
    zero_all_kernel<<<1024, 256>>>();
    adj_build_kernel<<<N_EDGES / 256, 256>>>(ei, mk);

    for (int l = 0; l < NL; l++) {
        layer_kernel<<<NG, 512, LAYER_SMEM>>>(
            x, Wn + l * HD * HD, bn + l * HD,
            Wo + l * HD * HD, bo + l * HD, Wr + l * HD * HD,
            lng + l * HD, lnb + l * HD, l);
    }

    pool_kernel<<<NG, 256>>>(s, flng, flnb, linw, bias, out);
    loss_kernel<<<1, 256>>>(Wo, bo, out);
}

// round 10
// speedup vs baseline: 2.0793x; 1.1023x over previous
#include <cuda_runtime.h>
#include <cuda_bf16.h>
#include <stdint.h>

// ---------------------------------------------------------------------------
// SEALNetwork fully fused: one persistent CTA per graph runs all 3 GNN layers
// AND the pooling head; h lives in shared memory the whole time.
//   agg = (Ain.h).Wn^T + (Aout.h).Wo^T + cin (x) bn + cout (x) bo
// Adjacency = packed u8 counts (exact in bf16); bf16 hi/lo split everywhere
// else (3-pass GEMMs). All smem XOR-swizzled stride-128.
// ---------------------------------------------------------------------------

#define N_NODES 32768
#define N_EDGES 524288
#define NG      256
#define NPG     128
#define HD      128
#define NL      3
#define NC      16
#define BUFB    32768            // bytes per swizzled bf16 buffer (128x128)
#define ADJ_EL  (NG * NPG * NPG)

__device__ int           g_cin[N_NODES];
__device__ int           g_cout[N_NODES];
__device__ float         g_l1[NG];
__device__ unsigned char g_adj[2][ADJ_EL];   // [0]=masked(in), [1]=out
__device__ int           g_ei64;
__device__ int           g_mk_kind;          // 0=u8/bool 1=i32 2=f32

// ---------------------------------------------------------------------------
__device__ __forceinline__ uint32_t smem_u32(const void* p) {
    uint32_t a;
    asm("{ .reg .u64 t; cvta.to.shared.u64 t, %1; cvt.u32.u64 %0, t; }"
        : "=r"(a) : "l"(p));
    return a;
}

__device__ __forceinline__ void ldm_x4(uint32_t& r0, uint32_t& r1,
                                       uint32_t& r2, uint32_t& r3,
                                       uint32_t addr) {
    asm volatile("ldmatrix.sync.aligned.m8n8.x4.shared.b16 {%0,%1,%2,%3}, [%4];"
                 : "=r"(r0), "=r"(r1), "=r"(r2), "=r"(r3) : "r"(addr));
}

__device__ __forceinline__ void ldm_x4t(uint32_t& r0, uint32_t& r1,
                                        uint32_t& r2, uint32_t& r3,
                                        uint32_t addr) {
    asm volatile(
        "ldmatrix.sync.aligned.m8n8.x4.trans.shared.b16 {%0,%1,%2,%3}, [%4];"
        : "=r"(r0), "=r"(r1), "=r"(r2), "=r"(r3) : "r"(addr));
}

__device__ __forceinline__ void mma_bf16(float* c, const uint32_t* a,
                                         uint32_t b0, uint32_t b1) {
    asm volatile(
        "mma.sync.aligned.m16n8k16.row.col.f32.bf16.bf16.f32 "
        "{%0,%1,%2,%3}, {%4,%5,%6,%7}, {%8,%9}, {%0,%1,%2,%3};"
        : "+f"(c[0]), "+f"(c[1]), "+f"(c[2]), "+f"(c[3])
        : "r"(a[0]), "r"(a[1]), "r"(a[2]), "r"(a[3]), "r"(b0), "r"(b1));
}

__device__ __forceinline__ uint32_t bf2pack(float a, float b) {
    unsigned short lo = __bfloat16_as_ushort(__float2bfloat16(a));
    unsigned short hi = __bfloat16_as_ushort(__float2bfloat16(b));
    return (uint32_t)lo | ((uint32_t)hi << 16);
}

__device__ __forceinline__ uint32_t swz(int r, int c) {
    return (uint32_t)(r * 256 + ((((c >> 3) ^ (r & 7)) << 4) | ((c & 7) * 2)));
}

__device__ __forceinline__ void pass_nn(float acc[2][4][4], uint32_t Abase,
                                        uint32_t Bbase, int m_blk, int n_blk,
                                        int lane) {
    int ar = lane & 15, ak = lane >> 4;
    int br = (lane & 7) + ((lane & 16) >> 1), bk = (lane & 8) >> 3;
    #pragma unroll
    for (int ks = 0; ks < 8; ks++) {
        uint32_t a[2][4];
        #pragma unroll
        for (int mt = 0; mt < 2; mt++) {
            int row = m_blk + mt * 16 + ar;
            int kg = ks * 2 + ak;
            ldm_x4(a[mt][0], a[mt][1], a[mt][2], a[mt][3],
                   Abase + (uint32_t)(row * 256 + ((kg ^ (row & 7)) << 4)));
        }
        uint32_t b[4][2];
        #pragma unroll
        for (int np = 0; np < 2; np++) {
            int row = n_blk + np * 16 + br;
            int kg = ks * 2 + bk;
            uint32_t r0, r1, r2, r3;
            ldm_x4(r0, r1, r2, r3,
                   Bbase + (uint32_t)(row * 256 + ((kg ^ (row & 7)) << 4)));
            b[np * 2][0] = r0;     b[np * 2][1] = r1;
            b[np * 2 + 1][0] = r2; b[np * 2 + 1][1] = r3;
        }
        #pragma unroll
        for (int mt = 0; mt < 2; mt++)
            #pragma unroll
            for (int nt = 0; nt < 4; nt++)
                mma_bf16(acc[mt][nt], a[mt], b[nt][0], b[nt][1]);
    }
}

__device__ __forceinline__ void pass_nt(float acc[2][4][4], uint32_t Abase,
                                        uint32_t Bbase, int m_blk, int n_blk,
                                        int lane) {
    int ar = lane & 15, ak = lane >> 4;
    int tr = lane & 15, tn = lane >> 4;
    #pragma unroll
    for (int ks = 0; ks < 8; ks++) {
        uint32_t a[2][4];
        #pragma unroll
        for (int mt = 0; mt < 2; mt++) {
            int row = m_blk + mt * 16 + ar;
            int kg = ks * 2 + ak;
            ldm_x4(a[mt][0], a[mt][1], a[mt][2], a[mt][3],
                   Abase + (uint32_t)(row * 256 + ((kg ^ (row & 7)) << 4)));
        }
        uint32_t b[4][2];
        #pragma unroll
        for (int np = 0; np < 2; np++) {
            int row = ks * 16 + tr;
            int ng = ((n_blk + np * 16) >> 3) + tn;
            uint32_t r0, r1, r2, r3;
            ldm_x4t(r0, r1, r2, r3,
                    Bbase + (uint32_t)(row * 256 + ((ng ^ (row & 7)) << 4)));
            b[np * 2][0] = r0;     b[np * 2][1] = r1;
            b[np * 2 + 1][0] = r2; b[np * 2 + 1][1] = r3;
        }
        #pragma unroll
        for (int mt = 0; mt < 2; mt++)
            #pragma unroll
            for (int nt = 0; nt < 4; nt++)
                mma_bf16(acc[mt][nt], a[mt], b[nt][0], b[nt][1]);
    }
}

// ---------------------------------------------------------------------------
__global__ void detect_kernel(const unsigned int* __restrict__ ei_w,
                              const unsigned int* __restrict__ mk_w) {
    int lane = threadIdx.x;
    int odd = 0;
    for (int i = lane; i < 64; i += 32)
        if (ei_w[2 * i + 1] != 0u) odd = 1;
    unsigned m1 = __ballot_sync(0xffffffffu, odd);
    int f1 = 0, mb = 0;
    for (int i = lane; i < 256; i += 32) {
        unsigned w = mk_w[i];
        if (w == 0x3F800000u) f1 = 1;
        else if ((w >> 8) != 0u) mb = 1;
    }
    unsigned mf = __ballot_sync(0xffffffffu, f1);
    unsigned mm = __ballot_sync(0xffffffffu, mb);
    if (lane == 0) {
        g_ei64 = (m1 == 0u) ? 1 : 0;
        g_mk_kind = mf ? 2 : (mm ? 0 : 1);
    }
}

__device__ __forceinline__ int load_idx(const void* ei, int pos) {
    if (g_ei64) return (int)((const long long*)ei)[pos];
    return ((const int*)ei)[pos];
}
__device__ __forceinline__ bool load_mask(const void* mk, int e) {
    int kind = g_mk_kind;
    if (kind == 0) return ((const unsigned char*)mk)[e] != 0;
    if (kind == 1) return ((const int*)mk)[e] != 0;
    return ((const float*)mk)[e] != 0.0f;
}

__global__ void zero_all_kernel() {
    int stride = gridDim.x * blockDim.x;
    int i0 = blockIdx.x * blockDim.x + threadIdx.x;
    uint4 z = make_uint4(0, 0, 0, 0);
    for (int i = i0; i < ADJ_EL / 16; i += stride) {
        ((uint4*)g_adj[0])[i] = z;
        ((uint4*)g_adj[1])[i] = z;
    }
    for (int i = i0; i < N_NODES; i += stride) {
        g_cin[i] = 0;
        g_cout[i] = 0;
    }
}

__global__ void adj_build_kernel(const void* __restrict__ ei,
                                 const void* __restrict__ mk) {
    int e = blockIdx.x * blockDim.x + threadIdx.x;
    if (e >= N_EDGES) return;
    int t = load_idx(ei, N_EDGES + e);
    int s = load_idx(ei, e);
    if ((unsigned)t >= (unsigned)N_NODES) return;
    if ((unsigned)s >= (unsigned)N_NODES) return;
    if ((t >> 7) != (s >> 7)) return;
    int sel = load_mask(mk, e) ? 0 : 1;
    int idx = ((t >> 7) * NPG + (t & 127)) * NPG + (s & 127);
    atomicAdd(&((unsigned int*)g_adj[sel])[idx >> 2], 1u << ((idx & 3) * 8));
    atomicAdd(sel ? &g_cout[t] : &g_cin[t], 1);
}

// ---------------------------------------------------------------------------
// Fused network kernel: one CTA per graph, 512 threads, all 3 layers + pool.
// Buffers (32KB each): [0]C0 [1]C1 [2]D [3]A0 [4]A1 [5]W0 [6]W1
// fp32 S[128][132] overlays buffers 0-2; fp32 P[128][132] overlays 3-5.
// ---------------------------------------------------------------------------
#define FUSED_SMEM (7 * BUFB)

__global__ void __launch_bounds__(512)
fused_kernel(const float* __restrict__ x,
             const float* __restrict__ Wn_, const float* __restrict__ bn_,
             const float* __restrict__ Wo_, const float* __restrict__ bo_,
             const float* __restrict__ Wr_,
             const float* __restrict__ lng_, const float* __restrict__ lnb_,
             const float* __restrict__ sIn,
             const float* __restrict__ flng, const float* __restrict__ flnb,
             const float* __restrict__ linw, const float* __restrict__ bias,
             float* __restrict__ dout) {
    extern __shared__ __align__(16) char dyn[];
    __shared__ float sbn[HD], sbo[HD];
    __shared__ float colsum[NC], xcs[NC];

    int tid = threadIdx.x;
    int w = tid >> 5, lane = tid & 31;
    int m_blk = (w >> 2) * 32, n_blk = (w & 3) * 32;
    int grp = lane >> 2, tig = lane & 3;
    int g = blockIdx.x, row0 = g * 128;

    uint32_t base = smem_u32(dyn);
    uint32_t C0 = base, C1 = base + BUFB, Dd = base + 2 * BUFB;
    uint32_t A0 = base + 3 * BUFB, A1 = base + 4 * BUFB;
    uint32_t W0 = base + 5 * BUFB, W1 = base + 6 * BUFB;
    float* S = (float*)dyn;
    float* P = (float*)(dyn + 3 * BUFB);

    // --- layer-0 h: split x into A0/A1 ---
    #pragma unroll
    for (int i = 0; i < 4; i++) {
        int gid = tid + i * 512;
        int r = gid >> 4, gq = gid & 15;
        const float* src = x + (size_t)(row0 + r) * HD + gq * 8;
        float v[8];
        *(float4*)(v)     = *(const float4*)(src);
        *(float4*)(v + 4) = *(const float4*)(src + 4);
        uint32_t hi[4], lo[4];
        #pragma unroll
        for (int j = 0; j < 4; j++) {
            float a = v[2 * j], b = v[2 * j + 1];
            __nv_bfloat16 ha = __float2bfloat16(a), hb = __float2bfloat16(b);
            hi[j] = (uint32_t)__bfloat16_as_ushort(ha)
                  | ((uint32_t)__bfloat16_as_ushort(hb) << 16);
            lo[j] = bf2pack(a - __bfloat162float(ha), b - __bfloat162float(hb));
        }
        uint32_t off = (uint32_t)(r * 256 + ((gq ^ (r & 7)) << 4));
        *(uint4*)((char*)dyn + (A0 - base) + off) = make_uint4(hi[0], hi[1], hi[2], hi[3]);
        *(uint4*)((char*)dyn + (A1 - base) + off) = make_uint4(lo[0], lo[1], lo[2], lo[3]);
    }

    #pragma unroll 1
    for (int l = 0; l < NL; l++) {
        const float* Wn = Wn_ + l * HD * HD;
        const float* Wo = Wo_ + l * HD * HD;
        const float* Wr = Wr_ + l * HD * HD;

        __syncthreads();   // A0/A1 (h) ready; S/C region free
        if (tid < HD) { sbn[tid] = bn_[l * HD + tid]; sbo[tid] = bo_[l * HD + tid]; }

        // adjacency u8 -> bf16 into C0/C1
        #pragma unroll
        for (int sel = 0; sel < 2; sel++) {
            const unsigned char* src = g_adj[sel] + (size_t)g * NPG * NPG;
            uint32_t dst = (sel == 0) ? C0 : C1;
            #pragma unroll
            for (int i = 0; i < 4; i++) {
                int gid = tid + i * 512;
                int r = gid >> 4, gq = gid & 15;
                uint2 raw = *(const uint2*)(src + r * NPG + gq * 8);
                uint32_t p[4];
                p[0] = bf2pack((float)(raw.x & 255), (float)((raw.x >> 8) & 255));
                p[1] = bf2pack((float)((raw.x >> 16) & 255), (float)(raw.x >> 24));
                p[2] = bf2pack((float)(raw.y & 255), (float)((raw.y >> 8) & 255));
                p[3] = bf2pack((float)((raw.y >> 16) & 255), (float)(raw.y >> 24));
                uint32_t off = (uint32_t)(r * 256 + ((gq ^ (r & 7)) << 4));
                *(uint4*)((char*)dyn + (dst - base) + off) = make_uint4(p[0], p[1], p[2], p[3]);
            }
        }

        // Wr split into W0/W1
        #pragma unroll
        for (int i = 0; i < 4; i++) {
            int gid = tid + i * 512;
            int r = gid >> 4, gq = gid & 15;
            const float* src = Wr + (size_t)r * HD + gq * 8;
            float v[8];
            *(float4*)(v)     = *(const float4*)(src);
            *(float4*)(v + 4) = *(const float4*)(src + 4);
            uint32_t hi[4], lo[4];
            #pragma unroll
            for (int j = 0; j < 4; j++) {
                float a = v[2 * j], b = v[2 * j + 1];
                __nv_bfloat16 ha = __float2bfloat16(a), hb = __float2bfloat16(b);
                hi[j] = (uint32_t)__bfloat16_as_ushort(ha)
                      | ((uint32_t)__bfloat16_as_ushort(hb) << 16);
                lo[j] = bf2pack(a - __bfloat162float(ha), b - __bfloat162float(hb));
            }
            uint32_t off = (uint32_t)(r * 256 + ((gq ^ (r & 7)) << 4));
            *(uint4*)((char*)dyn + (W0 - base) + off) = make_uint4(hi[0], hi[1], hi[2], hi[3]);
            *(uint4*)((char*)dyn + (W1 - base) + off) = make_uint4(lo[0], lo[1], lo[2], lo[3]);
        }
        __syncthreads();

        // root = h @ Wr^T
        float root[2][4][4];
        #pragma unroll
        for (int mt = 0; mt < 2; mt++)
            #pragma unroll
            for (int nt = 0; nt < 4; nt++)
                #pragma unroll
                for (int q = 0; q < 4; q++) root[mt][nt][q] = 0.f;
        pass_nn(root, A0, W0, m_blk, n_blk, lane);
        pass_nn(root, A0, W1, m_blk, n_blk, lane);
        pass_nn(root, A1, W0, m_blk, n_blk, lane);

        // Hin = Ain @ h
        float hacc[2][4][4];
        #pragma unroll
        for (int mt = 0; mt < 2; mt++)
            #pragma unroll
            for (int nt = 0; nt < 4; nt++)
                #pragma unroll
                for (int q = 0; q < 4; q++) hacc[mt][nt][q] = 0.f;
        pass_nt(hacc, C0, A0, m_blk, n_blk, lane);
        pass_nt(hacc, C0, A1, m_blk, n_blk, lane);
        __syncthreads();
        #pragma unroll
        for (int mt = 0; mt < 2; mt++) {
            #pragma unroll
            for (int nt = 0; nt < 4; nt++) {
                int rg = m_blk + mt * 16 + grp;
                int cg = n_blk + nt * 8 + tig * 2;
                #pragma unroll
                for (int half = 0; half < 2; half++) {
                    int row = rg + half * 8;
                    float a = hacc[mt][nt][half * 2], b = hacc[mt][nt][half * 2 + 1];
                    __nv_bfloat16 ha = __float2bfloat16(a), hb = __float2bfloat16(b);
                    uint32_t off = swz(row, cg);
                    *(uint32_t*)((char*)dyn + (C0 - base) + off) =
                        (uint32_t)__bfloat16_as_ushort(ha)
                        | ((uint32_t)__bfloat16_as_ushort(hb) << 16);
                    *(uint32_t*)((char*)dyn + (Dd - base) + off) =
                        bf2pack(a - __bfloat162float(ha), b - __bfloat162float(hb));
                }
            }
        }

        // Hout = Aout @ h
        #pragma unroll
        for (int mt = 0; mt < 2; mt++)
            #pragma unroll
            for (int nt = 0; nt < 4; nt++)
                #pragma unroll
                for (int q = 0; q < 4; q++) hacc[mt][nt][q] = 0.f;
        pass_nt(hacc, C1, A0, m_blk, n_blk, lane);
        pass_nt(hacc, C1, A1, m_blk, n_blk, lane);
        __syncthreads();
        #pragma unroll
        for (int mt = 0; mt < 2; mt++) {
            #pragma unroll
            for (int nt = 0; nt < 4; nt++) {
                int rg = m_blk + mt * 16 + grp;
                int cg = n_blk + nt * 8 + tig * 2;
                #pragma unroll
                for (int half = 0; half < 2; half++) {
                    int row = rg + half * 8;
                    float a = hacc[mt][nt][half * 2], b = hacc[mt][nt][half * 2 + 1];
                    __nv_bfloat16 ha = __float2bfloat16(a), hb = __float2bfloat16(b);
                    uint32_t off = swz(row, cg);
                    *(uint32_t*)((char*)dyn + (C1 - base) + off) =
                        (uint32_t)__bfloat16_as_ushort(ha)
                        | ((uint32_t)__bfloat16_as_ushort(hb) << 16);
                    *(uint32_t*)((char*)dyn + (A1 - base) + off) =
                        bf2pack(a - __bfloat162float(ha), b - __bfloat162float(hb));
                }
            }
        }
        __syncthreads();

        // agg = Hin @ Wn^T + Hout @ Wo^T
        float agg[2][4][4];
        #pragma unroll
        for (int mt = 0; mt < 2; mt++)
            #pragma unroll
            for (int nt = 0; nt < 4; nt++)
                #pragma unroll
                for (int q = 0; q < 4; q++) agg[mt][nt][q] = 0.f;

        const float* Wptr[2] = {Wn, Wo};
        #pragma unroll 1
        for (int m = 0; m < 2; m++) {
            const float* Wm = Wptr[m];
            #pragma unroll
            for (int i = 0; i < 4; i++) {
                int gid = tid + i * 512;
                int r = gid >> 4, gq = gid & 15;
                const float* src = Wm + (size_t)r * HD + gq * 8;
                float v[8];
                *(float4*)(v)     = *(const float4*)(src);
                *(float4*)(v + 4) = *(const float4*)(src + 4);
                uint32_t hi[4], lo[4];
                #pragma unroll
                for (int j = 0; j < 4; j++) {
                    float a = v[2 * j], b = v[2 * j + 1];
                    __nv_bfloat16 ha = __float2bfloat16(a), hb = __float2bfloat16(b);
                    hi[j] = (uint32_t)__bfloat16_as_ushort(ha)
                          | ((uint32_t)__bfloat16_as_ushort(hb) << 16);
                    lo[j] = bf2pack(a - __bfloat162float(ha),
                                    b - __bfloat162float(hb));
                }
                uint32_t off = (uint32_t)(r * 256 + ((gq ^ (r & 7)) << 4));
                *(uint4*)((char*)dyn + (W0 - base) + off) = make_uint4(hi[0], hi[1], hi[2], hi[3]);
                *(uint4*)((char*)dyn + (W1 - base) + off) = make_uint4(lo[0], lo[1], lo[2], lo[3]);
            }
            __syncthreads();

            uint32_t Hhi = (m == 0) ? C0 : C1;
            uint32_t Hlo = (m == 0) ? Dd : A1;
            pass_nn(agg, Hhi, W0, m_blk, n_blk, lane);
            pass_nn(agg, Hhi, W1, m_blk, n_blk, lane);
            pass_nn(agg, Hlo, W0, m_blk, n_blk, lane);
            __syncthreads();
        }

        // epilogue -> S (fp32, overlays C0/C1/D)
        #pragma unroll
        for (int mt = 0; mt < 2; mt++) {
            int rg = m_blk + mt * 16 + grp;
            #pragma unroll
            for (int half = 0; half < 2; half++) {
                int row = rg + half * 8;
                float ci = (float)g_cin[row0 + row];
                float co = (float)g_cout[row0 + row];
                float inv = 1.0f / fmaxf(ci + co, 1.0f);
                #pragma unroll
                for (int nt = 0; nt < 4; nt++) {
                    int cg = n_blk + nt * 8 + tig * 2;
                    float v0 = (agg[mt][nt][half * 2]     + ci * sbn[cg]
                                + co * sbo[cg]) * inv + root[mt][nt][half * 2];
                    float v1 = (agg[mt][nt][half * 2 + 1] + ci * sbn[cg + 1]
                                + co * sbo[cg + 1]) * inv + root[mt][nt][half * 2 + 1];
                    S[row * 132 + cg]     = v0;
                    S[row * 132 + cg + 1] = v1;
                }
            }
        }
        __syncthreads();

        // LayerNorm + ReLU (4 threads/row); write next-layer h or final P
        {
            int row = tid >> 2, q = tid & 3;
            const float* Sr = S + row * 132 + q * 32;
            float v[32];
            float sum = 0.f, sq = 0.f;
            #pragma unroll
            for (int j = 0; j < 32; j++) {
                v[j] = Sr[j];
                sum += v[j];
                sq  += v[j] * v[j];
            }
            sum += __shfl_xor_sync(0xffffffffu, sum, 1);
            sum += __shfl_xor_sync(0xffffffffu, sum, 2);
            sq  += __shfl_xor_sync(0xffffffffu, sq, 1);
            sq  += __shfl_xor_sync(0xffffffffu, sq, 2);
            float mu   = sum * (1.0f / 128.0f);
            float var  = sq * (1.0f / 128.0f) - mu * mu;
            float rstd = rsqrtf(var + 1e-5f);

            const float* gma = lng_ + l * HD + q * 32;
            const float* bta = lnb_ + l * HD + q * 32;
            if (l < NL - 1) {
                #pragma unroll
                for (int j = 0; j < 32; j += 2) {
                    float o0 = fmaxf((v[j]     - mu) * rstd * gma[j]     + bta[j],     0.f);
                    float o1 = fmaxf((v[j + 1] - mu) * rstd * gma[j + 1] + bta[j + 1], 0.f);
                    int c = q * 32 + j;
                    uint32_t off = swz(row, c);
                    __nv_bfloat16 h0 = __float2bfloat16(o0), h1 = __float2bfloat16(o1);
                    *(uint32_t*)((char*)dyn + (A0 - base) + off) =
                        (uint32_t)__bfloat16_as_ushort(h0)
                        | ((uint32_t)__bfloat16_as_ushort(h1) << 16);
                    *(uint32_t*)((char*)dyn + (A1 - base) + off) =
                        bf2pack(o0 - __bfloat162float(h0), o1 - __bfloat162float(h1));
                }
            } else {
                float* Pr = P + row * 132 + q * 32;
                #pragma unroll
                for (int j = 0; j < 32; j += 4) {
                    float o0 = fmaxf((v[j]     - mu) * rstd * gma[j]     + bta[j],     0.f);
                    float o1 = fmaxf((v[j + 1] - mu) * rstd * gma[j + 1] + bta[j + 1], 0.f);
                    float o2 = fmaxf((v[j + 2] - mu) * rstd * gma[j + 2] + bta[j + 2], 0.f);
                    float o3 = fmaxf((v[j + 3] - mu) * rstd * gma[j + 3] + bta[j + 3], 0.f);
                    *(float4*)(Pr + j) = make_float4(o0, o1, o2, o3);
                }
            }
        }
    }

    // =================== pooling head (in-CTA) ===================
    __syncthreads();
    float* sdP = (float*)dyn;             // 8KB (S region dead)
    float* plP = (float*)(dyn + 8192);    // 8KB

    *(float4*)(sdP + tid * 4) =
        *(const float4*)(sIn + (size_t)g * NPG * NC + tid * 4);
    __syncthreads();

    if (tid < NC) {
        float cs = 0.f;
        for (int n = 0; n < NPG; n++) cs += sdP[n * NC + tid];
        colsum[tid] = cs;
    }

    {
        int hcol = tid & 127, cgrp = tid >> 7;
        float pacc[4] = {0.f, 0.f, 0.f, 0.f};
        #pragma unroll 4
        for (int n = 0; n < NPG; n++) {
            float xv = P[n * 132 + hcol];
            #pragma unroll
            for (int c = 0; c < 4; c++)
                pacc[c] = fmaf(sdP[n * NC + cgrp * 4 + c], xv, pacc[c]);
        }
        #pragma unroll
        for (int c = 0; c < 4; c++)
            plP[(cgrp * 4 + c) * 128 + hcol] = pacc[c];
    }
    __syncthreads();

    {
        int rr = w;   // 16 warps -> 16 channels
        float4 v = *(float4*)(plP + rr * 128 + lane * 4);
        float sum = v.x + v.y + v.z + v.w;
        float sq  = v.x * v.x + v.y * v.y + v.z * v.z + v.w * v.w;
        #pragma unroll
        for (int o = 16; o; o >>= 1) {
            sum += __shfl_xor_sync(0xffffffffu, sum, o);
            sq  += __shfl_xor_sync(0xffffffffu, sq,  o);
        }
        float mu   = sum * (1.0f / 128.0f);
        float var  = sq * (1.0f / 128.0f) - mu * mu;
        float rstd = rsqrtf(var + 1e-5f);
        int f = lane * 4;
        float dot = ((v.x - mu) * rstd * flng[f + 0] + flnb[f + 0]) * linw[f + 0]
                  + ((v.y - mu) * rstd * flng[f + 1] + flnb[f + 1]) * linw[f + 1]
                  + ((v.z - mu) * rstd * flng[f + 2] + flnb[f + 2]) * linw[f + 2]
                  + ((v.w - mu) * rstd * flng[f + 3] + flnb[f + 3]) * linw[f + 3];
        #pragma unroll
        for (int o = 16; o; o >>= 1) dot += __shfl_xor_sync(0xffffffffu, dot, o);
        if (lane == 0) xcs[rr] = dot;
    }
    __syncthreads();

    if (tid == 0) {
        float ov = 0.f, l1 = 0.f, dn = 0.f;
        #pragma unroll
        for (int c = 0; c < NC; c++) {
            float mflag = (colsum[c] > 0.f) ? 1.f : 0.f;
            float v = xcs[c] * mflag;
            dout[257 + g * NC + c] = v;
            ov += v;
            l1 += fabsf(v);
            dn += mflag;
        }
        dout[g] = ov + bias[0];
        g_l1[g] = l1 / (dn + 1e-7f);
    }
}

// losses = 0.01*(sum|Wo|+sum|bo|) + 0.01*mean_g(l1[g])
__global__ void loss_kernel(const float* __restrict__ Wo,
                            const float* __restrict__ bo,
                            float* __restrict__ dout) {
    __shared__ float red[256];
    __shared__ float sreg;
    int tid = threadIdx.x;
    float rs = 0.f;
    for (int i = tid; i < NL * HD * HD; i += 256) rs += fabsf(Wo[i]);
    for (int i = tid; i < NL * HD; i += 256)      rs += fabsf(bo[i]);
    red[tid] = rs;
    __syncthreads();
    for (int o = 128; o; o >>= 1) {
        if (tid < o) red[tid] += red[tid + o];
        __syncthreads();
    }
    if (tid == 0) sreg = red[0];
    __syncthreads();
    float ls = (tid < NG) ? g_l1[tid] : 0.f;
    red[tid] = ls;
    __syncthreads();
    for (int o = 128; o; o >>= 1) {
        if (tid < o) red[tid] += red[tid + o];
        __syncthreads();
    }
    if (tid == 0)
        dout[256] = 0.01f * sreg + 0.01f * (red[0] / (float)NG);
}

// ---------------------------------------------------------------------------
extern "C" void kernel_launch(void* const* d_in, const int* in_sizes, int n_in,
                              void* d_out, int out_size) {
    const float* x    = (const float*)d_in[0];
    const void*  ei   = d_in[1];
    const void*  mk   = d_in[2];
    const float* s    = (const float*)d_in[3];
    // d_in[4] = batch (unused: graphs are equal-size, sorted)
    const float* Wn   = (const float*)d_in[5];
    const float* bn   = (const float*)d_in[6];
    const float* Wo   = (const float*)d_in[7];
    const float* bo   = (const float*)d_in[8];
    const float* Wr   = (const float*)d_in[9];
    const float* lng  = (const float*)d_in[10];
    const float* lnb  = (const float*)d_in[11];
    const float* flng = (const float*)d_in[12];
    const float* flnb = (const float*)d_in[13];
    const float* linw = (const float*)d_in[14];
    const float* bias = (const float*)d_in[15];
    float* out = (float*)d_out;

    cudaFuncSetAttribute(fused_kernel,
                         cudaFuncAttributeMaxDynamicSharedMemorySize, FUSED_SMEM);

    detect_kernel<<<1, 32>>>((const unsigned int*)ei, (const unsigned int*)mk);
    zero_all_kernel<<<1024, 256>>>();
    adj_build_kernel<<<N_EDGES / 256, 256>>>(ei, mk);

    fused_kernel<<<NG, 512, FUSED_SMEM>>>(
        x, Wn, bn, Wo, bo, Wr, lng, lnb,
        s, flng, flnb, linw, bias, out);

    loss_kernel<<<1, 256>>>(Wo, bo, out);
}

// round 11
// speedup vs baseline: 2.8254x; 1.3588x over previous
#include <cuda_runtime.h>
#include <cuda_bf16.h>
#include <stdint.h>

// ---------------------------------------------------------------------------
// SEALNetwork fully fused: one CTA per graph runs all 3 GNN layers + pooling;
// h lives in shared memory throughout.
//   agg = (Ain.h).Wn^T + (Aout.h).Wo^T + cin (x) bn + cout (x) bo
// Adjacency = packed u8 counts (exact in bf16); bf16 hi/lo split elsewhere.
// R11: fused multi-operand MMA passes — each K-sweep loads the shared
// operand's ldmatrix fragments ONCE and issues all split-term MMAs from
// them (3-term weight products, 2-term adjacency products), cutting LDSM
// traffic ~36% (L1 pipe was the 55% bottleneck).
// ---------------------------------------------------------------------------

#define N_NODES 32768
#define N_EDGES 524288
#define NG      256
#define NPG     128
#define HD      128
#define NL      3
#define NC      16
#define BUFB    32768
#define ADJ_EL  (NG * NPG * NPG)

__device__ int           g_cin[N_NODES];
__device__ int           g_cout[N_NODES];
__device__ float         g_l1[NG];
__device__ unsigned char g_adj[2][ADJ_EL];   // [0]=masked(in), [1]=out
__device__ int           g_ei64;
__device__ int           g_mk_kind;          // 0=u8/bool 1=i32 2=f32

// ---------------------------------------------------------------------------
__device__ __forceinline__ uint32_t smem_u32(const void* p) {
    uint32_t a;
    asm("{ .reg .u64 t; cvta.to.shared.u64 t, %1; cvt.u32.u64 %0, t; }"
        : "=r"(a) : "l"(p));
    return a;
}

__device__ __forceinline__ void ldm_x4(uint32_t& r0, uint32_t& r1,
                                       uint32_t& r2, uint32_t& r3,
                                       uint32_t addr) {
    asm volatile("ldmatrix.sync.aligned.m8n8.x4.shared.b16 {%0,%1,%2,%3}, [%4];"
                 : "=r"(r0), "=r"(r1), "=r"(r2), "=r"(r3) : "r"(addr));
}

__device__ __forceinline__ void ldm_x4t(uint32_t& r0, uint32_t& r1,
                                        uint32_t& r2, uint32_t& r3,
                                        uint32_t addr) {
    asm volatile(
        "ldmatrix.sync.aligned.m8n8.x4.trans.shared.b16 {%0,%1,%2,%3}, [%4];"
        : "=r"(r0), "=r"(r1), "=r"(r2), "=r"(r3) : "r"(addr));
}

__device__ __forceinline__ void mma_bf16(float* c, const uint32_t* a,
                                         uint32_t b0, uint32_t b1) {
    asm volatile(
        "mma.sync.aligned.m16n8k16.row.col.f32.bf16.bf16.f32 "
        "{%0,%1,%2,%3}, {%4,%5,%6,%7}, {%8,%9}, {%0,%1,%2,%3};"
        : "+f"(c[0]), "+f"(c[1]), "+f"(c[2]), "+f"(c[3])
        : "r"(a[0]), "r"(a[1]), "r"(a[2]), "r"(a[3]), "r"(b0), "r"(b1));
}

__device__ __forceinline__ uint32_t bf2pack(float a, float b) {
    unsigned short lo = __bfloat16_as_ushort(__float2bfloat16(a));
    unsigned short hi = __bfloat16_as_ushort(__float2bfloat16(b));
    return (uint32_t)lo | ((uint32_t)hi << 16);
}

__device__ __forceinline__ uint32_t swz(int r, int c) {
    return (uint32_t)(r * 256 + ((((c >> 3) ^ (r & 7)) << 4) | ((c & 7) * 2)));
}

// Fused 3-term split GEMM: acc += A0*B0^T + A0*B1^T + A1*B0^T.
// One fragment load per operand per k-step; 24 MMAs per 8 ldmatrix.x4.
__device__ __forceinline__ void pass3_nn(float acc[2][4][4],
                                         uint32_t A0b, uint32_t A1b,
                                         uint32_t B0b, uint32_t B1b,
                                         int m_blk, int n_blk, int lane) {
    int ar = lane & 15, ak = lane >> 4;
    int br = (lane & 7) + ((lane & 16) >> 1), bk = (lane & 8) >> 3;
    #pragma unroll
    for (int ks = 0; ks < 8; ks++) {
        uint32_t a0[2][4], a1[2][4];
        #pragma unroll
        for (int mt = 0; mt < 2; mt++) {
            int row = m_blk + mt * 16 + ar;
            uint32_t off = (uint32_t)(row * 256 + (((ks * 2 + ak) ^ (row & 7)) << 4));
            ldm_x4(a0[mt][0], a0[mt][1], a0[mt][2], a0[mt][3], A0b + off);
            ldm_x4(a1[mt][0], a1[mt][1], a1[mt][2], a1[mt][3], A1b + off);
        }
        uint32_t b0[4][2], b1[4][2];
        #pragma unroll
        for (int np = 0; np < 2; np++) {
            int row = n_blk + np * 16 + br;
            uint32_t off = (uint32_t)(row * 256 + (((ks * 2 + bk) ^ (row & 7)) << 4));
            uint32_t r0, r1, r2, r3;
            ldm_x4(r0, r1, r2, r3, B0b + off);
            b0[np * 2][0] = r0;     b0[np * 2][1] = r1;
            b0[np * 2 + 1][0] = r2; b0[np * 2 + 1][1] = r3;
            ldm_x4(r0, r1, r2, r3, B1b + off);
            b1[np * 2][0] = r0;     b1[np * 2][1] = r1;
            b1[np * 2 + 1][0] = r2; b1[np * 2 + 1][1] = r3;
        }
        #pragma unroll
        for (int mt = 0; mt < 2; mt++)
            #pragma unroll
            for (int nt = 0; nt < 4; nt++) {
                mma_bf16(acc[mt][nt], a0[mt], b0[nt][0], b0[nt][1]);
                mma_bf16(acc[mt][nt], a0[mt], b1[nt][0], b1[nt][1]);
                mma_bf16(acc[mt][nt], a1[mt], b0[nt][0], b0[nt][1]);
            }
    }
}

// Fused 2-term adjacency GEMM: acc += C*(B0 + B1) where B row-major (trans).
// C fragments loaded once per k-step; 16 MMAs per 6 ldmatrix.x4.
__device__ __forceinline__ void pass2_nt(float acc[2][4][4], uint32_t Cb,
                                         uint32_t B0b, uint32_t B1b,
                                         int m_blk, int n_blk, int lane) {
    int ar = lane & 15, ak = lane >> 4;
    int tr = lane & 15, tn = lane >> 4;
    #pragma unroll
    for (int ks = 0; ks < 8; ks++) {
        uint32_t c[2][4];
        #pragma unroll
        for (int mt = 0; mt < 2; mt++) {
            int row = m_blk + mt * 16 + ar;
            uint32_t off = (uint32_t)(row * 256 + (((ks * 2 + ak) ^ (row & 7)) << 4));
            ldm_x4(c[mt][0], c[mt][1], c[mt][2], c[mt][3], Cb + off);
        }
        uint32_t p[4][2], q[4][2];
        #pragma unroll
        for (int np = 0; np < 2; np++) {
            int row = ks * 16 + tr;
            int ng = ((n_blk + np * 16) >> 3) + tn;
            uint32_t off = (uint32_t)(row * 256 + ((ng ^ (row & 7)) << 4));
            uint32_t r0, r1, r2, r3;
            ldm_x4t(r0, r1, r2, r3, B0b + off);
            p[np * 2][0] = r0;     p[np * 2][1] = r1;
            p[np * 2 + 1][0] = r2; p[np * 2 + 1][1] = r3;
            ldm_x4t(r0, r1, r2, r3, B1b + off);
            q[np * 2][0] = r0;     q[np * 2][1] = r1;
            q[np * 2 + 1][0] = r2; q[np * 2 + 1][1] = r3;
        }
        #pragma unroll
        for (int mt = 0; mt < 2; mt++)
            #pragma unroll
            for (int nt = 0; nt < 4; nt++) {
                mma_bf16(acc[mt][nt], c[mt], p[nt][0], p[nt][1]);
                mma_bf16(acc[mt][nt], c[mt], q[nt][0], q[nt][1]);
            }
    }
}

// ---------------------------------------------------------------------------
__global__ void detect_kernel(const unsigned int* __restrict__ ei_w,
                              const unsigned int* __restrict__ mk_w) {
    int lane = threadIdx.x;
    int odd = 0;
    for (int i = lane; i < 64; i += 32)
        if (ei_w[2 * i + 1] != 0u) odd = 1;
    unsigned m1 = __ballot_sync(0xffffffffu, odd);
    int f1 = 0, mb = 0;
    for (int i = lane; i < 256; i += 32) {
        unsigned w = mk_w[i];
        if (w == 0x3F800000u) f1 = 1;
        else if ((w >> 8) != 0u) mb = 1;
    }
    unsigned mf = __ballot_sync(0xffffffffu, f1);
    unsigned mm = __ballot_sync(0xffffffffu, mb);
    if (lane == 0) {
        g_ei64 = (m1 == 0u) ? 1 : 0;
        g_mk_kind = mf ? 2 : (mm ? 0 : 1);
    }
}

__device__ __forceinline__ int load_idx(const void* ei, int pos) {
    if (g_ei64) return (int)((const long long*)ei)[pos];
    return ((const int*)ei)[pos];
}
__device__ __forceinline__ bool load_mask(const void* mk, int e) {
    int kind = g_mk_kind;
    if (kind == 0) return ((const unsigned char*)mk)[e] != 0;
    if (kind == 1) return ((const int*)mk)[e] != 0;
    return ((const float*)mk)[e] != 0.0f;
}

__global__ void zero_all_kernel() {
    int stride = gridDim.x * blockDim.x;
    int i0 = blockIdx.x * blockDim.x + threadIdx.x;
    uint4 z = make_uint4(0, 0, 0, 0);
    for (int i = i0; i < ADJ_EL / 16; i += stride) {
        ((uint4*)g_adj[0])[i] = z;
        ((uint4*)g_adj[1])[i] = z;
    }
    for (int i = i0; i < N_NODES; i += stride) {
        g_cin[i] = 0;
        g_cout[i] = 0;
    }
}

__global__ void adj_build_kernel(const void* __restrict__ ei,
                                 const void* __restrict__ mk) {
    int e = blockIdx.x * blockDim.x + threadIdx.x;
    if (e >= N_EDGES) return;
    int t = load_idx(ei, N_EDGES + e);
    int s = load_idx(ei, e);
    if ((unsigned)t >= (unsigned)N_NODES) return;
    if ((unsigned)s >= (unsigned)N_NODES) return;
    if ((t >> 7) != (s >> 7)) return;
    int sel = load_mask(mk, e) ? 0 : 1;
    int idx = ((t >> 7) * NPG + (t & 127)) * NPG + (s & 127);
    atomicAdd(&((unsigned int*)g_adj[sel])[idx >> 2], 1u << ((idx & 3) * 8));
    atomicAdd(sel ? &g_cout[t] : &g_cin[t], 1);
}

// ---------------------------------------------------------------------------
#define FUSED_SMEM (7 * BUFB)

__global__ void __launch_bounds__(512)
fused_kernel(const float* __restrict__ x,
             const float* __restrict__ Wn_, const float* __restrict__ bn_,
             const float* __restrict__ Wo_, const float* __restrict__ bo_,
             const float* __restrict__ Wr_,
             const float* __restrict__ lng_, const float* __restrict__ lnb_,
             const float* __restrict__ sIn,
             const float* __restrict__ flng, const float* __restrict__ flnb,
             const float* __restrict__ linw, const float* __restrict__ bias,
             float* __restrict__ dout) {
    extern __shared__ __align__(16) char dyn[];
    __shared__ float sbn[HD], sbo[HD];
    __shared__ float colsum[NC], xcs[NC];

    int tid = threadIdx.x;
    int w = tid >> 5, lane = tid & 31;
    int m_blk = (w >> 2) * 32, n_blk = (w & 3) * 32;
    int grp = lane >> 2, tig = lane & 3;
    int g = blockIdx.x, row0 = g * 128;

    uint32_t base = smem_u32(dyn);
    uint32_t C0 = base, C1 = base + BUFB, Dd = base + 2 * BUFB;
    uint32_t A0 = base + 3 * BUFB, A1 = base + 4 * BUFB;
    uint32_t W0 = base + 5 * BUFB, W1 = base + 6 * BUFB;
    float* S = (float*)dyn;
    float* P = (float*)(dyn + 3 * BUFB);

    // --- layer-0 h: split x into A0/A1 ---
    #pragma unroll
    for (int i = 0; i < 4; i++) {
        int gid = tid + i * 512;
        int r = gid >> 4, gq = gid & 15;
        const float* src = x + (size_t)(row0 + r) * HD + gq * 8;
        float v[8];
        *(float4*)(v)     = *(const float4*)(src);
        *(float4*)(v + 4) = *(const float4*)(src + 4);
        uint32_t hi[4], lo[4];
        #pragma unroll
        for (int j = 0; j < 4; j++) {
            float a = v[2 * j], b = v[2 * j + 1];
            __nv_bfloat16 ha = __float2bfloat16(a), hb = __float2bfloat16(b);
            hi[j] = (uint32_t)__bfloat16_as_ushort(ha)
                  | ((uint32_t)__bfloat16_as_ushort(hb) << 16);
            lo[j] = bf2pack(a - __bfloat162float(ha), b - __bfloat162float(hb));
        }
        uint32_t off = (uint32_t)(r * 256 + ((gq ^ (r & 7)) << 4));
        *(uint4*)((char*)dyn + (A0 - base) + off) = make_uint4(hi[0], hi[1], hi[2], hi[3]);
        *(uint4*)((char*)dyn + (A1 - base) + off) = make_uint4(lo[0], lo[1], lo[2], lo[3]);
    }

    #pragma unroll 1
    for (int l = 0; l < NL; l++) {
        const float* Wn = Wn_ + l * HD * HD;
        const float* Wo = Wo_ + l * HD * HD;
        const float* Wr = Wr_ + l * HD * HD;

        __syncthreads();
        if (tid < HD) { sbn[tid] = bn_[l * HD + tid]; sbo[tid] = bo_[l * HD + tid]; }

        // adjacency u8 -> bf16 into C0/C1
        #pragma unroll
        for (int sel = 0; sel < 2; sel++) {
            const unsigned char* src = g_adj[sel] + (size_t)g * NPG * NPG;
            uint32_t dst = (sel == 0) ? C0 : C1;
            #pragma unroll
            for (int i = 0; i < 4; i++) {
                int gid = tid + i * 512;
                int r = gid >> 4, gq = gid & 15;
                uint2 raw = *(const uint2*)(src + r * NPG + gq * 8);
                uint32_t p[4];
                p[0] = bf2pack((float)(raw.x & 255), (float)((raw.x >> 8) & 255));
                p[1] = bf2pack((float)((raw.x >> 16) & 255), (float)(raw.x >> 24));
                p[2] = bf2pack((float)(raw.y & 255), (float)((raw.y >> 8) & 255));
                p[3] = bf2pack((float)((raw.y >> 16) & 255), (float)(raw.y >> 24));
                uint32_t off = (uint32_t)(r * 256 + ((gq ^ (r & 7)) << 4));
                *(uint4*)((char*)dyn + (dst - base) + off) = make_uint4(p[0], p[1], p[2], p[3]);
            }
        }

        // Wr split into W0/W1
        #pragma unroll
        for (int i = 0; i < 4; i++) {
            int gid = tid + i * 512;
            int r = gid >> 4, gq = gid & 15;
            const float* src = Wr + (size_t)r * HD + gq * 8;
            float v[8];
            *(float4*)(v)     = *(const float4*)(src);
            *(float4*)(v + 4) = *(const float4*)(src + 4);
            uint32_t hi[4], lo[4];
            #pragma unroll
            for (int j = 0; j < 4; j++) {
                float a = v[2 * j], b = v[2 * j + 1];
                __nv_bfloat16 ha = __float2bfloat16(a), hb = __float2bfloat16(b);
                hi[j] = (uint32_t)__bfloat16_as_ushort(ha)
                      | ((uint32_t)__bfloat16_as_ushort(hb) << 16);
                lo[j] = bf2pack(a - __bfloat162float(ha), b - __bfloat162float(hb));
            }
            uint32_t off = (uint32_t)(r * 256 + ((gq ^ (r & 7)) << 4));
            *(uint4*)((char*)dyn + (W0 - base) + off) = make_uint4(hi[0], hi[1], hi[2], hi[3]);
            *(uint4*)((char*)dyn + (W1 - base) + off) = make_uint4(lo[0], lo[1], lo[2], lo[3]);
        }
        __syncthreads();

        // root = h @ Wr^T (fused 3-term)
        float root[2][4][4];
        #pragma unroll
        for (int mt = 0; mt < 2; mt++)
            #pragma unroll
            for (int nt = 0; nt < 4; nt++)
                #pragma unroll
                for (int q = 0; q < 4; q++) root[mt][nt][q] = 0.f;
        pass3_nn(root, A0, A1, W0, W1, m_blk, n_blk, lane);

        // Hin = Ain @ (A0 + A1)  (fused 2-term, exact adjacency)
        float hacc[2][4][4];
        #pragma unroll
        for (int mt = 0; mt < 2; mt++)
            #pragma unroll
            for (int nt = 0; nt < 4; nt++)
                #pragma unroll
                for (int q = 0; q < 4; q++) hacc[mt][nt][q] = 0.f;
        pass2_nt(hacc, C0, A0, A1, m_blk, n_blk, lane);
        __syncthreads();
        #pragma unroll
        for (int mt = 0; mt < 2; mt++) {
            #pragma unroll
            for (int nt = 0; nt < 4; nt++) {
                int rg = m_blk + mt * 16 + grp;
                int cg = n_blk + nt * 8 + tig * 2;
                #pragma unroll
                for (int half = 0; half < 2; half++) {
                    int row = rg + half * 8;
                    float a = hacc[mt][nt][half * 2], b = hacc[mt][nt][half * 2 + 1];
                    __nv_bfloat16 ha = __float2bfloat16(a), hb = __float2bfloat16(b);
                    uint32_t off = swz(row, cg);
                    *(uint32_t*)((char*)dyn + (C0 - base) + off) =
                        (uint32_t)__bfloat16_as_ushort(ha)
                        | ((uint32_t)__bfloat16_as_ushort(hb) << 16);
                    *(uint32_t*)((char*)dyn + (Dd - base) + off) =
                        bf2pack(a - __bfloat162float(ha), b - __bfloat162float(hb));
                }
            }
        }

        // Hout = Aout @ (A0 + A1)
        #pragma unroll
        for (int mt = 0; mt < 2; mt++)
            #pragma unroll
            for (int nt = 0; nt < 4; nt++)
                #pragma unroll
                for (int q = 0; q < 4; q++) hacc[mt][nt][q] = 0.f;
        pass2_nt(hacc, C1, A0, A1, m_blk, n_blk, lane);
        __syncthreads();
        #pragma unroll
        for (int mt = 0; mt < 2; mt++) {
            #pragma unroll
            for (int nt = 0; nt < 4; nt++) {
                int rg = m_blk + mt * 16 + grp;
                int cg = n_blk + nt * 8 + tig * 2;
                #pragma unroll
                for (int half = 0; half < 2; half++) {
                    int row = rg + half * 8;
                    float a = hacc[mt][nt][half * 2], b = hacc[mt][nt][half * 2 + 1];
                    __nv_bfloat16 ha = __float2bfloat16(a), hb = __float2bfloat16(b);
                    uint32_t off = swz(row, cg);
                    *(uint32_t*)((char*)dyn + (C1 - base) + off) =
                        (uint32_t)__bfloat16_as_ushort(ha)
                        | ((uint32_t)__bfloat16_as_ushort(hb) << 16);
                    *(uint32_t*)((char*)dyn + (A1 - base) + off) =
                        bf2pack(a - __bfloat162float(ha), b - __bfloat162float(hb));
                }
            }
        }
        __syncthreads();

        // agg = Hin @ Wn^T + Hout @ Wo^T (fused 3-term each)
        float agg[2][4][4];
        #pragma unroll
        for (int mt = 0; mt < 2; mt++)
            #pragma unroll
            for (int nt = 0; nt < 4; nt++)
                #pragma unroll
                for (int q = 0; q < 4; q++) agg[mt][nt][q] = 0.f;

        const float* Wptr[2] = {Wn, Wo};
        #pragma unroll 1
        for (int m = 0; m < 2; m++) {
            const float* Wm = Wptr[m];
            #pragma unroll
            for (int i = 0; i < 4; i++) {
                int gid = tid + i * 512;
                int r = gid >> 4, gq = gid & 15;
                const float* src = Wm + (size_t)r * HD + gq * 8;
                float v[8];
                *(float4*)(v)     = *(const float4*)(src);
                *(float4*)(v + 4) = *(const float4*)(src + 4);
                uint32_t hi[4], lo[4];
                #pragma unroll
                for (int j = 0; j < 4; j++) {
                    float a = v[2 * j], b = v[2 * j + 1];
                    __nv_bfloat16 ha = __float2bfloat16(a), hb = __float2bfloat16(b);
                    hi[j] = (uint32_t)__bfloat16_as_ushort(ha)
                          | ((uint32_t)__bfloat16_as_ushort(hb) << 16);
                    lo[j] = bf2pack(a - __bfloat162float(ha),
                                    b - __bfloat162float(hb));
                }
                uint32_t off = (uint32_t)(r * 256 + ((gq ^ (r & 7)) << 4));
                *(uint4*)((char*)dyn + (W0 - base) + off) = make_uint4(hi[0], hi[1], hi[2], hi[3]);
                *(uint4*)((char*)dyn + (W1 - base) + off) = make_uint4(lo[0], lo[1], lo[2], lo[3]);
            }
            __syncthreads();

            uint32_t Hhi = (m == 0) ? C0 : C1;
            uint32_t Hlo = (m == 0) ? Dd : A1;
            pass3_nn(agg, Hhi, Hlo, W0, W1, m_blk, n_blk, lane);
            __syncthreads();
        }

        // epilogue -> S (fp32, overlays C0/C1/D)
        #pragma unroll
        for (int mt = 0; mt < 2; mt++) {
            int rg = m_blk + mt * 16 + grp;
            #pragma unroll
            for (int half = 0; half < 2; half++) {
                int row = rg + half * 8;
                float ci = (float)g_cin[row0 + row];
                float co = (float)g_cout[row0 + row];
                float inv = 1.0f / fmaxf(ci + co, 1.0f);
                #pragma unroll
                for (int nt = 0; nt < 4; nt++) {
                    int cg = n_blk + nt * 8 + tig * 2;
                    float v0 = (agg[mt][nt][half * 2]     + ci * sbn[cg]
                                + co * sbo[cg]) * inv + root[mt][nt][half * 2];
                    float v1 = (agg[mt][nt][half * 2 + 1] + ci * sbn[cg + 1]
                                + co * sbo[cg + 1]) * inv + root[mt][nt][half * 2 + 1];
                    S[row * 132 + cg]     = v0;
                    S[row * 132 + cg + 1] = v1;
                }
            }
        }
        __syncthreads();

        // LayerNorm + ReLU (4 threads/row); write next-layer h or final P
        {
            int row = tid >> 2, q = tid & 3;
            const float* Sr = S + row * 132 + q * 32;
            float v[32];
            float sum = 0.f, sq = 0.f;
            #pragma unroll
            for (int j = 0; j < 32; j++) {
                v[j] = Sr[j];
                sum += v[j];
                sq  += v[j] * v[j];
            }
            sum += __shfl_xor_sync(0xffffffffu, sum, 1);
            sum += __shfl_xor_sync(0xffffffffu, sum, 2);
            sq  += __shfl_xor_sync(0xffffffffu, sq, 1);
            sq  += __shfl_xor_sync(0xffffffffu, sq, 2);
            float mu   = sum * (1.0f / 128.0f);
            float var  = sq * (1.0f / 128.0f) - mu * mu;
            float rstd = rsqrtf(var + 1e-5f);

            const float* gma = lng_ + l * HD + q * 32;
            const float* bta = lnb_ + l * HD + q * 32;
            if (l < NL - 1) {
                #pragma unroll
                for (int j = 0; j < 32; j += 2) {
                    float o0 = fmaxf((v[j]     - mu) * rstd * gma[j]     + bta[j],     0.f);
                    float o1 = fmaxf((v[j + 1] - mu) * rstd * gma[j + 1] + bta[j + 1], 0.f);
                    int c = q * 32 + j;
                    uint32_t off = swz(row, c);
                    __nv_bfloat16 h0 = __float2bfloat16(o0), h1 = __float2bfloat16(o1);
                    *(uint32_t*)((char*)dyn + (A0 - base) + off) =
                        (uint32_t)__bfloat16_as_ushort(h0)
                        | ((uint32_t)__bfloat16_as_ushort(h1) << 16);
                    *(uint32_t*)((char*)dyn + (A1 - base) + off) =
                        bf2pack(o0 - __bfloat162float(h0), o1 - __bfloat162float(h1));
                }
            } else {
                float* Pr = P + row * 132 + q * 32;
                #pragma unroll
                for (int j = 0; j < 32; j += 4) {
                    float o0 = fmaxf((v[j]     - mu) * rstd * gma[j]     + bta[j],     0.f);
                    float o1 = fmaxf((v[j + 1] - mu) * rstd * gma[j + 1] + bta[j + 1], 0.f);
                    float o2 = fmaxf((v[j + 2] - mu) * rstd * gma[j + 2] + bta[j + 2], 0.f);
                    float o3 = fmaxf((v[j + 3] - mu) * rstd * gma[j + 3] + bta[j + 3], 0.f);
                    *(float4*)(Pr + j) = make_float4(o0, o1, o2, o3);
                }
            }
        }
    }

    // =================== pooling head (in-CTA) ===================
    __syncthreads();
    float* sdP = (float*)dyn;
    float* plP = (float*)(dyn + 8192);

    *(float4*)(sdP + tid * 4) =
        *(const float4*)(sIn + (size_t)g * NPG * NC + tid * 4);
    __syncthreads();

    if (tid < NC) {
        float cs = 0.f;
        for (int n = 0; n < NPG; n++) cs += sdP[n * NC + tid];
        colsum[tid] = cs;
    }

    {
        int hcol = tid & 127, cgrp = tid >> 7;
        float pacc[4] = {0.f, 0.f, 0.f, 0.f};
        #pragma unroll 4
        for (int n = 0; n < NPG; n++) {
            float xv = P[n * 132 + hcol];
            #pragma unroll
            for (int c = 0; c < 4; c++)
                pacc[c] = fmaf(sdP[n * NC + cgrp * 4 + c], xv, pacc[c]);
        }
        #pragma unroll
        for (int c = 0; c < 4; c++)
            plP[(cgrp * 4 + c) * 128 + hcol] = pacc[c];
    }
    __syncthreads();

    {
        int rr = w;
        float4 v = *(float4*)(plP + rr * 128 + lane * 4);
        float sum = v.x + v.y + v.z + v.w;
        float sq  = v.x * v.x + v.y * v.y + v.z * v.z + v.w * v.w;
        #pragma unroll
        for (int o = 16; o; o >>= 1) {
            sum += __shfl_xor_sync(0xffffffffu, sum, o);
            sq  += __shfl_xor_sync(0xffffffffu, sq,  o);
        }
        float mu   = sum * (1.0f / 128.0f);
        float var  = sq * (1.0f / 128.0f) - mu * mu;
        float rstd = rsqrtf(var + 1e-5f);
        int f = lane * 4;
        float dot = ((v.x - mu) * rstd * flng[f + 0] + flnb[f + 0]) * linw[f + 0]
                  + ((v.y - mu) * rstd * flng[f + 1] + flnb[f + 1]) * linw[f + 1]
                  + ((v.z - mu) * rstd * flng[f + 2] + flnb[f + 2]) * linw[f + 2]
                  + ((v.w - mu) * rstd * flng[f + 3] + flnb[f + 3]) * linw[f + 3];
        #pragma unroll
        for (int o = 16; o; o >>= 1) dot += __shfl_xor_sync(0xffffffffu, dot, o);
        if (lane == 0) xcs[rr] = dot;
    }
    __syncthreads();

    if (tid == 0) {
        float ov = 0.f, l1 = 0.f, dn = 0.f;
        #pragma unroll
        for (int c = 0; c < NC; c++) {
            float mflag = (colsum[c] > 0.f) ? 1.f : 0.f;
            float v = xcs[c] * mflag;
            dout[257 + g * NC + c] = v;
            ov += v;
            l1 += fabsf(v);
            dn += mflag;
        }
        dout[g] = ov + bias[0];
        g_l1[g] = l1 / (dn + 1e-7f);
    }
}

// losses = 0.01*(sum|Wo|+sum|bo|) + 0.01*mean_g(l1[g])
__global__ void loss_kernel(const float* __restrict__ Wo,
                            const float* __restrict__ bo,
                            float* __restrict__ dout) {
    __shared__ float red[256];
    __shared__ float sreg;
    int tid = threadIdx.x;
    float rs = 0.f;
    for (int i = tid; i < NL * HD * HD; i += 256) rs += fabsf(Wo[i]);
    for (int i = tid; i < NL * HD; i += 256)      rs += fabsf(bo[i]);
    red[tid] = rs;
    __syncthreads();
    for (int o = 128; o; o >>= 1) {
        if (tid < o) red[tid] += red[tid + o];
        __syncthreads();
    }
    if (tid == 0) sreg = red[0];
    __syncthreads();
    float ls = (tid < NG) ? g_l1[tid] : 0.f;
    red[tid] = ls;
    __syncthreads();
    for (int o = 128; o; o >>= 1) {
        if (tid < o) red[tid] += red[tid + o];
        __syncthreads();
    }
    if (tid == 0)
        dout[256] = 0.01f * sreg + 0.01f * (red[0] / (float)NG);
}

// ---------------------------------------------------------------------------
extern "C" void kernel_launch(void* const* d_in, const int* in_sizes, int n_in,
                              void* d_out, int out_size) {
    const float* x    = (const float*)d_in[0];
    const void*  ei   = d_in[1];
    const void*  mk   = d_in[2];
    const float* s    = (const float*)d_in[3];
    const float* Wn   = (const float*)d_in[5];
    const float* bn   = (const float*)d_in[6];
    const float* Wo   = (const float*)d_in[7];
    const float* bo   = (const float*)d_in[8];
    const float* Wr   = (const float*)d_in[9];
    const float* lng  = (const float*)d_in[10];
    const float* lnb  = (const float*)d_in[11];
    const float* flng = (const float*)d_in[12];
    const float* flnb = (const float*)d_in[13];
    const float* linw = (const float*)d_in[14];
    const float* bias = (const float*)d_in[15];
    float* out = (float*)d_out;

    cudaFuncSetAttribute(fused_kernel,
                         cudaFuncAttributeMaxDynamicSharedMemorySize, FUSED_SMEM);

    detect_kernel<<<1, 32>>>((const unsigned int*)ei, (const unsigned int*)mk);
    zero_all_kernel<<<1024, 256>>>();
    adj_build_kernel<<<N_EDGES / 256, 256>>>(ei, mk);

    fused_kernel<<<NG, 512, FUSED_SMEM>>>(
        x, Wn, bn, Wo, bo, Wr, lng, lnb,
        s, flng, flnb, linw, bias, out);

    loss_kernel<<<1, 256>>>(Wo, bo, out);
}